// round 4
// baseline (speedup 1.0000x reference)
#include <cuda_runtime.h>
#include <math.h>

// Problem constants
#define BB   4
#define TT   2048
#define CC   2048
#define HH   16
#define DH   128
#define BT   (BB * TT)          // 8192
#define ELEMS ((size_t)BT * CC) // 16777216

// ---------------- scratch (device globals; no allocation allowed) ----------
__device__ __align__(16) float g_x[ELEMS];   // rmsnormed input
__device__ __align__(16) float g_q[ELEMS];
__device__ __align__(16) float g_k[ELEMS];
__device__ __align__(16) float g_v[ELEMS];
__device__ __align__(16) float g_y[ELEMS];   // attention output (pre-proj)
__device__ __align__(16) float g_cos[TT * 64];
__device__ __align__(16) float g_sin[TT * 64];

#define RMS_EPS 1.1920928955078125e-07f

// ---------------- kernel 1: rmsnorm over C of residual ---------------------
__global__ __launch_bounds__(256) void rmsnorm_in_kernel(const float* __restrict__ in,
                                                         float* __restrict__ out) {
    int row = blockIdx.x;
    const float4* ip = reinterpret_cast<const float4*>(in) + (size_t)row * 512;
    float4*       op = reinterpret_cast<float4*>(out)      + (size_t)row * 512;
    int t = threadIdx.x;
    float4 a = ip[t];
    float4 b = ip[t + 256];
    float ss = a.x*a.x + a.y*a.y + a.z*a.z + a.w*a.w
             + b.x*b.x + b.y*b.y + b.z*b.z + b.w*b.w;
    __shared__ float red[8];
    #pragma unroll
    for (int o = 16; o > 0; o >>= 1) ss += __shfl_xor_sync(0xffffffffu, ss, o);
    if ((t & 31) == 0) red[t >> 5] = ss;
    __syncthreads();
    if (t < 8) {
        float v = red[t];
        #pragma unroll
        for (int o = 4; o > 0; o >>= 1) v += __shfl_xor_sync(0xffu, v, o);
        if (t == 0) red[0] = v;
    }
    __syncthreads();
    float sc = rsqrtf(red[0] * (1.0f / 2048.0f) + RMS_EPS);
    a.x *= sc; a.y *= sc; a.z *= sc; a.w *= sc;
    b.x *= sc; b.y *= sc; b.z *= sc; b.w *= sc;
    op[t]       = a;
    op[t + 256] = b;
}

// ---------------- kernel 2: RoPE cos/sin tables (accurate inv_freq) --------
__global__ void rope_table_kernel() {
    int idx = blockIdx.x * blockDim.x + threadIdx.x;
    if (idx >= TT * 64) return;
    int t = idx >> 6;
    int p = idx & 63;
    double inv = pow(10000.0, -((double)p) / 64.0);   // exact-to-0.5ulp inv_freq
    float ang = (float)t * (float)inv;                // match ref fp32 product
    g_cos[idx] = cosf(ang);
    g_sin[idx] = sinf(ang);
}

// ---------------- kernel 3: SGEMM  C[m,n] = sum_k A[m,k]*W[n,k] (+addend) --
#define GBM 128
#define GBN 64
#define GBK 16

__global__ __launch_bounds__(256) void sgemm_nt_kernel(const float* __restrict__ A,
                                                       const float* __restrict__ W,
                                                       const float* __restrict__ addend,
                                                       float* __restrict__ Cmat,
                                                       int M, int N, int K) {
    __shared__ float As[GBK][132];   // transposed A tile [k][m], padded
    __shared__ float Bs[GBK][68];    // transposed W tile [k][n], padded
    int tid = threadIdx.x;
    int tx = tid & 15, ty = tid >> 4;
    int m0 = blockIdx.y * GBM, n0 = blockIdx.x * GBN;

    float acc[8][4];
    #pragma unroll
    for (int i = 0; i < 8; i++)
        #pragma unroll
        for (int j = 0; j < 4; j++) acc[i][j] = 0.f;

    for (int k0 = 0; k0 < K; k0 += GBK) {
        #pragma unroll
        for (int it = 0; it < 2; it++) {
            int f4i = tid + it * 256;         // 0..511
            int r = f4i >> 2, c4 = f4i & 3;
            float4 v = *reinterpret_cast<const float4*>(A + (size_t)(m0 + r) * K + k0 + 4 * c4);
            As[4*c4+0][r] = v.x; As[4*c4+1][r] = v.y;
            As[4*c4+2][r] = v.z; As[4*c4+3][r] = v.w;
        }
        {
            int r = tid >> 2, c4 = tid & 3;   // 0..63
            float4 v = *reinterpret_cast<const float4*>(W + (size_t)(n0 + r) * K + k0 + 4 * c4);
            Bs[4*c4+0][r] = v.x; Bs[4*c4+1][r] = v.y;
            Bs[4*c4+2][r] = v.z; Bs[4*c4+3][r] = v.w;
        }
        __syncthreads();
        #pragma unroll
        for (int kk = 0; kk < GBK; kk++) {
            float4 a0 = *reinterpret_cast<const float4*>(&As[kk][8 * ty]);
            float4 a1 = *reinterpret_cast<const float4*>(&As[kk][8 * ty + 4]);
            float4 b  = *reinterpret_cast<const float4*>(&Bs[kk][4 * tx]);
            float av[8] = {a0.x, a0.y, a0.z, a0.w, a1.x, a1.y, a1.z, a1.w};
            float bv[4] = {b.x, b.y, b.z, b.w};
            #pragma unroll
            for (int i = 0; i < 8; i++)
                #pragma unroll
                for (int j = 0; j < 4; j++)
                    acc[i][j] += av[i] * bv[j];
        }
        __syncthreads();
    }

    #pragma unroll
    for (int i = 0; i < 8; i++) {
        size_t idx = (size_t)(m0 + 8 * ty + i) * N + n0 + 4 * tx;
        float4 r = make_float4(acc[i][0], acc[i][1], acc[i][2], acc[i][3]);
        if (addend) {
            float4 ad = *reinterpret_cast<const float4*>(addend + idx);
            r.x += ad.x; r.y += ad.y; r.z += ad.z; r.w += ad.w;
        }
        *reinterpret_cast<float4*>(Cmat + idx) = r;
    }
}

// ---------------- kernel 4: per-head rmsnorm + RoPE (q and k, in place) ----
__global__ __launch_bounds__(256) void qknorm_rope_kernel(float* __restrict__ q,
                                                          float* __restrict__ k) {
    int gwarp = (blockIdx.x * 256 + threadIdx.x) >> 5;   // [0, BT*HH)
    int lane  = threadIdx.x & 31;
    int m = gwarp >> 4;         // b*T + t
    int h = gwarp & 15;
    int t = m & (TT - 1);
    size_t base = (size_t)m * CC + h * DH;

    float c0 = g_cos[t * 64 + lane],      s0 = g_sin[t * 64 + lane];
    float c1 = g_cos[t * 64 + 32 + lane], s1 = g_sin[t * 64 + 32 + lane];

    float* bufs[2] = {q, k};
    #pragma unroll
    for (int w = 0; w < 2; w++) {
        float* p = bufs[w] + base;
        float v0 = p[lane], v1 = p[lane + 32], v2 = p[lane + 64], v3 = p[lane + 96];
        float ss = v0*v0 + v1*v1 + v2*v2 + v3*v3;
        #pragma unroll
        for (int o = 16; o > 0; o >>= 1) ss += __shfl_xor_sync(0xffffffffu, ss, o);
        float sc = rsqrtf(ss * (1.0f / 128.0f) + RMS_EPS);
        v0 *= sc; v1 *= sc; v2 *= sc; v3 *= sc;
        // pair (d, d+64): y1 = x1*c + x2*s ; y2 = -x1*s + x2*c
        p[lane]      = v0 * c0 + v2 * s0;
        p[lane + 64] = v2 * c0 - v0 * s0;
        p[lane + 32] = v1 * c1 + v3 * s1;
        p[lane + 96] = v3 * c1 - v1 * s1;
    }
}

// ---------------- kernel 5: causal flash attention (fp32) ------------------
#define AT_BM 64
#define AT_BN 64
// smem layout (floats): Qst[128][68], Kst[128][68], Vs[64][128], Ps[64][68]
#define ATT_SMEM_FLOATS (2 * 128 * 68 + 64 * 128 + 64 * 68)
#define ATT_SMEM_BYTES  (ATT_SMEM_FLOATS * 4)

__global__ __launch_bounds__(256) void attn_kernel(const float* __restrict__ Q,
                                                   const float* __restrict__ K,
                                                   const float* __restrict__ V,
                                                   float* __restrict__ O) {
    extern __shared__ float sm[];
    float* Qst = sm;
    float* Kst = sm + 128 * 68;
    float* Vs  = sm + 2 * 128 * 68;
    float* Ps  = sm + 2 * 128 * 68 + 64 * 128;

    int tid = threadIdx.x;
    int tx = tid & 15, ty = tid >> 4;
    int qt = blockIdx.x;               // q tile
    int bh = blockIdx.y;
    int b = bh >> 4, h = bh & 15;
    int m0 = qt * AT_BM;
    size_t base = (size_t)b * TT * CC + (size_t)h * DH;
    const float qscale = 1.0f / sqrtf((float)DH);

    // load Q tile transposed + prescaled
    for (int idx = tid; idx < AT_BM * 128; idx += 256) {
        int d = idx & 127, r = idx >> 7;
        Qst[d * 68 + r] = Q[base + (size_t)(m0 + r) * CC + d] * qscale;
    }

    float o[4][8];
    float mrun[4], lrun[4];
    #pragma unroll
    for (int i = 0; i < 4; i++) {
        mrun[i] = -1e30f; lrun[i] = 0.f;
        #pragma unroll
        for (int j = 0; j < 8; j++) o[i][j] = 0.f;
    }

    for (int kt = 0; kt <= qt; kt++) {
        int n0 = kt * AT_BN;
        __syncthreads();   // prior-iteration smem reads done; also publishes Q load

        // K tile transposed [d][n]
        for (int idx = tid; idx < AT_BN * 128; idx += 256) {
            int d = idx & 127, n = idx >> 7;
            Kst[d * 68 + n] = K[base + (size_t)(n0 + n) * CC + d];
        }
        // V tile plain [n][d]
        for (int f = tid; f < AT_BN * 32; f += 256) {
            int n = f >> 5, d4 = f & 31;
            reinterpret_cast<float4*>(Vs)[n * 32 + d4] =
                *reinterpret_cast<const float4*>(V + base + (size_t)(n0 + n) * CC + 4 * d4);
        }
        __syncthreads();

        // S = Q K^T fragment (rows 4ty+i, cols 4tx+j)
        float s[4][4];
        #pragma unroll
        for (int i = 0; i < 4; i++)
            #pragma unroll
            for (int j = 0; j < 4; j++) s[i][j] = 0.f;
        for (int d = 0; d < 128; d++) {
            float4 a  = *reinterpret_cast<const float4*>(&Qst[d * 68 + 4 * ty]);
            float4 bb = *reinterpret_cast<const float4*>(&Kst[d * 68 + 4 * tx]);
            float av[4] = {a.x, a.y, a.z, a.w};
            float bv[4] = {bb.x, bb.y, bb.z, bb.w};
            #pragma unroll
            for (int i = 0; i < 4; i++)
                #pragma unroll
                for (int j = 0; j < 4; j++)
                    s[i][j] += av[i] * bv[j];
        }

        bool diag = (kt == qt);
        #pragma unroll
        for (int i = 0; i < 4; i++) {
            int rg = m0 + 4 * ty + i;
            float mloc = -1e30f;
            #pragma unroll
            for (int j = 0; j < 4; j++) {
                if (diag && (n0 + 4 * tx + j > rg)) s[i][j] = -1e30f;
                mloc = fmaxf(mloc, s[i][j]);
            }
            #pragma unroll
            for (int off = 8; off > 0; off >>= 1)
                mloc = fmaxf(mloc, __shfl_xor_sync(0xffffffffu, mloc, off));
            float mnew  = fmaxf(mrun[i], mloc);
            float alpha = expf(mrun[i] - mnew);
            float rs = 0.f;
            #pragma unroll
            for (int j = 0; j < 4; j++) { s[i][j] = expf(s[i][j] - mnew); rs += s[i][j]; }
            #pragma unroll
            for (int off = 8; off > 0; off >>= 1)
                rs += __shfl_xor_sync(0xffffffffu, rs, off);
            lrun[i] = lrun[i] * alpha + rs;
            mrun[i] = mnew;
            #pragma unroll
            for (int j = 0; j < 8; j++) o[i][j] *= alpha;
            #pragma unroll
            for (int j = 0; j < 4; j++)
                Ps[(4 * ty + i) * 68 + 4 * tx + j] = s[i][j];
        }
        __syncthreads();

        // O += P V   (rows 4ty+i, cols 8tx+j)
        for (int n = 0; n < AT_BN; n++) {
            float pp[4];
            #pragma unroll
            for (int i = 0; i < 4; i++) pp[i] = Ps[(4 * ty + i) * 68 + n];
            float4 v0 = *reinterpret_cast<const float4*>(&Vs[n * 128 + 8 * tx]);
            float4 v1 = *reinterpret_cast<const float4*>(&Vs[n * 128 + 8 * tx + 4]);
            float vv[8] = {v0.x, v0.y, v0.z, v0.w, v1.x, v1.y, v1.z, v1.w};
            #pragma unroll
            for (int i = 0; i < 4; i++)
                #pragma unroll
                for (int j = 0; j < 8; j++)
                    o[i][j] += pp[i] * vv[j];
        }
    }

    // write normalized O into [b,t,h,d] (= [m][h*128+d]) layout
    #pragma unroll
    for (int i = 0; i < 4; i++) {
        float inv = 1.0f / lrun[i];
        size_t oidx = base + (size_t)(m0 + 4 * ty + i) * CC + 8 * tx;
        float4 r0 = make_float4(o[i][0] * inv, o[i][1] * inv, o[i][2] * inv, o[i][3] * inv);
        float4 r1 = make_float4(o[i][4] * inv, o[i][5] * inv, o[i][6] * inv, o[i][7] * inv);
        *reinterpret_cast<float4*>(O + oidx)     = r0;
        *reinterpret_cast<float4*>(O + oidx + 4) = r1;
    }
}

// ---------------- launch ----------------------------------------------------
extern "C" void kernel_launch(void* const* d_in, const int* in_sizes, int n_in,
                              void* d_out, int out_size) {
    const float* residual = (const float*)d_in[0];
    const float* wq    = (const float*)d_in[1];
    const float* wk    = (const float*)d_in[2];
    const float* wv    = (const float*)d_in[3];
    const float* wproj = (const float*)d_in[4];
    float* out = (float*)d_out;

    cudaFuncSetAttribute(attn_kernel, cudaFuncAttributeMaxDynamicSharedMemorySize,
                         ATT_SMEM_BYTES);

    void *px, *pq, *pk, *pv, *py;
    cudaGetSymbolAddress(&px, g_x);
    cudaGetSymbolAddress(&pq, g_q);
    cudaGetSymbolAddress(&pk, g_k);
    cudaGetSymbolAddress(&pv, g_v);
    cudaGetSymbolAddress(&py, g_y);
    float* gx = (float*)px; float* gq = (float*)pq; float* gk = (float*)pk;
    float* gv = (float*)pv; float* gy = (float*)py;

    // 1. rmsnorm input
    rmsnorm_in_kernel<<<BT, 256>>>(residual, gx);
    // 2. rope tables (deterministic, rebuilt each replay)
    rope_table_kernel<<<(TT * 64 + 255) / 256, 256>>>();
    // 3. QKV projections
    dim3 ggrid(CC / GBN, BT / GBM);
    sgemm_nt_kernel<<<ggrid, 256>>>(gx, wq, nullptr, gq, BT, CC, CC);
    sgemm_nt_kernel<<<ggrid, 256>>>(gx, wk, nullptr, gk, BT, CC, CC);
    sgemm_nt_kernel<<<ggrid, 256>>>(gx, wv, nullptr, gv, BT, CC, CC);
    // 4. per-head rmsnorm + rope on q, k
    qknorm_rope_kernel<<<(BT * HH) / 8, 256>>>(gq, gk);
    // 5. causal flash attention
    dim3 agrid(TT / AT_BM, BB * HH);
    attn_kernel<<<agrid, 256, ATT_SMEM_BYTES>>>(gq, gk, gv, gy);
    // 6. output projection + residual add
    sgemm_nt_kernel<<<ggrid, 256>>>(gy, wproj, residual, out, BT, CC, CC);
}

// round 6
// speedup vs baseline: 1.6093x; 1.6093x over previous
#include <cuda_runtime.h>
#include <cuda_bf16.h>
#include <math.h>
#include <stdint.h>

// Problem constants
#define BB   4
#define TT   2048
#define CC   2048
#define HH   16
#define DH   128
#define BT   (BB * TT)          // 8192
#define ELEMS ((size_t)BT * CC) // 16777216

#define RMS_EPS 1.1920928955078125e-07f

// ---------------- scratch (device globals; no allocation allowed) ----------
__device__ __align__(16) float g_q[ELEMS];
__device__ __align__(16) float g_k[ELEMS];
__device__ __align__(16) float g_v[ELEMS];
__device__ __align__(16) __nv_bfloat16 g_xh[ELEMS];
__device__ __align__(16) __nv_bfloat16 g_xl[ELEMS];
__device__ __align__(16) __nv_bfloat16 g_yh[ELEMS];
__device__ __align__(16) __nv_bfloat16 g_yl[ELEMS];
__device__ __align__(16) __nv_bfloat16 g_wh[4][(size_t)CC * CC];
__device__ __align__(16) __nv_bfloat16 g_wl[4][(size_t)CC * CC];
__device__ __align__(16) float g_cos[TT * 64];
__device__ __align__(16) float g_sin[TT * 64];

// ======================= PTX helpers (portable, no 'a' features) ============
__device__ __forceinline__ uint32_t smem_u32(const void* p) {
    uint32_t a;
    asm("{ .reg .u64 t; cvta.to.shared.u64 t, %1; cvt.u32.u64 %0, t; }"
        : "=r"(a) : "l"(p));
    return a;
}

__device__ __forceinline__ void ldsm_x4(uint32_t* r, uint32_t addr) {
    asm volatile("ldmatrix.sync.aligned.m8n8.x4.shared.b16 {%0,%1,%2,%3}, [%4];"
                 : "=r"(r[0]), "=r"(r[1]), "=r"(r[2]), "=r"(r[3]) : "r"(addr));
}

__device__ __forceinline__ void mma16816(float* d, const uint32_t* a,
                                         const uint32_t* b, const float* c) {
    asm volatile(
        "mma.sync.aligned.m16n8k16.row.col.f32.bf16.bf16.f32 "
        "{%0,%1,%2,%3}, {%4,%5,%6,%7}, {%8,%9}, {%10,%11,%12,%13};\n"
        : "=f"(d[0]), "=f"(d[1]), "=f"(d[2]), "=f"(d[3])
        : "r"(a[0]), "r"(a[1]), "r"(a[2]), "r"(a[3]),
          "r"(b[0]), "r"(b[1]),
          "f"(c[0]), "f"(c[1]), "f"(c[2]), "f"(c[3]));
}

// ------------- bf16 hi/lo split store helpers ------------------------------
__device__ __forceinline__ void store4_hilo(__nv_bfloat16* ph, __nv_bfloat16* pl,
                                            float a, float b, float c, float d) {
    __nv_bfloat16 ha = __float2bfloat16_rn(a), hb = __float2bfloat16_rn(b);
    __nv_bfloat16 hc = __float2bfloat16_rn(c), hd = __float2bfloat16_rn(d);
    __nv_bfloat16 la = __float2bfloat16_rn(a - __bfloat162float(ha));
    __nv_bfloat16 lb = __float2bfloat16_rn(b - __bfloat162float(hb));
    __nv_bfloat16 lc = __float2bfloat16_rn(c - __bfloat162float(hc));
    __nv_bfloat16 ld = __float2bfloat16_rn(d - __bfloat162float(hd));
    __nv_bfloat162 h0 = __halves2bfloat162(ha, hb), h1 = __halves2bfloat162(hc, hd);
    __nv_bfloat162 l0 = __halves2bfloat162(la, lb), l1 = __halves2bfloat162(lc, ld);
    uint2 uh, ul;
    uh.x = *reinterpret_cast<unsigned int*>(&h0); uh.y = *reinterpret_cast<unsigned int*>(&h1);
    ul.x = *reinterpret_cast<unsigned int*>(&l0); ul.y = *reinterpret_cast<unsigned int*>(&l1);
    *reinterpret_cast<uint2*>(ph) = uh;
    *reinterpret_cast<uint2*>(pl) = ul;
}

// ---------------- kernel: split fp32 -> bf16 hi/lo --------------------------
__global__ __launch_bounds__(256) void split_kernel(const float* __restrict__ in,
                                                    __nv_bfloat16* __restrict__ hi,
                                                    __nv_bfloat16* __restrict__ lo,
                                                    int n4) {
    int i = blockIdx.x * 256 + threadIdx.x;
    if (i >= n4) return;
    float4 v = reinterpret_cast<const float4*>(in)[i];
    store4_hilo(hi + 4 * (size_t)i, lo + 4 * (size_t)i, v.x, v.y, v.z, v.w);
}

// ---------------- kernel 1: rmsnorm over C, output split bf16 ---------------
__global__ __launch_bounds__(256) void rmsnorm_in_kernel(const float* __restrict__ in,
                                                         __nv_bfloat16* __restrict__ xh,
                                                         __nv_bfloat16* __restrict__ xl) {
    int row = blockIdx.x;
    const float4* ip = reinterpret_cast<const float4*>(in) + (size_t)row * 512;
    int t = threadIdx.x;
    float4 a = ip[t];
    float4 b = ip[t + 256];
    float ss = a.x*a.x + a.y*a.y + a.z*a.z + a.w*a.w
             + b.x*b.x + b.y*b.y + b.z*b.z + b.w*b.w;
    __shared__ float red[8];
    #pragma unroll
    for (int o = 16; o > 0; o >>= 1) ss += __shfl_xor_sync(0xffffffffu, ss, o);
    if ((t & 31) == 0) red[t >> 5] = ss;
    __syncthreads();
    if (t < 8) {
        float v = red[t];
        #pragma unroll
        for (int o = 4; o > 0; o >>= 1) v += __shfl_xor_sync(0xffu, v, o);
        if (t == 0) red[0] = v;
    }
    __syncthreads();
    float sc = rsqrtf(red[0] * (1.0f / 2048.0f) + RMS_EPS);
    size_t base = (size_t)row * CC;
    store4_hilo(xh + base + 4 * t,         xl + base + 4 * t,
                a.x * sc, a.y * sc, a.z * sc, a.w * sc);
    store4_hilo(xh + base + 4 * (t + 256), xl + base + 4 * (t + 256),
                b.x * sc, b.y * sc, b.z * sc, b.w * sc);
}

// ---------------- kernel 2: RoPE cos/sin tables -----------------------------
__global__ void rope_table_kernel() {
    int idx = blockIdx.x * blockDim.x + threadIdx.x;
    if (idx >= TT * 64) return;
    int t = idx >> 6;
    int p = idx & 63;
    double inv = pow(10000.0, -((double)p) / 64.0);
    float ang = (float)t * (float)inv;
    g_cos[idx] = cosf(ang);
    g_sin[idx] = sinf(ang);
}

// ---------------- kernel 3: HMMA split-bf16 GEMM ----------------------------
// C[m,n] = sum_k A[m,k]*W[n,k] (+ addend); A,W given as bf16 hi/lo splits.
// Block tile 128x128, Kc = 32. 8 warps as 2(M) x 4(N); warp tile 64x32.
#define QM 128
#define QN 128
#define QKC 32
#define LDT 40   // smem row pitch in halves (80B) -> conflict-free ldmatrix

__global__ __launch_bounds__(256, 2) void gemm_mma_kernel(
    const __nv_bfloat16* __restrict__ Ah, const __nv_bfloat16* __restrict__ Al,
    const __nv_bfloat16* __restrict__ Wh, const __nv_bfloat16* __restrict__ Wl,
    const float* __restrict__ addend, float* __restrict__ Cmat) {
    __shared__ __nv_bfloat16 sAh[QM * LDT], sAl[QM * LDT];
    __shared__ __nv_bfloat16 sWh[QN * LDT], sWl[QN * LDT];

    int tid = threadIdx.x;
    int l = tid & 31, wid = tid >> 5;
    int warp_m = wid >> 2;        // 0..1
    int warp_n = wid & 3;         // 0..3
    int m0 = blockIdx.y * QM, n0 = blockIdx.x * QN;

    float acc[4][4][4];
    #pragma unroll
    for (int i = 0; i < 4; i++)
        #pragma unroll
        for (int j = 0; j < 4; j++)
            #pragma unroll
            for (int q = 0; q < 4; q++) acc[i][j][q] = 0.f;

    uint32_t sAh_u = smem_u32(sAh), sAl_u = smem_u32(sAl);
    uint32_t sWh_u = smem_u32(sWh), sWl_u = smem_u32(sWl);

    // ldmatrix per-lane address components
    int arow = warp_m * 64 + (l & 15);       // + mt*16
    int acol = (l >> 4) << 3;                // k offset within tile
    int brow = warp_n * 32 + (l & 7) + ((l >> 4) << 3);  // + p*16
    int bk   = ((l >> 3) & 1) << 3;

    for (int k0 = 0; k0 < CC; k0 += QKC) {
        __syncthreads();
        // global -> shared: 128 rows x 32 halves per array, uint4 = 8 halves
        #pragma unroll
        for (int it = 0; it < 2; it++) {
            int idx = tid + it * 256;           // 0..511
            int r = idx >> 2, c = idx & 3;
            size_t ga = (size_t)(m0 + r) * CC + k0 + c * 8;
            size_t gw = (size_t)(n0 + r) * CC + k0 + c * 8;
            *reinterpret_cast<uint4*>(&sAh[r * LDT + c * 8]) =
                *reinterpret_cast<const uint4*>(&Ah[ga]);
            *reinterpret_cast<uint4*>(&sAl[r * LDT + c * 8]) =
                *reinterpret_cast<const uint4*>(&Al[ga]);
            *reinterpret_cast<uint4*>(&sWh[r * LDT + c * 8]) =
                *reinterpret_cast<const uint4*>(&Wh[gw]);
            *reinterpret_cast<uint4*>(&sWl[r * LDT + c * 8]) =
                *reinterpret_cast<const uint4*>(&Wl[gw]);
        }
        __syncthreads();

        #pragma unroll
        for (int ks = 0; ks < QKC; ks += 16) {
            uint32_t af[4][4], bf[2][4];
            // pass 1: Ah x Wh
            #pragma unroll
            for (int mt = 0; mt < 4; mt++)
                ldsm_x4(af[mt], sAh_u + ((arow + mt * 16) * LDT + ks + acol) * 2);
            #pragma unroll
            for (int p = 0; p < 2; p++)
                ldsm_x4(bf[p], sWh_u + ((brow + p * 16) * LDT + ks + bk) * 2);
            #pragma unroll
            for (int mt = 0; mt < 4; mt++)
                #pragma unroll
                for (int nt = 0; nt < 4; nt++)
                    mma16816(acc[mt][nt], af[mt], &bf[nt >> 1][(nt & 1) * 2], acc[mt][nt]);
            // pass 2: Ah x Wl
            #pragma unroll
            for (int p = 0; p < 2; p++)
                ldsm_x4(bf[p], sWl_u + ((brow + p * 16) * LDT + ks + bk) * 2);
            #pragma unroll
            for (int mt = 0; mt < 4; mt++)
                #pragma unroll
                for (int nt = 0; nt < 4; nt++)
                    mma16816(acc[mt][nt], af[mt], &bf[nt >> 1][(nt & 1) * 2], acc[mt][nt]);
            // pass 3: Al x Wh (reload Wh)
            #pragma unroll
            for (int mt = 0; mt < 4; mt++)
                ldsm_x4(af[mt], sAl_u + ((arow + mt * 16) * LDT + ks + acol) * 2);
            #pragma unroll
            for (int p = 0; p < 2; p++)
                ldsm_x4(bf[p], sWh_u + ((brow + p * 16) * LDT + ks + bk) * 2);
            #pragma unroll
            for (int mt = 0; mt < 4; mt++)
                #pragma unroll
                for (int nt = 0; nt < 4; nt++)
                    mma16816(acc[mt][nt], af[mt], &bf[nt >> 1][(nt & 1) * 2], acc[mt][nt]);
        }
    }

    // epilogue
    #pragma unroll
    for (int mt = 0; mt < 4; mt++) {
        #pragma unroll
        for (int nt = 0; nt < 4; nt++) {
            int row = m0 + warp_m * 64 + mt * 16 + (l >> 2);
            int col = n0 + warp_n * 32 + nt * 8 + (l & 3) * 2;
            size_t i0 = (size_t)row * CC + col;
            size_t i1 = (size_t)(row + 8) * CC + col;
            float2 v0 = make_float2(acc[mt][nt][0], acc[mt][nt][1]);
            float2 v1 = make_float2(acc[mt][nt][2], acc[mt][nt][3]);
            if (addend) {
                float2 a0 = *reinterpret_cast<const float2*>(addend + i0);
                float2 a1 = *reinterpret_cast<const float2*>(addend + i1);
                v0.x += a0.x; v0.y += a0.y;
                v1.x += a1.x; v1.y += a1.y;
            }
            *reinterpret_cast<float2*>(Cmat + i0) = v0;
            *reinterpret_cast<float2*>(Cmat + i1) = v1;
        }
    }
}

// ---------------- kernel 4: per-head rmsnorm + RoPE -------------------------
__global__ __launch_bounds__(256) void qknorm_rope_kernel(float* __restrict__ q,
                                                          float* __restrict__ k) {
    int gwarp = (blockIdx.x * 256 + threadIdx.x) >> 5;
    int lane  = threadIdx.x & 31;
    int m = gwarp >> 4;
    int h = gwarp & 15;
    int t = m & (TT - 1);
    size_t base = (size_t)m * CC + h * DH;

    float c0 = g_cos[t * 64 + lane],      s0 = g_sin[t * 64 + lane];
    float c1 = g_cos[t * 64 + 32 + lane], s1 = g_sin[t * 64 + 32 + lane];

    float* bufs[2] = {q, k};
    #pragma unroll
    for (int w = 0; w < 2; w++) {
        float* p = bufs[w] + base;
        float v0 = p[lane], v1 = p[lane + 32], v2 = p[lane + 64], v3 = p[lane + 96];
        float ss = v0*v0 + v1*v1 + v2*v2 + v3*v3;
        #pragma unroll
        for (int o = 16; o > 0; o >>= 1) ss += __shfl_xor_sync(0xffffffffu, ss, o);
        float sc = rsqrtf(ss * (1.0f / 128.0f) + RMS_EPS);
        v0 *= sc; v1 *= sc; v2 *= sc; v3 *= sc;
        p[lane]      = v0 * c0 + v2 * s0;
        p[lane + 64] = v2 * c0 - v0 * s0;
        p[lane + 32] = v1 * c1 + v3 * s1;
        p[lane + 96] = v3 * c1 - v1 * s1;
    }
}

// ---------------- kernel 5: causal flash attention (fp32) -------------------
#define AT_BM 64
#define AT_BN 64
#define ATT_SMEM_FLOATS (2 * 128 * 68 + 64 * 128 + 64 * 68)
#define ATT_SMEM_BYTES  (ATT_SMEM_FLOATS * 4)

__global__ __launch_bounds__(256) void attn_kernel(const float* __restrict__ Q,
                                                   const float* __restrict__ K,
                                                   const float* __restrict__ V,
                                                   __nv_bfloat16* __restrict__ Oh,
                                                   __nv_bfloat16* __restrict__ Ol) {
    extern __shared__ float sm[];
    float* Qst = sm;
    float* Kst = sm + 128 * 68;
    float* Vs  = sm + 2 * 128 * 68;
    float* Ps  = sm + 2 * 128 * 68 + 64 * 128;

    int tid = threadIdx.x;
    int tx = tid & 15, ty = tid >> 4;
    int qt = blockIdx.x;
    int bh = blockIdx.y;
    int b = bh >> 4, h = bh & 15;
    int m0 = qt * AT_BM;
    size_t base = (size_t)b * TT * CC + (size_t)h * DH;
    const float qscale = 1.0f / sqrtf((float)DH);

    for (int idx = tid; idx < AT_BM * 128; idx += 256) {
        int d = idx & 127, r = idx >> 7;
        Qst[d * 68 + r] = Q[base + (size_t)(m0 + r) * CC + d] * qscale;
    }

    float o[4][8];
    float mrun[4], lrun[4];
    #pragma unroll
    for (int i = 0; i < 4; i++) {
        mrun[i] = -1e30f; lrun[i] = 0.f;
        #pragma unroll
        for (int j = 0; j < 8; j++) o[i][j] = 0.f;
    }

    for (int kt = 0; kt <= qt; kt++) {
        int n0 = kt * AT_BN;
        __syncthreads();

        for (int idx = tid; idx < AT_BN * 128; idx += 256) {
            int d = idx & 127, n = idx >> 7;
            Kst[d * 68 + n] = K[base + (size_t)(n0 + n) * CC + d];
        }
        for (int f = tid; f < AT_BN * 32; f += 256) {
            int n = f >> 5, d4 = f & 31;
            reinterpret_cast<float4*>(Vs)[n * 32 + d4] =
                *reinterpret_cast<const float4*>(V + base + (size_t)(n0 + n) * CC + 4 * d4);
        }
        __syncthreads();

        float s[4][4];
        #pragma unroll
        for (int i = 0; i < 4; i++)
            #pragma unroll
            for (int j = 0; j < 4; j++) s[i][j] = 0.f;
        for (int d = 0; d < 128; d++) {
            float4 a  = *reinterpret_cast<const float4*>(&Qst[d * 68 + 4 * ty]);
            float4 bb = *reinterpret_cast<const float4*>(&Kst[d * 68 + 4 * tx]);
            float av[4] = {a.x, a.y, a.z, a.w};
            float bv[4] = {bb.x, bb.y, bb.z, bb.w};
            #pragma unroll
            for (int i = 0; i < 4; i++)
                #pragma unroll
                for (int j = 0; j < 4; j++)
                    s[i][j] += av[i] * bv[j];
        }

        bool diag = (kt == qt);
        #pragma unroll
        for (int i = 0; i < 4; i++) {
            int rg = m0 + 4 * ty + i;
            float mloc = -1e30f;
            #pragma unroll
            for (int j = 0; j < 4; j++) {
                if (diag && (n0 + 4 * tx + j > rg)) s[i][j] = -1e30f;
                mloc = fmaxf(mloc, s[i][j]);
            }
            #pragma unroll
            for (int off = 8; off > 0; off >>= 1)
                mloc = fmaxf(mloc, __shfl_xor_sync(0xffffffffu, mloc, off));
            float mnew  = fmaxf(mrun[i], mloc);
            float alpha = expf(mrun[i] - mnew);
            float rs = 0.f;
            #pragma unroll
            for (int j = 0; j < 4; j++) { s[i][j] = expf(s[i][j] - mnew); rs += s[i][j]; }
            #pragma unroll
            for (int off = 8; off > 0; off >>= 1)
                rs += __shfl_xor_sync(0xffffffffu, rs, off);
            lrun[i] = lrun[i] * alpha + rs;
            mrun[i] = mnew;
            #pragma unroll
            for (int j = 0; j < 8; j++) o[i][j] *= alpha;
            #pragma unroll
            for (int j = 0; j < 4; j++)
                Ps[(4 * ty + i) * 68 + 4 * tx + j] = s[i][j];
        }
        __syncthreads();

        for (int n = 0; n < AT_BN; n++) {
            float pp[4];
            #pragma unroll
            for (int i = 0; i < 4; i++) pp[i] = Ps[(4 * ty + i) * 68 + n];
            float4 v0 = *reinterpret_cast<const float4*>(&Vs[n * 128 + 8 * tx]);
            float4 v1 = *reinterpret_cast<const float4*>(&Vs[n * 128 + 8 * tx + 4]);
            float vv[8] = {v0.x, v0.y, v0.z, v0.w, v1.x, v1.y, v1.z, v1.w};
            #pragma unroll
            for (int i = 0; i < 4; i++)
                #pragma unroll
                for (int j = 0; j < 8; j++)
                    o[i][j] += pp[i] * vv[j];
        }
    }

    #pragma unroll
    for (int i = 0; i < 4; i++) {
        float inv = 1.0f / lrun[i];
        size_t oidx = base + (size_t)(m0 + 4 * ty + i) * CC + 8 * tx;
        store4_hilo(Oh + oidx,     Ol + oidx,
                    o[i][0] * inv, o[i][1] * inv, o[i][2] * inv, o[i][3] * inv);
        store4_hilo(Oh + oidx + 4, Ol + oidx + 4,
                    o[i][4] * inv, o[i][5] * inv, o[i][6] * inv, o[i][7] * inv);
    }
}

// ---------------- launch -----------------------------------------------------
extern "C" void kernel_launch(void* const* d_in, const int* in_sizes, int n_in,
                              void* d_out, int out_size) {
    const float* residual = (const float*)d_in[0];
    const float* w[4] = {(const float*)d_in[1], (const float*)d_in[2],
                         (const float*)d_in[3], (const float*)d_in[4]};
    float* out = (float*)d_out;

    cudaFuncSetAttribute(attn_kernel, cudaFuncAttributeMaxDynamicSharedMemorySize,
                         ATT_SMEM_BYTES);

    void *pq, *pk, *pv, *pxh, *pxl, *pyh, *pyl, *pwh, *pwl;
    cudaGetSymbolAddress(&pq, g_q);
    cudaGetSymbolAddress(&pk, g_k);
    cudaGetSymbolAddress(&pv, g_v);
    cudaGetSymbolAddress(&pxh, g_xh);
    cudaGetSymbolAddress(&pxl, g_xl);
    cudaGetSymbolAddress(&pyh, g_yh);
    cudaGetSymbolAddress(&pyl, g_yl);
    cudaGetSymbolAddress(&pwh, g_wh);
    cudaGetSymbolAddress(&pwl, g_wl);
    float* gq = (float*)pq; float* gk = (float*)pk; float* gv = (float*)pv;
    __nv_bfloat16* xh = (__nv_bfloat16*)pxh; __nv_bfloat16* xl = (__nv_bfloat16*)pxl;
    __nv_bfloat16* yh = (__nv_bfloat16*)pyh; __nv_bfloat16* yl = (__nv_bfloat16*)pyl;
    __nv_bfloat16* wh = (__nv_bfloat16*)pwh; __nv_bfloat16* wl = (__nv_bfloat16*)pwl;

    const size_t WSZ = (size_t)CC * CC;

    // 0. split weights to bf16 hi/lo
    for (int i = 0; i < 4; i++)
        split_kernel<<<(int)(WSZ / 4 / 256), 256>>>(w[i], wh + i * WSZ, wl + i * WSZ,
                                                    (int)(WSZ / 4));
    // 1. rmsnorm input -> split bf16
    rmsnorm_in_kernel<<<BT, 256>>>(residual, xh, xl);
    // 2. rope tables
    rope_table_kernel<<<(TT * 64 + 255) / 256, 256>>>();
    // 3. QKV projections (HMMA tensor cores, split-bf16)
    dim3 ggrid(CC / QN, BT / QM);
    gemm_mma_kernel<<<ggrid, 256>>>(xh, xl, wh + 0 * WSZ, wl + 0 * WSZ, nullptr, gq);
    gemm_mma_kernel<<<ggrid, 256>>>(xh, xl, wh + 1 * WSZ, wl + 1 * WSZ, nullptr, gk);
    gemm_mma_kernel<<<ggrid, 256>>>(xh, xl, wh + 2 * WSZ, wl + 2 * WSZ, nullptr, gv);
    // 4. per-head rmsnorm + rope
    qknorm_rope_kernel<<<(BT * HH) / 8, 256>>>(gq, gk);
    // 5. causal flash attention (writes split bf16 y)
    dim3 agrid(TT / AT_BM, BB * HH);
    attn_kernel<<<agrid, 256, ATT_SMEM_BYTES>>>(gq, gk, gv, yh, yl);
    // 6. output projection + residual add (HMMA tensor cores)
    gemm_mma_kernel<<<ggrid, 256>>>(yh, yl, wh + 3 * WSZ, wl + 3 * WSZ, residual, out);
}

// round 7
// speedup vs baseline: 1.6093x; 1.0000x over previous
#include <cuda_runtime.h>
#include <cuda_bf16.h>
#include <math.h>
#include <stdint.h>

// Problem constants
#define BB   4
#define TT   2048
#define CC   2048
#define HH   16
#define DH   128
#define BT   (BB * TT)          // 8192
#define ELEMS ((size_t)BT * CC) // 16777216

#define RMS_EPS 1.1920928955078125e-07f

// ---------------- scratch (device globals; no allocation allowed) ----------
__device__ __align__(16) float g_q[ELEMS];
__device__ __align__(16) float g_k[ELEMS];
__device__ __align__(16) float g_v[ELEMS];
__device__ __align__(16) __nv_bfloat16 g_xh[ELEMS];
__device__ __align__(16) __nv_bfloat16 g_xl[ELEMS];
__device__ __align__(16) __nv_bfloat16 g_yh[ELEMS];
__device__ __align__(16) __nv_bfloat16 g_yl[ELEMS];
__device__ __align__(16) __nv_bfloat16 g_wh[4][(size_t)CC * CC];
__device__ __align__(16) __nv_bfloat16 g_wl[4][(size_t)CC * CC];
__device__ __align__(16) float g_cos[TT * 64];
__device__ __align__(16) float g_sin[TT * 64];

// ======================= PTX helpers (portable, no 'a' features) ============
__device__ __forceinline__ uint32_t smem_u32(const void* p) {
    uint32_t a;
    asm("{ .reg .u64 t; cvta.to.shared.u64 t, %1; cvt.u32.u64 %0, t; }"
        : "=r"(a) : "l"(p));
    return a;
}

__device__ __forceinline__ void ldsm_x4(uint32_t* r, uint32_t addr) {
    asm volatile("ldmatrix.sync.aligned.m8n8.x4.shared.b16 {%0,%1,%2,%3}, [%4];"
                 : "=r"(r[0]), "=r"(r[1]), "=r"(r[2]), "=r"(r[3]) : "r"(addr));
}

__device__ __forceinline__ void mma16816(float* d, const uint32_t* a,
                                         const uint32_t* b, const float* c) {
    asm volatile(
        "mma.sync.aligned.m16n8k16.row.col.f32.bf16.bf16.f32 "
        "{%0,%1,%2,%3}, {%4,%5,%6,%7}, {%8,%9}, {%10,%11,%12,%13};\n"
        : "=f"(d[0]), "=f"(d[1]), "=f"(d[2]), "=f"(d[3])
        : "r"(a[0]), "r"(a[1]), "r"(a[2]), "r"(a[3]),
          "r"(b[0]), "r"(b[1]),
          "f"(c[0]), "f"(c[1]), "f"(c[2]), "f"(c[3]));
}

// ------------- bf16 hi/lo split store helpers ------------------------------
__device__ __forceinline__ void store4_hilo(__nv_bfloat16* ph, __nv_bfloat16* pl,
                                            float a, float b, float c, float d) {
    __nv_bfloat16 ha = __float2bfloat16_rn(a), hb = __float2bfloat16_rn(b);
    __nv_bfloat16 hc = __float2bfloat16_rn(c), hd = __float2bfloat16_rn(d);
    __nv_bfloat16 la = __float2bfloat16_rn(a - __bfloat162float(ha));
    __nv_bfloat16 lb = __float2bfloat16_rn(b - __bfloat162float(hb));
    __nv_bfloat16 lc = __float2bfloat16_rn(c - __bfloat162float(hc));
    __nv_bfloat16 ld = __float2bfloat16_rn(d - __bfloat162float(hd));
    __nv_bfloat162 h0 = __halves2bfloat162(ha, hb), h1 = __halves2bfloat162(hc, hd);
    __nv_bfloat162 l0 = __halves2bfloat162(la, lb), l1 = __halves2bfloat162(lc, ld);
    uint2 uh, ul;
    uh.x = *reinterpret_cast<unsigned int*>(&h0); uh.y = *reinterpret_cast<unsigned int*>(&h1);
    ul.x = *reinterpret_cast<unsigned int*>(&l0); ul.y = *reinterpret_cast<unsigned int*>(&l1);
    *reinterpret_cast<uint2*>(ph) = uh;
    *reinterpret_cast<uint2*>(pl) = ul;
}

// ---------------- kernel: split fp32 -> bf16 hi/lo --------------------------
__global__ __launch_bounds__(256) void split_kernel(const float* __restrict__ in,
                                                    __nv_bfloat16* __restrict__ hi,
                                                    __nv_bfloat16* __restrict__ lo,
                                                    int n4) {
    int i = blockIdx.x * 256 + threadIdx.x;
    if (i >= n4) return;
    float4 v = reinterpret_cast<const float4*>(in)[i];
    store4_hilo(hi + 4 * (size_t)i, lo + 4 * (size_t)i, v.x, v.y, v.z, v.w);
}

// ---------------- kernel 1: rmsnorm over C, output split bf16 ---------------
__global__ __launch_bounds__(256) void rmsnorm_in_kernel(const float* __restrict__ in,
                                                         __nv_bfloat16* __restrict__ xh,
                                                         __nv_bfloat16* __restrict__ xl) {
    int row = blockIdx.x;
    const float4* ip = reinterpret_cast<const float4*>(in) + (size_t)row * 512;
    int t = threadIdx.x;
    float4 a = ip[t];
    float4 b = ip[t + 256];
    float ss = a.x*a.x + a.y*a.y + a.z*a.z + a.w*a.w
             + b.x*b.x + b.y*b.y + b.z*b.z + b.w*b.w;
    __shared__ float red[8];
    #pragma unroll
    for (int o = 16; o > 0; o >>= 1) ss += __shfl_xor_sync(0xffffffffu, ss, o);
    if ((t & 31) == 0) red[t >> 5] = ss;
    __syncthreads();
    if (t < 8) {
        float v = red[t];
        #pragma unroll
        for (int o = 4; o > 0; o >>= 1) v += __shfl_xor_sync(0xffu, v, o);
        if (t == 0) red[0] = v;
    }
    __syncthreads();
    float sc = rsqrtf(red[0] * (1.0f / 2048.0f) + RMS_EPS);
    size_t base = (size_t)row * CC;
    store4_hilo(xh + base + 4 * t,         xl + base + 4 * t,
                a.x * sc, a.y * sc, a.z * sc, a.w * sc);
    store4_hilo(xh + base + 4 * (t + 256), xl + base + 4 * (t + 256),
                b.x * sc, b.y * sc, b.z * sc, b.w * sc);
}

// ---------------- kernel 2: RoPE cos/sin tables -----------------------------
__global__ void rope_table_kernel() {
    int idx = blockIdx.x * blockDim.x + threadIdx.x;
    if (idx >= TT * 64) return;
    int t = idx >> 6;
    int p = idx & 63;
    double inv = pow(10000.0, -((double)p) / 64.0);
    float ang = (float)t * (float)inv;
    g_cos[idx] = cosf(ang);
    g_sin[idx] = sinf(ang);
}

// ---------------- kernel 3: HMMA split-bf16 GEMM ----------------------------
// C[m,n] = sum_k A[m,k]*W[n,k] (+ addend); A,W given as bf16 hi/lo splits.
// Block tile 128x128, Kc = 32. 8 warps as 2(M) x 4(N); warp tile 64x32.
#define QM 128
#define QN 128
#define QKC 32
#define LDT 40   // smem row pitch in halves (80B) -> conflict-free ldmatrix

__global__ __launch_bounds__(256, 2) void gemm_mma_kernel(
    const __nv_bfloat16* __restrict__ Ah, const __nv_bfloat16* __restrict__ Al,
    const __nv_bfloat16* __restrict__ Wh, const __nv_bfloat16* __restrict__ Wl,
    const float* __restrict__ addend, float* __restrict__ Cmat) {
    __shared__ __nv_bfloat16 sAh[QM * LDT], sAl[QM * LDT];
    __shared__ __nv_bfloat16 sWh[QN * LDT], sWl[QN * LDT];

    int tid = threadIdx.x;
    int l = tid & 31, wid = tid >> 5;
    int warp_m = wid >> 2;        // 0..1
    int warp_n = wid & 3;         // 0..3
    int m0 = blockIdx.y * QM, n0 = blockIdx.x * QN;

    float acc[4][4][4];
    #pragma unroll
    for (int i = 0; i < 4; i++)
        #pragma unroll
        for (int j = 0; j < 4; j++)
            #pragma unroll
            for (int q = 0; q < 4; q++) acc[i][j][q] = 0.f;

    uint32_t sAh_u = smem_u32(sAh), sAl_u = smem_u32(sAl);
    uint32_t sWh_u = smem_u32(sWh), sWl_u = smem_u32(sWl);

    // ldmatrix per-lane address components
    int arow = warp_m * 64 + (l & 15);       // + mt*16
    int acol = (l >> 4) << 3;                // k offset within tile
    int brow = warp_n * 32 + (l & 7) + ((l >> 4) << 3);  // + p*16
    int bk   = ((l >> 3) & 1) << 3;

    for (int k0 = 0; k0 < CC; k0 += QKC) {
        __syncthreads();
        // global -> shared: 128 rows x 32 halves per array, uint4 = 8 halves
        #pragma unroll
        for (int it = 0; it < 2; it++) {
            int idx = tid + it * 256;           // 0..511
            int r = idx >> 2, c = idx & 3;
            size_t ga = (size_t)(m0 + r) * CC + k0 + c * 8;
            size_t gw = (size_t)(n0 + r) * CC + k0 + c * 8;
            *reinterpret_cast<uint4*>(&sAh[r * LDT + c * 8]) =
                *reinterpret_cast<const uint4*>(&Ah[ga]);
            *reinterpret_cast<uint4*>(&sAl[r * LDT + c * 8]) =
                *reinterpret_cast<const uint4*>(&Al[ga]);
            *reinterpret_cast<uint4*>(&sWh[r * LDT + c * 8]) =
                *reinterpret_cast<const uint4*>(&Wh[gw]);
            *reinterpret_cast<uint4*>(&sWl[r * LDT + c * 8]) =
                *reinterpret_cast<const uint4*>(&Wl[gw]);
        }
        __syncthreads();

        #pragma unroll
        for (int ks = 0; ks < QKC; ks += 16) {
            uint32_t af[4][4], bf[2][4];
            // pass 1: Ah x Wh
            #pragma unroll
            for (int mt = 0; mt < 4; mt++)
                ldsm_x4(af[mt], sAh_u + ((arow + mt * 16) * LDT + ks + acol) * 2);
            #pragma unroll
            for (int p = 0; p < 2; p++)
                ldsm_x4(bf[p], sWh_u + ((brow + p * 16) * LDT + ks + bk) * 2);
            #pragma unroll
            for (int mt = 0; mt < 4; mt++)
                #pragma unroll
                for (int nt = 0; nt < 4; nt++)
                    mma16816(acc[mt][nt], af[mt], &bf[nt >> 1][(nt & 1) * 2], acc[mt][nt]);
            // pass 2: Ah x Wl
            #pragma unroll
            for (int p = 0; p < 2; p++)
                ldsm_x4(bf[p], sWl_u + ((brow + p * 16) * LDT + ks + bk) * 2);
            #pragma unroll
            for (int mt = 0; mt < 4; mt++)
                #pragma unroll
                for (int nt = 0; nt < 4; nt++)
                    mma16816(acc[mt][nt], af[mt], &bf[nt >> 1][(nt & 1) * 2], acc[mt][nt]);
            // pass 3: Al x Wh (reload Wh)
            #pragma unroll
            for (int mt = 0; mt < 4; mt++)
                ldsm_x4(af[mt], sAl_u + ((arow + mt * 16) * LDT + ks + acol) * 2);
            #pragma unroll
            for (int p = 0; p < 2; p++)
                ldsm_x4(bf[p], sWh_u + ((brow + p * 16) * LDT + ks + bk) * 2);
            #pragma unroll
            for (int mt = 0; mt < 4; mt++)
                #pragma unroll
                for (int nt = 0; nt < 4; nt++)
                    mma16816(acc[mt][nt], af[mt], &bf[nt >> 1][(nt & 1) * 2], acc[mt][nt]);
        }
    }

    // epilogue
    #pragma unroll
    for (int mt = 0; mt < 4; mt++) {
        #pragma unroll
        for (int nt = 0; nt < 4; nt++) {
            int row = m0 + warp_m * 64 + mt * 16 + (l >> 2);
            int col = n0 + warp_n * 32 + nt * 8 + (l & 3) * 2;
            size_t i0 = (size_t)row * CC + col;
            size_t i1 = (size_t)(row + 8) * CC + col;
            float2 v0 = make_float2(acc[mt][nt][0], acc[mt][nt][1]);
            float2 v1 = make_float2(acc[mt][nt][2], acc[mt][nt][3]);
            if (addend) {
                float2 a0 = *reinterpret_cast<const float2*>(addend + i0);
                float2 a1 = *reinterpret_cast<const float2*>(addend + i1);
                v0.x += a0.x; v0.y += a0.y;
                v1.x += a1.x; v1.y += a1.y;
            }
            *reinterpret_cast<float2*>(Cmat + i0) = v0;
            *reinterpret_cast<float2*>(Cmat + i1) = v1;
        }
    }
}

// ---------------- kernel 4: per-head rmsnorm + RoPE -------------------------
__global__ __launch_bounds__(256) void qknorm_rope_kernel(float* __restrict__ q,
                                                          float* __restrict__ k) {
    int gwarp = (blockIdx.x * 256 + threadIdx.x) >> 5;
    int lane  = threadIdx.x & 31;
    int m = gwarp >> 4;
    int h = gwarp & 15;
    int t = m & (TT - 1);
    size_t base = (size_t)m * CC + h * DH;

    float c0 = g_cos[t * 64 + lane],      s0 = g_sin[t * 64 + lane];
    float c1 = g_cos[t * 64 + 32 + lane], s1 = g_sin[t * 64 + 32 + lane];

    float* bufs[2] = {q, k};
    #pragma unroll
    for (int w = 0; w < 2; w++) {
        float* p = bufs[w] + base;
        float v0 = p[lane], v1 = p[lane + 32], v2 = p[lane + 64], v3 = p[lane + 96];
        float ss = v0*v0 + v1*v1 + v2*v2 + v3*v3;
        #pragma unroll
        for (int o = 16; o > 0; o >>= 1) ss += __shfl_xor_sync(0xffffffffu, ss, o);
        float sc = rsqrtf(ss * (1.0f / 128.0f) + RMS_EPS);
        v0 *= sc; v1 *= sc; v2 *= sc; v3 *= sc;
        p[lane]      = v0 * c0 + v2 * s0;
        p[lane + 64] = v2 * c0 - v0 * s0;
        p[lane + 32] = v1 * c1 + v3 * s1;
        p[lane + 96] = v3 * c1 - v1 * s1;
    }
}

// ---------------- kernel 5: causal flash attention (fp32) -------------------
#define AT_BM 64
#define AT_BN 64
#define ATT_SMEM_FLOATS (2 * 128 * 68 + 64 * 128 + 64 * 68)
#define ATT_SMEM_BYTES  (ATT_SMEM_FLOATS * 4)

__global__ __launch_bounds__(256) void attn_kernel(const float* __restrict__ Q,
                                                   const float* __restrict__ K,
                                                   const float* __restrict__ V,
                                                   __nv_bfloat16* __restrict__ Oh,
                                                   __nv_bfloat16* __restrict__ Ol) {
    extern __shared__ float sm[];
    float* Qst = sm;
    float* Kst = sm + 128 * 68;
    float* Vs  = sm + 2 * 128 * 68;
    float* Ps  = sm + 2 * 128 * 68 + 64 * 128;

    int tid = threadIdx.x;
    int tx = tid & 15, ty = tid >> 4;
    int qt = blockIdx.x;
    int bh = blockIdx.y;
    int b = bh >> 4, h = bh & 15;
    int m0 = qt * AT_BM;
    size_t base = (size_t)b * TT * CC + (size_t)h * DH;
    const float qscale = 1.0f / sqrtf((float)DH);

    for (int idx = tid; idx < AT_BM * 128; idx += 256) {
        int d = idx & 127, r = idx >> 7;
        Qst[d * 68 + r] = Q[base + (size_t)(m0 + r) * CC + d] * qscale;
    }

    float o[4][8];
    float mrun[4], lrun[4];
    #pragma unroll
    for (int i = 0; i < 4; i++) {
        mrun[i] = -1e30f; lrun[i] = 0.f;
        #pragma unroll
        for (int j = 0; j < 8; j++) o[i][j] = 0.f;
    }

    for (int kt = 0; kt <= qt; kt++) {
        int n0 = kt * AT_BN;
        __syncthreads();

        for (int idx = tid; idx < AT_BN * 128; idx += 256) {
            int d = idx & 127, n = idx >> 7;
            Kst[d * 68 + n] = K[base + (size_t)(n0 + n) * CC + d];
        }
        for (int f = tid; f < AT_BN * 32; f += 256) {
            int n = f >> 5, d4 = f & 31;
            reinterpret_cast<float4*>(Vs)[n * 32 + d4] =
                *reinterpret_cast<const float4*>(V + base + (size_t)(n0 + n) * CC + 4 * d4);
        }
        __syncthreads();

        float s[4][4];
        #pragma unroll
        for (int i = 0; i < 4; i++)
            #pragma unroll
            for (int j = 0; j < 4; j++) s[i][j] = 0.f;
        for (int d = 0; d < 128; d++) {
            float4 a  = *reinterpret_cast<const float4*>(&Qst[d * 68 + 4 * ty]);
            float4 bb = *reinterpret_cast<const float4*>(&Kst[d * 68 + 4 * tx]);
            float av[4] = {a.x, a.y, a.z, a.w};
            float bv[4] = {bb.x, bb.y, bb.z, bb.w};
            #pragma unroll
            for (int i = 0; i < 4; i++)
                #pragma unroll
                for (int j = 0; j < 4; j++)
                    s[i][j] += av[i] * bv[j];
        }

        bool diag = (kt == qt);
        #pragma unroll
        for (int i = 0; i < 4; i++) {
            int rg = m0 + 4 * ty + i;
            float mloc = -1e30f;
            #pragma unroll
            for (int j = 0; j < 4; j++) {
                if (diag && (n0 + 4 * tx + j > rg)) s[i][j] = -1e30f;
                mloc = fmaxf(mloc, s[i][j]);
            }
            #pragma unroll
            for (int off = 8; off > 0; off >>= 1)
                mloc = fmaxf(mloc, __shfl_xor_sync(0xffffffffu, mloc, off));
            float mnew  = fmaxf(mrun[i], mloc);
            float alpha = expf(mrun[i] - mnew);
            float rs = 0.f;
            #pragma unroll
            for (int j = 0; j < 4; j++) { s[i][j] = expf(s[i][j] - mnew); rs += s[i][j]; }
            #pragma unroll
            for (int off = 8; off > 0; off >>= 1)
                rs += __shfl_xor_sync(0xffffffffu, rs, off);
            lrun[i] = lrun[i] * alpha + rs;
            mrun[i] = mnew;
            #pragma unroll
            for (int j = 0; j < 8; j++) o[i][j] *= alpha;
            #pragma unroll
            for (int j = 0; j < 4; j++)
                Ps[(4 * ty + i) * 68 + 4 * tx + j] = s[i][j];
        }
        __syncthreads();

        for (int n = 0; n < AT_BN; n++) {
            float pp[4];
            #pragma unroll
            for (int i = 0; i < 4; i++) pp[i] = Ps[(4 * ty + i) * 68 + n];
            float4 v0 = *reinterpret_cast<const float4*>(&Vs[n * 128 + 8 * tx]);
            float4 v1 = *reinterpret_cast<const float4*>(&Vs[n * 128 + 8 * tx + 4]);
            float vv[8] = {v0.x, v0.y, v0.z, v0.w, v1.x, v1.y, v1.z, v1.w};
            #pragma unroll
            for (int i = 0; i < 4; i++)
                #pragma unroll
                for (int j = 0; j < 8; j++)
                    o[i][j] += pp[i] * vv[j];
        }
    }

    #pragma unroll
    for (int i = 0; i < 4; i++) {
        float inv = 1.0f / lrun[i];
        size_t oidx = base + (size_t)(m0 + 4 * ty + i) * CC + 8 * tx;
        store4_hilo(Oh + oidx,     Ol + oidx,
                    o[i][0] * inv, o[i][1] * inv, o[i][2] * inv, o[i][3] * inv);
        store4_hilo(Oh + oidx + 4, Ol + oidx + 4,
                    o[i][4] * inv, o[i][5] * inv, o[i][6] * inv, o[i][7] * inv);
    }
}

// ---------------- launch -----------------------------------------------------
extern "C" void kernel_launch(void* const* d_in, const int* in_sizes, int n_in,
                              void* d_out, int out_size) {
    const float* residual = (const float*)d_in[0];
    const float* w[4] = {(const float*)d_in[1], (const float*)d_in[2],
                         (const float*)d_in[3], (const float*)d_in[4]};
    float* out = (float*)d_out;

    cudaFuncSetAttribute(attn_kernel, cudaFuncAttributeMaxDynamicSharedMemorySize,
                         ATT_SMEM_BYTES);

    void *pq, *pk, *pv, *pxh, *pxl, *pyh, *pyl, *pwh, *pwl;
    cudaGetSymbolAddress(&pq, g_q);
    cudaGetSymbolAddress(&pk, g_k);
    cudaGetSymbolAddress(&pv, g_v);
    cudaGetSymbolAddress(&pxh, g_xh);
    cudaGetSymbolAddress(&pxl, g_xl);
    cudaGetSymbolAddress(&pyh, g_yh);
    cudaGetSymbolAddress(&pyl, g_yl);
    cudaGetSymbolAddress(&pwh, g_wh);
    cudaGetSymbolAddress(&pwl, g_wl);
    float* gq = (float*)pq; float* gk = (float*)pk; float* gv = (float*)pv;
    __nv_bfloat16* xh = (__nv_bfloat16*)pxh; __nv_bfloat16* xl = (__nv_bfloat16*)pxl;
    __nv_bfloat16* yh = (__nv_bfloat16*)pyh; __nv_bfloat16* yl = (__nv_bfloat16*)pyl;
    __nv_bfloat16* wh = (__nv_bfloat16*)pwh; __nv_bfloat16* wl = (__nv_bfloat16*)pwl;

    const size_t WSZ = (size_t)CC * CC;

    // 0. split weights to bf16 hi/lo
    for (int i = 0; i < 4; i++)
        split_kernel<<<(int)(WSZ / 4 / 256), 256>>>(w[i], wh + i * WSZ, wl + i * WSZ,
                                                    (int)(WSZ / 4));
    // 1. rmsnorm input -> split bf16
    rmsnorm_in_kernel<<<BT, 256>>>(residual, xh, xl);
    // 2. rope tables
    rope_table_kernel<<<(TT * 64 + 255) / 256, 256>>>();
    // 3. QKV projections (HMMA tensor cores, split-bf16)
    dim3 ggrid(CC / QN, BT / QM);
    gemm_mma_kernel<<<ggrid, 256>>>(xh, xl, wh + 0 * WSZ, wl + 0 * WSZ, nullptr, gq);
    gemm_mma_kernel<<<ggrid, 256>>>(xh, xl, wh + 1 * WSZ, wl + 1 * WSZ, nullptr, gk);
    gemm_mma_kernel<<<ggrid, 256>>>(xh, xl, wh + 2 * WSZ, wl + 2 * WSZ, nullptr, gv);
    // 4. per-head rmsnorm + rope
    qknorm_rope_kernel<<<(BT * HH) / 8, 256>>>(gq, gk);
    // 5. causal flash attention (writes split bf16 y)
    dim3 agrid(TT / AT_BM, BB * HH);
    attn_kernel<<<agrid, 256, ATT_SMEM_BYTES>>>(gq, gk, gv, yh, yl);
    // 6. output projection + residual add (HMMA tensor cores)
    gemm_mma_kernel<<<ggrid, 256>>>(yh, yl, wh + 3 * WSZ, wl + 3 * WSZ, residual, out);
}

// round 8
// speedup vs baseline: 2.7924x; 1.7352x over previous
#include <cuda_runtime.h>
#include <cuda_bf16.h>
#include <math.h>
#include <stdint.h>

// Problem constants
#define BB   4
#define TT   2048
#define CC   2048
#define HH   16
#define DH   128
#define BT   (BB * TT)          // 8192
#define ELEMS ((size_t)BT * CC) // 16777216

#define RMS_EPS 1.1920928955078125e-07f

// ---------------- scratch (device globals; no allocation allowed) ----------
__device__ __align__(16) float g_q[ELEMS];
__device__ __align__(16) float g_k[ELEMS];
__device__ __align__(16) float g_v[ELEMS];
__device__ __align__(16) __nv_bfloat16 g_xh[ELEMS];
__device__ __align__(16) __nv_bfloat16 g_xl[ELEMS];
__device__ __align__(16) __nv_bfloat16 g_yh[ELEMS];
__device__ __align__(16) __nv_bfloat16 g_yl[ELEMS];
__device__ __align__(16) __nv_bfloat16 g_qh[ELEMS];
__device__ __align__(16) __nv_bfloat16 g_ql[ELEMS];
__device__ __align__(16) __nv_bfloat16 g_kh[ELEMS];
__device__ __align__(16) __nv_bfloat16 g_kl[ELEMS];
__device__ __align__(16) __nv_bfloat16 g_vh[ELEMS];
__device__ __align__(16) __nv_bfloat16 g_vl[ELEMS];
__device__ __align__(16) __nv_bfloat16 g_wh[4][(size_t)CC * CC];
__device__ __align__(16) __nv_bfloat16 g_wl[4][(size_t)CC * CC];
__device__ __align__(16) float g_cos[TT * 64];
__device__ __align__(16) float g_sin[TT * 64];

// ======================= PTX helpers (portable, no 'a' features) ============
__device__ __forceinline__ uint32_t smem_u32(const void* p) {
    uint32_t a;
    asm("{ .reg .u64 t; cvta.to.shared.u64 t, %1; cvt.u32.u64 %0, t; }"
        : "=r"(a) : "l"(p));
    return a;
}

__device__ __forceinline__ void ldsm_x4(uint32_t* r, uint32_t addr) {
    asm volatile("ldmatrix.sync.aligned.m8n8.x4.shared.b16 {%0,%1,%2,%3}, [%4];"
                 : "=r"(r[0]), "=r"(r[1]), "=r"(r[2]), "=r"(r[3]) : "r"(addr));
}
__device__ __forceinline__ void ldsm_x4_t(uint32_t* r, uint32_t addr) {
    asm volatile("ldmatrix.sync.aligned.m8n8.x4.trans.shared.b16 {%0,%1,%2,%3}, [%4];"
                 : "=r"(r[0]), "=r"(r[1]), "=r"(r[2]), "=r"(r[3]) : "r"(addr));
}

__device__ __forceinline__ void mma16816(float* d, const uint32_t* a,
                                         const uint32_t* b, const float* c) {
    asm volatile(
        "mma.sync.aligned.m16n8k16.row.col.f32.bf16.bf16.f32 "
        "{%0,%1,%2,%3}, {%4,%5,%6,%7}, {%8,%9}, {%10,%11,%12,%13};\n"
        : "=f"(d[0]), "=f"(d[1]), "=f"(d[2]), "=f"(d[3])
        : "r"(a[0]), "r"(a[1]), "r"(a[2]), "r"(a[3]),
          "r"(b[0]), "r"(b[1]),
          "f"(c[0]), "f"(c[1]), "f"(c[2]), "f"(c[3]));
}

// pack two fp32 into bf16x2 (lo -> low half)
__device__ __forceinline__ uint32_t packbf(float lo, float hi) {
    uint32_t d;
    asm("cvt.rn.bf16x2.f32 %0, %1, %2;" : "=r"(d) : "f"(hi), "f"(lo));
    return d;
}
__device__ __forceinline__ float bfhi(float x) {
    return __bfloat162float(__float2bfloat16_rn(x));
}

// fast e^x for x <= 0 (no MUFU): 2^y with rint + deg-5 poly, rel err ~2.4e-6
__device__ __forceinline__ float fexp(float x) {
    float y = x * 1.4426950408889634f;
    y = fmaxf(y, -126.0f);
    float nf = rintf(y);
    float f = y - nf;
    float p = 1.3333558146e-3f;
    p = fmaf(p, f, 9.6181291076e-3f);
    p = fmaf(p, f, 5.5504108664e-2f);
    p = fmaf(p, f, 2.4022650696e-1f);
    p = fmaf(p, f, 6.9314718056e-1f);
    p = fmaf(p, f, 1.0f);
    return __int_as_float(__float_as_int(p) + (((int)nf) << 23));
}

// ------------- bf16 hi/lo split store helpers ------------------------------
__device__ __forceinline__ void store4_hilo(__nv_bfloat16* ph, __nv_bfloat16* pl,
                                            float a, float b, float c, float d) {
    __nv_bfloat16 ha = __float2bfloat16_rn(a), hb = __float2bfloat16_rn(b);
    __nv_bfloat16 hc = __float2bfloat16_rn(c), hd = __float2bfloat16_rn(d);
    __nv_bfloat16 la = __float2bfloat16_rn(a - __bfloat162float(ha));
    __nv_bfloat16 lb = __float2bfloat16_rn(b - __bfloat162float(hb));
    __nv_bfloat16 lc = __float2bfloat16_rn(c - __bfloat162float(hc));
    __nv_bfloat16 ld = __float2bfloat16_rn(d - __bfloat162float(hd));
    __nv_bfloat162 h0 = __halves2bfloat162(ha, hb), h1 = __halves2bfloat162(hc, hd);
    __nv_bfloat162 l0 = __halves2bfloat162(la, lb), l1 = __halves2bfloat162(lc, ld);
    uint2 uh, ul;
    uh.x = *reinterpret_cast<unsigned int*>(&h0); uh.y = *reinterpret_cast<unsigned int*>(&h1);
    ul.x = *reinterpret_cast<unsigned int*>(&l0); ul.y = *reinterpret_cast<unsigned int*>(&l1);
    *reinterpret_cast<uint2*>(ph) = uh;
    *reinterpret_cast<uint2*>(pl) = ul;
}

__device__ __forceinline__ void store1_hilo(__nv_bfloat16* ph, __nv_bfloat16* pl, float v) {
    __nv_bfloat16 h = __float2bfloat16_rn(v);
    *ph = h;
    *pl = __float2bfloat16_rn(v - __bfloat162float(h));
}

__device__ __forceinline__ void store2_hilo(__nv_bfloat16* ph, __nv_bfloat16* pl,
                                            float a, float b) {
    uint32_t hv = packbf(a, b);
    float ra = a - bfhi(a), rb = b - bfhi(b);
    uint32_t lv = packbf(ra, rb);
    *reinterpret_cast<uint32_t*>(ph) = hv;
    *reinterpret_cast<uint32_t*>(pl) = lv;
}

// ---------------- kernel: split fp32 -> bf16 hi/lo --------------------------
__global__ __launch_bounds__(256) void split_kernel(const float* __restrict__ in,
                                                    __nv_bfloat16* __restrict__ hi,
                                                    __nv_bfloat16* __restrict__ lo,
                                                    int n4) {
    int i = blockIdx.x * 256 + threadIdx.x;
    if (i >= n4) return;
    float4 v = reinterpret_cast<const float4*>(in)[i];
    store4_hilo(hi + 4 * (size_t)i, lo + 4 * (size_t)i, v.x, v.y, v.z, v.w);
}

// ---------------- kernel 1: rmsnorm over C, output split bf16 ---------------
__global__ __launch_bounds__(256) void rmsnorm_in_kernel(const float* __restrict__ in,
                                                         __nv_bfloat16* __restrict__ xh,
                                                         __nv_bfloat16* __restrict__ xl) {
    int row = blockIdx.x;
    const float4* ip = reinterpret_cast<const float4*>(in) + (size_t)row * 512;
    int t = threadIdx.x;
    float4 a = ip[t];
    float4 b = ip[t + 256];
    float ss = a.x*a.x + a.y*a.y + a.z*a.z + a.w*a.w
             + b.x*b.x + b.y*b.y + b.z*b.z + b.w*b.w;
    __shared__ float red[8];
    #pragma unroll
    for (int o = 16; o > 0; o >>= 1) ss += __shfl_xor_sync(0xffffffffu, ss, o);
    if ((t & 31) == 0) red[t >> 5] = ss;
    __syncthreads();
    if (t < 8) {
        float v = red[t];
        #pragma unroll
        for (int o = 4; o > 0; o >>= 1) v += __shfl_xor_sync(0xffu, v, o);
        if (t == 0) red[0] = v;
    }
    __syncthreads();
    float sc = rsqrtf(red[0] * (1.0f / 2048.0f) + RMS_EPS);
    size_t base = (size_t)row * CC;
    store4_hilo(xh + base + 4 * t,         xl + base + 4 * t,
                a.x * sc, a.y * sc, a.z * sc, a.w * sc);
    store4_hilo(xh + base + 4 * (t + 256), xl + base + 4 * (t + 256),
                b.x * sc, b.y * sc, b.z * sc, b.w * sc);
}

// ---------------- kernel 2: RoPE cos/sin tables -----------------------------
__global__ void rope_table_kernel() {
    int idx = blockIdx.x * blockDim.x + threadIdx.x;
    if (idx >= TT * 64) return;
    int t = idx >> 6;
    int p = idx & 63;
    double inv = pow(10000.0, -((double)p) / 64.0);
    float ang = (float)t * (float)inv;
    g_cos[idx] = cosf(ang);
    g_sin[idx] = sinf(ang);
}

// ---------------- kernel 3: HMMA split-bf16 GEMM ----------------------------
#define QM 128
#define QN 128
#define QKC 32
#define LDT 40   // smem row pitch in halves (80B) -> conflict-free ldmatrix

__global__ __launch_bounds__(256, 2) void gemm_mma_kernel(
    const __nv_bfloat16* __restrict__ Ah, const __nv_bfloat16* __restrict__ Al,
    const __nv_bfloat16* __restrict__ Wh, const __nv_bfloat16* __restrict__ Wl,
    const float* __restrict__ addend, float* __restrict__ Cmat) {
    __shared__ __nv_bfloat16 sAh[QM * LDT], sAl[QM * LDT];
    __shared__ __nv_bfloat16 sWh[QN * LDT], sWl[QN * LDT];

    int tid = threadIdx.x;
    int l = tid & 31, wid = tid >> 5;
    int warp_m = wid >> 2;
    int warp_n = wid & 3;
    int m0 = blockIdx.y * QM, n0 = blockIdx.x * QN;

    float acc[4][4][4];
    #pragma unroll
    for (int i = 0; i < 4; i++)
        #pragma unroll
        for (int j = 0; j < 4; j++)
            #pragma unroll
            for (int q = 0; q < 4; q++) acc[i][j][q] = 0.f;

    uint32_t sAh_u = smem_u32(sAh), sAl_u = smem_u32(sAl);
    uint32_t sWh_u = smem_u32(sWh), sWl_u = smem_u32(sWl);

    int arow = warp_m * 64 + (l & 15);
    int acol = (l >> 4) << 3;
    int brow = warp_n * 32 + (l & 7) + ((l >> 4) << 3);
    int bk   = ((l >> 3) & 1) << 3;

    for (int k0 = 0; k0 < CC; k0 += QKC) {
        __syncthreads();
        #pragma unroll
        for (int it = 0; it < 2; it++) {
            int idx = tid + it * 256;
            int r = idx >> 2, c = idx & 3;
            size_t ga = (size_t)(m0 + r) * CC + k0 + c * 8;
            size_t gw = (size_t)(n0 + r) * CC + k0 + c * 8;
            *reinterpret_cast<uint4*>(&sAh[r * LDT + c * 8]) =
                *reinterpret_cast<const uint4*>(&Ah[ga]);
            *reinterpret_cast<uint4*>(&sAl[r * LDT + c * 8]) =
                *reinterpret_cast<const uint4*>(&Al[ga]);
            *reinterpret_cast<uint4*>(&sWh[r * LDT + c * 8]) =
                *reinterpret_cast<const uint4*>(&Wh[gw]);
            *reinterpret_cast<uint4*>(&sWl[r * LDT + c * 8]) =
                *reinterpret_cast<const uint4*>(&Wl[gw]);
        }
        __syncthreads();

        #pragma unroll
        for (int ks = 0; ks < QKC; ks += 16) {
            uint32_t af[4][4], bf[2][4];
            #pragma unroll
            for (int mt = 0; mt < 4; mt++)
                ldsm_x4(af[mt], sAh_u + ((arow + mt * 16) * LDT + ks + acol) * 2);
            #pragma unroll
            for (int p = 0; p < 2; p++)
                ldsm_x4(bf[p], sWh_u + ((brow + p * 16) * LDT + ks + bk) * 2);
            #pragma unroll
            for (int mt = 0; mt < 4; mt++)
                #pragma unroll
                for (int nt = 0; nt < 4; nt++)
                    mma16816(acc[mt][nt], af[mt], &bf[nt >> 1][(nt & 1) * 2], acc[mt][nt]);
            #pragma unroll
            for (int p = 0; p < 2; p++)
                ldsm_x4(bf[p], sWl_u + ((brow + p * 16) * LDT + ks + bk) * 2);
            #pragma unroll
            for (int mt = 0; mt < 4; mt++)
                #pragma unroll
                for (int nt = 0; nt < 4; nt++)
                    mma16816(acc[mt][nt], af[mt], &bf[nt >> 1][(nt & 1) * 2], acc[mt][nt]);
            #pragma unroll
            for (int mt = 0; mt < 4; mt++)
                ldsm_x4(af[mt], sAl_u + ((arow + mt * 16) * LDT + ks + acol) * 2);
            #pragma unroll
            for (int p = 0; p < 2; p++)
                ldsm_x4(bf[p], sWh_u + ((brow + p * 16) * LDT + ks + bk) * 2);
            #pragma unroll
            for (int mt = 0; mt < 4; mt++)
                #pragma unroll
                for (int nt = 0; nt < 4; nt++)
                    mma16816(acc[mt][nt], af[mt], &bf[nt >> 1][(nt & 1) * 2], acc[mt][nt]);
        }
    }

    #pragma unroll
    for (int mt = 0; mt < 4; mt++) {
        #pragma unroll
        for (int nt = 0; nt < 4; nt++) {
            int row = m0 + warp_m * 64 + mt * 16 + (l >> 2);
            int col = n0 + warp_n * 32 + nt * 8 + (l & 3) * 2;
            size_t i0 = (size_t)row * CC + col;
            size_t i1 = (size_t)(row + 8) * CC + col;
            float2 v0 = make_float2(acc[mt][nt][0], acc[mt][nt][1]);
            float2 v1 = make_float2(acc[mt][nt][2], acc[mt][nt][3]);
            if (addend) {
                float2 a0 = *reinterpret_cast<const float2*>(addend + i0);
                float2 a1 = *reinterpret_cast<const float2*>(addend + i1);
                v0.x += a0.x; v0.y += a0.y;
                v1.x += a1.x; v1.y += a1.y;
            }
            *reinterpret_cast<float2*>(Cmat + i0) = v0;
            *reinterpret_cast<float2*>(Cmat + i1) = v1;
        }
    }
}

// ---------------- kernel 4: per-head rmsnorm + RoPE, split bf16 out ---------
// q pre-scaled by 1/sqrt(DH)
__global__ __launch_bounds__(256) void qknorm_rope_split_kernel(
    const float* __restrict__ q, const float* __restrict__ k,
    __nv_bfloat16* __restrict__ qh, __nv_bfloat16* __restrict__ ql,
    __nv_bfloat16* __restrict__ kh, __nv_bfloat16* __restrict__ kl) {
    int gwarp = (blockIdx.x * 256 + threadIdx.x) >> 5;
    int lane  = threadIdx.x & 31;
    int m = gwarp >> 4;
    int h = gwarp & 15;
    int t = m & (TT - 1);
    size_t base = (size_t)m * CC + h * DH;
    const float qscale = 0.08838834764831845f;  // 1/sqrt(128)

    float c0 = g_cos[t * 64 + lane],      s0 = g_sin[t * 64 + lane];
    float c1 = g_cos[t * 64 + 32 + lane], s1 = g_sin[t * 64 + 32 + lane];

    #pragma unroll
    for (int w = 0; w < 2; w++) {
        const float* p = (w ? k : q) + base;
        __nv_bfloat16* oh = (w ? kh : qh) + base;
        __nv_bfloat16* ol = (w ? kl : ql) + base;
        float sc2 = w ? 1.0f : qscale;
        float v0 = p[lane], v1 = p[lane + 32], v2 = p[lane + 64], v3 = p[lane + 96];
        float ss = v0*v0 + v1*v1 + v2*v2 + v3*v3;
        #pragma unroll
        for (int o = 16; o > 0; o >>= 1) ss += __shfl_xor_sync(0xffffffffu, ss, o);
        float sc = rsqrtf(ss * (1.0f / 128.0f) + RMS_EPS) * sc2;
        v0 *= sc; v1 *= sc; v2 *= sc; v3 *= sc;
        // wait: rmsnorm scale must NOT include qscale inside rsqrt usage order —
        // multiplication commutes, so folding qscale here is exact.
        store1_hilo(oh + lane,      ol + lane,      v0 * c0 + v2 * s0);
        store1_hilo(oh + lane + 64, ol + lane + 64, v2 * c0 - v0 * s0);
        store1_hilo(oh + lane + 32, ol + lane + 32, v1 * c1 + v3 * s1);
        store1_hilo(oh + lane + 96, ol + lane + 96, v3 * c1 - v1 * s1);
    }
}

// ---------------- kernel 5: HMMA causal flash attention ---------------------
// BM=128 q rows, BN=64 kv. 8 warps, warp owns 16 q rows. Split bf16 QK & PV.
#define AP 136   // smem pitch in halves (272B) -> conflict-free ldmatrix
#define ATTM_SMEM (512 * AP * 2)   // 139264 bytes

__global__ __launch_bounds__(256, 1) void attn_mma_kernel(
    const __nv_bfloat16* __restrict__ Qh, const __nv_bfloat16* __restrict__ Ql,
    const __nv_bfloat16* __restrict__ Kh, const __nv_bfloat16* __restrict__ Kl,
    const __nv_bfloat16* __restrict__ Vh, const __nv_bfloat16* __restrict__ Vl,
    __nv_bfloat16* __restrict__ Oh, __nv_bfloat16* __restrict__ Ol) {
    extern __shared__ __nv_bfloat16 smA[];
    __nv_bfloat16* sQh = smA;
    __nv_bfloat16* sQl = smA + 128 * AP;
    __nv_bfloat16* sKh = smA + 256 * AP;
    __nv_bfloat16* sKl = smA + 320 * AP;
    __nv_bfloat16* sVh = smA + 384 * AP;
    __nv_bfloat16* sVl = smA + 448 * AP;

    int tid = threadIdx.x;
    int l = tid & 31, wid = tid >> 5;
    int qt = (int)(gridDim.x - 1 - blockIdx.x);   // heavy tiles first
    int m0 = qt * 128;
    int bh = blockIdx.y;
    int b = bh >> 4, h = bh & 15;
    size_t base = (size_t)b * TT * CC + (size_t)h * DH;

    // load Q (hi + lo): 128 rows x 128 halves
    for (int idx = tid; idx < 128 * 16; idx += 256) {
        int r = idx >> 4, c = idx & 15;
        size_t g = base + (size_t)(m0 + r) * CC + c * 8;
        *reinterpret_cast<uint4*>(&sQh[r * AP + c * 8]) =
            *reinterpret_cast<const uint4*>(&Qh[g]);
        *reinterpret_cast<uint4*>(&sQl[r * AP + c * 8]) =
            *reinterpret_cast<const uint4*>(&Ql[g]);
    }

    float o[16][4];
    #pragma unroll
    for (int i = 0; i < 16; i++)
        #pragma unroll
        for (int j = 0; j < 4; j++) o[i][j] = 0.f;
    float mrow[2] = {-1e30f, -1e30f};
    float lrow[2] = {0.f, 0.f};

    uint32_t sQh_u = smem_u32(sQh), sQl_u = smem_u32(sQl);
    uint32_t sKh_u = smem_u32(sKh), sKl_u = smem_u32(sKl);
    uint32_t sVh_u = smem_u32(sVh), sVl_u = smem_u32(sVl);

    int aoff = ((wid * 16 + (l & 15)) * AP + ((l >> 4) << 3)) * 2;  // + ks*32 bytes
    int brow = (l & 7) + ((l >> 4) << 3);
    int bk   = ((l >> 3) & 1) << 3;
    int vrow = l & 15;
    int vcol = (l >> 4) << 3;

    int nkv = 2 * qt + 2;
    for (int kt = 0; kt < nkv; ++kt) {
        int n0 = kt * 64;
        __syncthreads();
        for (int idx = tid; idx < 64 * 16; idx += 256) {
            int r = idx >> 4, c = idx & 15;
            size_t g = base + (size_t)(n0 + r) * CC + c * 8;
            *reinterpret_cast<uint4*>(&sKh[r * AP + c * 8]) =
                *reinterpret_cast<const uint4*>(&Kh[g]);
            *reinterpret_cast<uint4*>(&sKl[r * AP + c * 8]) =
                *reinterpret_cast<const uint4*>(&Kl[g]);
            *reinterpret_cast<uint4*>(&sVh[r * AP + c * 8]) =
                *reinterpret_cast<const uint4*>(&Vh[g]);
            *reinterpret_cast<uint4*>(&sVl[r * AP + c * 8]) =
                *reinterpret_cast<const uint4*>(&Vl[g]);
        }
        __syncthreads();

        float s[8][4];
        #pragma unroll
        for (int i = 0; i < 8; i++)
            #pragma unroll
            for (int j = 0; j < 4; j++) s[i][j] = 0.f;

        #pragma unroll
        for (int ks = 0; ks < 8; ++ks) {
            uint32_t aH[4], aL[4], bb[4][4];
            ldsm_x4(aH, sQh_u + aoff + ks * 32);
            ldsm_x4(aL, sQl_u + aoff + ks * 32);
            #pragma unroll
            for (int p = 0; p < 4; p++)
                ldsm_x4(bb[p], sKh_u + ((p * 16 + brow) * AP + ks * 16 + bk) * 2);
            #pragma unroll
            for (int nt = 0; nt < 8; nt++)
                mma16816(s[nt], aH, &bb[nt >> 1][(nt & 1) * 2], s[nt]);
            #pragma unroll
            for (int nt = 0; nt < 8; nt++)
                mma16816(s[nt], aL, &bb[nt >> 1][(nt & 1) * 2], s[nt]);
            #pragma unroll
            for (int p = 0; p < 4; p++)
                ldsm_x4(bb[p], sKl_u + ((p * 16 + brow) * AP + ks * 16 + bk) * 2);
            #pragma unroll
            for (int nt = 0; nt < 8; nt++)
                mma16816(s[nt], aH, &bb[nt >> 1][(nt & 1) * 2], s[nt]);
        }

        // ---- softmax update (rows gr0, gr1 per thread) ----
        int gr0 = m0 + wid * 16 + (l >> 2);
        int gr1 = gr0 + 8;
        if (kt >= 2 * qt) {
            #pragma unroll
            for (int nt = 0; nt < 8; nt++) {
                int c0 = n0 + nt * 8 + (l & 3) * 2;
                if (c0     > gr0) s[nt][0] = -1e30f;
                if (c0 + 1 > gr0) s[nt][1] = -1e30f;
                if (c0     > gr1) s[nt][2] = -1e30f;
                if (c0 + 1 > gr1) s[nt][3] = -1e30f;
            }
        }
        float tm0 = -1e30f, tm1 = -1e30f;
        #pragma unroll
        for (int nt = 0; nt < 8; nt++) {
            tm0 = fmaxf(tm0, fmaxf(s[nt][0], s[nt][1]));
            tm1 = fmaxf(tm1, fmaxf(s[nt][2], s[nt][3]));
        }
        tm0 = fmaxf(tm0, __shfl_xor_sync(0xffffffffu, tm0, 1));
        tm0 = fmaxf(tm0, __shfl_xor_sync(0xffffffffu, tm0, 2));
        tm1 = fmaxf(tm1, __shfl_xor_sync(0xffffffffu, tm1, 1));
        tm1 = fmaxf(tm1, __shfl_xor_sync(0xffffffffu, tm1, 2));
        float mn0 = fmaxf(mrow[0], tm0), mn1 = fmaxf(mrow[1], tm1);
        float al0 = fexp(mrow[0] - mn0), al1 = fexp(mrow[1] - mn1);
        float ts0 = 0.f, ts1 = 0.f;
        #pragma unroll
        for (int nt = 0; nt < 8; nt++) {
            s[nt][0] = fexp(s[nt][0] - mn0); ts0 += s[nt][0];
            s[nt][1] = fexp(s[nt][1] - mn0); ts0 += s[nt][1];
            s[nt][2] = fexp(s[nt][2] - mn1); ts1 += s[nt][2];
            s[nt][3] = fexp(s[nt][3] - mn1); ts1 += s[nt][3];
        }
        ts0 += __shfl_xor_sync(0xffffffffu, ts0, 1);
        ts0 += __shfl_xor_sync(0xffffffffu, ts0, 2);
        ts1 += __shfl_xor_sync(0xffffffffu, ts1, 1);
        ts1 += __shfl_xor_sync(0xffffffffu, ts1, 2);
        lrow[0] = lrow[0] * al0 + ts0; mrow[0] = mn0;
        lrow[1] = lrow[1] * al1 + ts1; mrow[1] = mn1;
        #pragma unroll
        for (int ot = 0; ot < 16; ot++) {
            o[ot][0] *= al0; o[ot][1] *= al0;
            o[ot][2] *= al1; o[ot][3] *= al1;
        }

        // ---- pack P fragments (hi/lo) directly from accumulators ----
        uint32_t pH[4][4], pL[4][4];
        #pragma unroll
        for (int k2 = 0; k2 < 4; k2++) {
            #pragma unroll
            for (int hx = 0; hx < 2; hx++) {
                int nt = 2 * k2 + hx;
                pH[k2][hx * 2 + 0] = packbf(s[nt][0], s[nt][1]);
                pH[k2][hx * 2 + 1] = packbf(s[nt][2], s[nt][3]);
                pL[k2][hx * 2 + 0] = packbf(s[nt][0] - bfhi(s[nt][0]),
                                            s[nt][1] - bfhi(s[nt][1]));
                pL[k2][hx * 2 + 1] = packbf(s[nt][2] - bfhi(s[nt][2]),
                                            s[nt][3] - bfhi(s[nt][3]));
            }
        }

        // ---- O += P V (3 split passes) ----
        #pragma unroll
        for (int k2 = 0; k2 < 4; k2++) {
            uint32_t bV[8][4];
            #pragma unroll
            for (int dv = 0; dv < 8; dv++)
                ldsm_x4_t(bV[dv], sVh_u + ((k2 * 16 + vrow) * AP + dv * 16 + vcol) * 2);
            #pragma unroll
            for (int ot = 0; ot < 16; ot++)
                mma16816(o[ot], pH[k2], &bV[ot >> 1][(ot & 1) * 2], o[ot]);
            #pragma unroll
            for (int ot = 0; ot < 16; ot++)
                mma16816(o[ot], pL[k2], &bV[ot >> 1][(ot & 1) * 2], o[ot]);
            #pragma unroll
            for (int dv = 0; dv < 8; dv++)
                ldsm_x4_t(bV[dv], sVl_u + ((k2 * 16 + vrow) * AP + dv * 16 + vcol) * 2);
            #pragma unroll
            for (int ot = 0; ot < 16; ot++)
                mma16816(o[ot], pH[k2], &bV[ot >> 1][(ot & 1) * 2], o[ot]);
        }
    }

    // ---- epilogue: normalize and write split bf16 ----
    float inv0 = 1.f / lrow[0], inv1 = 1.f / lrow[1];
    int gr0 = m0 + wid * 16 + (l >> 2);
    #pragma unroll
    for (int ot = 0; ot < 16; ot++) {
        size_t i0 = base + (size_t)gr0 * CC + ot * 8 + (l & 3) * 2;
        size_t i1 = i0 + (size_t)8 * CC;
        store2_hilo(Oh + i0, Ol + i0, o[ot][0] * inv0, o[ot][1] * inv0);
        store2_hilo(Oh + i1, Ol + i1, o[ot][2] * inv1, o[ot][3] * inv1);
    }
}

// ---------------- launch -----------------------------------------------------
extern "C" void kernel_launch(void* const* d_in, const int* in_sizes, int n_in,
                              void* d_out, int out_size) {
    const float* residual = (const float*)d_in[0];
    const float* w[4] = {(const float*)d_in[1], (const float*)d_in[2],
                         (const float*)d_in[3], (const float*)d_in[4]};
    float* out = (float*)d_out;

    cudaFuncSetAttribute(attn_mma_kernel, cudaFuncAttributeMaxDynamicSharedMemorySize,
                         ATTM_SMEM);

    void *pq, *pk, *pv, *pxh, *pxl, *pyh, *pyl, *pwh, *pwl;
    void *pqh, *pql, *pkh, *pkl, *pvh, *pvl;
    cudaGetSymbolAddress(&pq, g_q);
    cudaGetSymbolAddress(&pk, g_k);
    cudaGetSymbolAddress(&pv, g_v);
    cudaGetSymbolAddress(&pxh, g_xh);
    cudaGetSymbolAddress(&pxl, g_xl);
    cudaGetSymbolAddress(&pyh, g_yh);
    cudaGetSymbolAddress(&pyl, g_yl);
    cudaGetSymbolAddress(&pwh, g_wh);
    cudaGetSymbolAddress(&pwl, g_wl);
    cudaGetSymbolAddress(&pqh, g_qh);
    cudaGetSymbolAddress(&pql, g_ql);
    cudaGetSymbolAddress(&pkh, g_kh);
    cudaGetSymbolAddress(&pkl, g_kl);
    cudaGetSymbolAddress(&pvh, g_vh);
    cudaGetSymbolAddress(&pvl, g_vl);
    float* gq = (float*)pq; float* gk = (float*)pk; float* gv = (float*)pv;
    __nv_bfloat16* xh = (__nv_bfloat16*)pxh; __nv_bfloat16* xl = (__nv_bfloat16*)pxl;
    __nv_bfloat16* yh = (__nv_bfloat16*)pyh; __nv_bfloat16* yl = (__nv_bfloat16*)pyl;
    __nv_bfloat16* wh = (__nv_bfloat16*)pwh; __nv_bfloat16* wl = (__nv_bfloat16*)pwl;
    __nv_bfloat16* qh = (__nv_bfloat16*)pqh; __nv_bfloat16* ql = (__nv_bfloat16*)pql;
    __nv_bfloat16* kh = (__nv_bfloat16*)pkh; __nv_bfloat16* kl = (__nv_bfloat16*)pkl;
    __nv_bfloat16* vh = (__nv_bfloat16*)pvh; __nv_bfloat16* vl = (__nv_bfloat16*)pvl;

    const size_t WSZ = (size_t)CC * CC;

    // 0. split weights to bf16 hi/lo
    for (int i = 0; i < 4; i++)
        split_kernel<<<(int)(WSZ / 4 / 256), 256>>>(w[i], wh + i * WSZ, wl + i * WSZ,
                                                    (int)(WSZ / 4));
    // 1. rmsnorm input -> split bf16
    rmsnorm_in_kernel<<<BT, 256>>>(residual, xh, xl);
    // 2. rope tables
    rope_table_kernel<<<(TT * 64 + 255) / 256, 256>>>();
    // 3. QKV projections (HMMA, split-bf16)
    dim3 ggrid(CC / QN, BT / QM);
    gemm_mma_kernel<<<ggrid, 256>>>(xh, xl, wh + 0 * WSZ, wl + 0 * WSZ, nullptr, gq);
    gemm_mma_kernel<<<ggrid, 256>>>(xh, xl, wh + 1 * WSZ, wl + 1 * WSZ, nullptr, gk);
    gemm_mma_kernel<<<ggrid, 256>>>(xh, xl, wh + 2 * WSZ, wl + 2 * WSZ, nullptr, gv);
    // 4. per-head rmsnorm + rope -> split bf16 q,k ; split v
    qknorm_rope_split_kernel<<<(BT * HH) / 8, 256>>>(gq, gk, qh, ql, kh, kl);
    split_kernel<<<(int)(ELEMS / 4 / 256), 256>>>(gv, vh, vl, (int)(ELEMS / 4));
    // 5. HMMA causal flash attention -> split bf16 y
    dim3 agrid(TT / 128, BB * HH);
    attn_mma_kernel<<<agrid, 256, ATTM_SMEM>>>(qh, ql, kh, kl, vh, vl, yh, yl);
    // 6. output projection + residual add
    gemm_mma_kernel<<<ggrid, 256>>>(yh, yl, wh + 3 * WSZ, wl + 3 * WSZ, residual, out);
}

// round 9
// speedup vs baseline: 2.9896x; 1.0706x over previous
#include <cuda_runtime.h>
#include <cuda_bf16.h>
#include <math.h>
#include <stdint.h>

// Problem constants
#define BB   4
#define TT   2048
#define CC   2048
#define HH   16
#define DH   128
#define BT   (BB * TT)          // 8192
#define ELEMS ((size_t)BT * CC) // 16777216

#define RMS_EPS 1.1920928955078125e-07f

// ---------------- scratch (device globals; no allocation allowed) ----------
__device__ __align__(16) float g_q[ELEMS];
__device__ __align__(16) float g_k[ELEMS];
__device__ __align__(16) __nv_bfloat16 g_xh[ELEMS];
__device__ __align__(16) __nv_bfloat16 g_xl[ELEMS];
__device__ __align__(16) __nv_bfloat16 g_yh[ELEMS];
__device__ __align__(16) __nv_bfloat16 g_yl[ELEMS];
__device__ __align__(16) __nv_bfloat16 g_qh[ELEMS];
__device__ __align__(16) __nv_bfloat16 g_ql[ELEMS];
__device__ __align__(16) __nv_bfloat16 g_kh[ELEMS];
__device__ __align__(16) __nv_bfloat16 g_kl[ELEMS];
__device__ __align__(16) __nv_bfloat16 g_vh[ELEMS];
__device__ __align__(16) __nv_bfloat16 g_vl[ELEMS];
__device__ __align__(16) __nv_bfloat16 g_wh[4][(size_t)CC * CC];
__device__ __align__(16) __nv_bfloat16 g_wl[4][(size_t)CC * CC];
__device__ __align__(16) float g_cos[TT * 64];
__device__ __align__(16) float g_sin[TT * 64];

// ======================= PTX helpers (portable, no 'a' features) ============
__device__ __forceinline__ uint32_t smem_u32(const void* p) {
    uint32_t a;
    asm("{ .reg .u64 t; cvta.to.shared.u64 t, %1; cvt.u32.u64 %0, t; }"
        : "=r"(a) : "l"(p));
    return a;
}

__device__ __forceinline__ void ldsm_x4(uint32_t* r, uint32_t addr) {
    asm volatile("ldmatrix.sync.aligned.m8n8.x4.shared.b16 {%0,%1,%2,%3}, [%4];"
                 : "=r"(r[0]), "=r"(r[1]), "=r"(r[2]), "=r"(r[3]) : "r"(addr));
}
__device__ __forceinline__ void ldsm_x4_t(uint32_t* r, uint32_t addr) {
    asm volatile("ldmatrix.sync.aligned.m8n8.x4.trans.shared.b16 {%0,%1,%2,%3}, [%4];"
                 : "=r"(r[0]), "=r"(r[1]), "=r"(r[2]), "=r"(r[3]) : "r"(addr));
}

__device__ __forceinline__ void mma16816(float* d, const uint32_t* a,
                                         const uint32_t* b, const float* c) {
    asm volatile(
        "mma.sync.aligned.m16n8k16.row.col.f32.bf16.bf16.f32 "
        "{%0,%1,%2,%3}, {%4,%5,%6,%7}, {%8,%9}, {%10,%11,%12,%13};\n"
        : "=f"(d[0]), "=f"(d[1]), "=f"(d[2]), "=f"(d[3])
        : "r"(a[0]), "r"(a[1]), "r"(a[2]), "r"(a[3]),
          "r"(b[0]), "r"(b[1]),
          "f"(c[0]), "f"(c[1]), "f"(c[2]), "f"(c[3]));
}

#define CP_ASYNC16(sdst, gsrc) \
    asm volatile("cp.async.cg.shared.global [%0], [%1], 16;" \
                 :: "r"(sdst), "l"(gsrc) : "memory")
#define CP_COMMIT() asm volatile("cp.async.commit_group;" ::: "memory")
#define CP_WAIT1()  asm volatile("cp.async.wait_group 1;" ::: "memory")
#define CP_WAIT0()  asm volatile("cp.async.wait_group 0;" ::: "memory")

// pack two fp32 into bf16x2 (lo -> low half)
__device__ __forceinline__ uint32_t packbf(float lo, float hi) {
    uint32_t d;
    asm("cvt.rn.bf16x2.f32 %0, %1, %2;" : "=r"(d) : "f"(hi), "f"(lo));
    return d;
}
__device__ __forceinline__ float bfhi(float x) {
    return __bfloat162float(__float2bfloat16_rn(x));
}

// fast e^x for x <= 0 (no MUFU): 2^y with rint + deg-5 poly, rel err ~2.4e-6
__device__ __forceinline__ float fexp(float x) {
    float y = x * 1.4426950408889634f;
    y = fmaxf(y, -126.0f);
    float nf = rintf(y);
    float f = y - nf;
    float p = 1.3333558146e-3f;
    p = fmaf(p, f, 9.6181291076e-3f);
    p = fmaf(p, f, 5.5504108664e-2f);
    p = fmaf(p, f, 2.4022650696e-1f);
    p = fmaf(p, f, 6.9314718056e-1f);
    p = fmaf(p, f, 1.0f);
    return __int_as_float(__float_as_int(p) + (((int)nf) << 23));
}

// ------------- bf16 hi/lo split store helpers ------------------------------
__device__ __forceinline__ void store4_hilo(__nv_bfloat16* ph, __nv_bfloat16* pl,
                                            float a, float b, float c, float d) {
    __nv_bfloat16 ha = __float2bfloat16_rn(a), hb = __float2bfloat16_rn(b);
    __nv_bfloat16 hc = __float2bfloat16_rn(c), hd = __float2bfloat16_rn(d);
    __nv_bfloat16 la = __float2bfloat16_rn(a - __bfloat162float(ha));
    __nv_bfloat16 lb = __float2bfloat16_rn(b - __bfloat162float(hb));
    __nv_bfloat16 lc = __float2bfloat16_rn(c - __bfloat162float(hc));
    __nv_bfloat16 ld = __float2bfloat16_rn(d - __bfloat162float(hd));
    __nv_bfloat162 h0 = __halves2bfloat162(ha, hb), h1 = __halves2bfloat162(hc, hd);
    __nv_bfloat162 l0 = __halves2bfloat162(la, lb), l1 = __halves2bfloat162(lc, ld);
    uint2 uh, ul;
    uh.x = *reinterpret_cast<unsigned int*>(&h0); uh.y = *reinterpret_cast<unsigned int*>(&h1);
    ul.x = *reinterpret_cast<unsigned int*>(&l0); ul.y = *reinterpret_cast<unsigned int*>(&l1);
    *reinterpret_cast<uint2*>(ph) = uh;
    *reinterpret_cast<uint2*>(pl) = ul;
}

__device__ __forceinline__ void store1_hilo(__nv_bfloat16* ph, __nv_bfloat16* pl, float v) {
    __nv_bfloat16 h = __float2bfloat16_rn(v);
    *ph = h;
    *pl = __float2bfloat16_rn(v - __bfloat162float(h));
}

__device__ __forceinline__ void store2_hilo(__nv_bfloat16* ph, __nv_bfloat16* pl,
                                            float a, float b) {
    uint32_t hv = packbf(a, b);
    float ra = a - bfhi(a), rb = b - bfhi(b);
    uint32_t lv = packbf(ra, rb);
    *reinterpret_cast<uint32_t*>(ph) = hv;
    *reinterpret_cast<uint32_t*>(pl) = lv;
}

// ---------------- kernel: split fp32 -> bf16 hi/lo --------------------------
__global__ __launch_bounds__(256) void split_kernel(const float* __restrict__ in,
                                                    __nv_bfloat16* __restrict__ hi,
                                                    __nv_bfloat16* __restrict__ lo,
                                                    int n4) {
    int i = blockIdx.x * 256 + threadIdx.x;
    if (i >= n4) return;
    float4 v = reinterpret_cast<const float4*>(in)[i];
    store4_hilo(hi + 4 * (size_t)i, lo + 4 * (size_t)i, v.x, v.y, v.z, v.w);
}

// ---------------- kernel 1: rmsnorm over C, output split bf16 ---------------
__global__ __launch_bounds__(256) void rmsnorm_in_kernel(const float* __restrict__ in,
                                                         __nv_bfloat16* __restrict__ xh,
                                                         __nv_bfloat16* __restrict__ xl) {
    int row = blockIdx.x;
    const float4* ip = reinterpret_cast<const float4*>(in) + (size_t)row * 512;
    int t = threadIdx.x;
    float4 a = ip[t];
    float4 b = ip[t + 256];
    float ss = a.x*a.x + a.y*a.y + a.z*a.z + a.w*a.w
             + b.x*b.x + b.y*b.y + b.z*b.z + b.w*b.w;
    __shared__ float red[8];
    #pragma unroll
    for (int o = 16; o > 0; o >>= 1) ss += __shfl_xor_sync(0xffffffffu, ss, o);
    if ((t & 31) == 0) red[t >> 5] = ss;
    __syncthreads();
    if (t < 8) {
        float v = red[t];
        #pragma unroll
        for (int o = 4; o > 0; o >>= 1) v += __shfl_xor_sync(0xffu, v, o);
        if (t == 0) red[0] = v;
    }
    __syncthreads();
    float sc = rsqrtf(red[0] * (1.0f / 2048.0f) + RMS_EPS);
    size_t base = (size_t)row * CC;
    store4_hilo(xh + base + 4 * t,         xl + base + 4 * t,
                a.x * sc, a.y * sc, a.z * sc, a.w * sc);
    store4_hilo(xh + base + 4 * (t + 256), xl + base + 4 * (t + 256),
                b.x * sc, b.y * sc, b.z * sc, b.w * sc);
}

// ---------------- kernel 2: RoPE cos/sin tables -----------------------------
__global__ void rope_table_kernel() {
    int idx = blockIdx.x * blockDim.x + threadIdx.x;
    if (idx >= TT * 64) return;
    int t = idx >> 6;
    int p = idx & 63;
    double inv = pow(10000.0, -((double)p) / 64.0);
    float ang = (float)t * (float)inv;
    g_cos[idx] = cosf(ang);
    g_sin[idx] = sinf(ang);
}

// ---------------- kernel 3: pipelined HMMA split-bf16 GEMM ------------------
// C[m,n] = sum_k A[m,k]*W[n,k]; A,W as bf16 hi/lo splits.
// Block tile 128x128, Kc = 32, cp.async double buffer.
// MODE 0: fused QKV over N=6144; q,k -> fp32, v -> split bf16.
// MODE 1: proj: out = acc + addend (fp32).
#define QM 128
#define QN 128
#define QKC 32
#define LDT 40                      // smem row pitch halves (80B)
#define ARR_B (QM * LDT * 2)        // 10240 bytes per array
#define BUF_B (4 * ARR_B)           // 40960 bytes per buffer
#define GEMM_SMEM (2 * BUF_B)       // 81920 bytes

__device__ __forceinline__ void gemm_chunk_load(
    uint32_t sbuf, const __nv_bfloat16* __restrict__ Ah,
    const __nv_bfloat16* __restrict__ Al,
    const __nv_bfloat16* __restrict__ Wh, const __nv_bfloat16* __restrict__ Wl,
    int m0, int wrow0, int k0, int tid) {
    #pragma unroll
    for (int it = 0; it < 2; it++) {
        int idx = tid + it * 256;
        int r = idx >> 2, c = idx & 3;
        uint32_t so = (uint32_t)(r * LDT + c * 8) * 2;
        size_t ga = (size_t)(m0 + r) * CC + k0 + c * 8;
        size_t gw = (size_t)(wrow0 + r) * CC + k0 + c * 8;
        CP_ASYNC16(sbuf + 0 * ARR_B + so, Ah + ga);
        CP_ASYNC16(sbuf + 1 * ARR_B + so, Al + ga);
        CP_ASYNC16(sbuf + 2 * ARR_B + so, Wh + gw);
        CP_ASYNC16(sbuf + 3 * ARR_B + so, Wl + gw);
    }
}

__device__ __forceinline__ void gemm_chunk_compute(
    uint32_t sbuf, int arow, int acol, int brow, int bk, float acc[4][4][4]) {
    uint32_t sAh = sbuf, sAl = sbuf + ARR_B;
    uint32_t sWh = sbuf + 2 * ARR_B, sWl = sbuf + 3 * ARR_B;
    #pragma unroll
    for (int ks = 0; ks < QKC; ks += 16) {
        uint32_t af[4][4], bh[2][4], bl[2][4];
        #pragma unroll
        for (int mt = 0; mt < 4; mt++)
            ldsm_x4(af[mt], sAh + ((arow + mt * 16) * LDT + ks + acol) * 2);
        #pragma unroll
        for (int p = 0; p < 2; p++)
            ldsm_x4(bh[p], sWh + ((brow + p * 16) * LDT + ks + bk) * 2);
        #pragma unroll
        for (int mt = 0; mt < 4; mt++)
            #pragma unroll
            for (int nt = 0; nt < 4; nt++)
                mma16816(acc[mt][nt], af[mt], &bh[nt >> 1][(nt & 1) * 2], acc[mt][nt]);
        #pragma unroll
        for (int p = 0; p < 2; p++)
            ldsm_x4(bl[p], sWl + ((brow + p * 16) * LDT + ks + bk) * 2);
        #pragma unroll
        for (int mt = 0; mt < 4; mt++)
            #pragma unroll
            for (int nt = 0; nt < 4; nt++)
                mma16816(acc[mt][nt], af[mt], &bl[nt >> 1][(nt & 1) * 2], acc[mt][nt]);
        #pragma unroll
        for (int mt = 0; mt < 4; mt++)
            ldsm_x4(af[mt], sAl + ((arow + mt * 16) * LDT + ks + acol) * 2);
        #pragma unroll
        for (int mt = 0; mt < 4; mt++)
            #pragma unroll
            for (int nt = 0; nt < 4; nt++)
                mma16816(acc[mt][nt], af[mt], &bh[nt >> 1][(nt & 1) * 2], acc[mt][nt]);
    }
}

template <int MODE>
__global__ __launch_bounds__(256, 2) void gemm_pipe_kernel(
    const __nv_bfloat16* __restrict__ Ah, const __nv_bfloat16* __restrict__ Al,
    const __nv_bfloat16* __restrict__ Whb, const __nv_bfloat16* __restrict__ Wlb,
    const float* __restrict__ addend,
    float* __restrict__ outq, float* __restrict__ outk,
    __nv_bfloat16* __restrict__ vh, __nv_bfloat16* __restrict__ vl) {
    extern __shared__ __align__(16) char sdyn[];
    uint32_t sbase = smem_u32(sdyn);

    int tid = threadIdx.x;
    int l = tid & 31, wid = tid >> 5;
    int warp_m = wid >> 2;
    int warp_n = wid & 3;
    int m0 = blockIdx.y * QM;
    int n0 = blockIdx.x * QN;

    // which output / weight row origin
    int which = (MODE == 0) ? (n0 >> 11) : 3;
    const __nv_bfloat16* Wh = Whb + (size_t)which * CC * CC;
    const __nv_bfloat16* Wl = Wlb + (size_t)which * CC * CC;
    int wrow0 = (MODE == 0) ? (n0 & 2047) : n0;

    float acc[4][4][4];
    #pragma unroll
    for (int i = 0; i < 4; i++)
        #pragma unroll
        for (int j = 0; j < 4; j++)
            #pragma unroll
            for (int q = 0; q < 4; q++) acc[i][j][q] = 0.f;

    int arow = warp_m * 64 + (l & 15);
    int acol = (l >> 4) << 3;
    int brow = warp_n * 32 + (l & 7) + ((l >> 4) << 3);
    int bk   = ((l >> 3) & 1) << 3;

    const int NC = CC / QKC;  // 64
    gemm_chunk_load(sbase, Ah, Al, Wh, Wl, m0, wrow0, 0, tid);
    CP_COMMIT();

    for (int c = 0; c < NC; ++c) {
        uint32_t sbuf = sbase + (c & 1) * BUF_B;
        if (c + 1 < NC) {
            gemm_chunk_load(sbase + ((c + 1) & 1) * BUF_B, Ah, Al, Wh, Wl,
                            m0, wrow0, (c + 1) * QKC, tid);
            CP_COMMIT();
            CP_WAIT1();
        } else {
            CP_WAIT0();
        }
        __syncthreads();
        gemm_chunk_compute(sbuf, arow, acol, brow, bk, acc);
        __syncthreads();
    }

    // epilogue
    #pragma unroll
    for (int mt = 0; mt < 4; mt++) {
        #pragma unroll
        for (int nt = 0; nt < 4; nt++) {
            int row = m0 + warp_m * 64 + mt * 16 + (l >> 2);
            int col = wrow0 + warp_n * 32 + nt * 8 + (l & 3) * 2;
            size_t i0 = (size_t)row * CC + col;
            size_t i1 = (size_t)(row + 8) * CC + col;
            float2 v0 = make_float2(acc[mt][nt][0], acc[mt][nt][1]);
            float2 v1 = make_float2(acc[mt][nt][2], acc[mt][nt][3]);
            if (MODE == 1) {
                float2 a0 = *reinterpret_cast<const float2*>(addend + i0);
                float2 a1 = *reinterpret_cast<const float2*>(addend + i1);
                v0.x += a0.x; v0.y += a0.y;
                v1.x += a1.x; v1.y += a1.y;
                *reinterpret_cast<float2*>(outq + i0) = v0;
                *reinterpret_cast<float2*>(outq + i1) = v1;
            } else if (which == 0) {
                *reinterpret_cast<float2*>(outq + i0) = v0;
                *reinterpret_cast<float2*>(outq + i1) = v1;
            } else if (which == 1) {
                *reinterpret_cast<float2*>(outk + i0) = v0;
                *reinterpret_cast<float2*>(outk + i1) = v1;
            } else {
                store2_hilo(vh + i0, vl + i0, v0.x, v0.y);
                store2_hilo(vh + i1, vl + i1, v1.x, v1.y);
            }
        }
    }
}

// ---------------- kernel 4: per-head rmsnorm + RoPE, split bf16 out ---------
__global__ __launch_bounds__(256) void qknorm_rope_split_kernel(
    const float* __restrict__ q, const float* __restrict__ k,
    __nv_bfloat16* __restrict__ qh, __nv_bfloat16* __restrict__ ql,
    __nv_bfloat16* __restrict__ kh, __nv_bfloat16* __restrict__ kl) {
    int gwarp = (blockIdx.x * 256 + threadIdx.x) >> 5;
    int lane  = threadIdx.x & 31;
    int m = gwarp >> 4;
    int h = gwarp & 15;
    int t = m & (TT - 1);
    size_t base = (size_t)m * CC + h * DH;
    const float qscale = 0.08838834764831845f;  // 1/sqrt(128)

    float c0 = g_cos[t * 64 + lane],      s0 = g_sin[t * 64 + lane];
    float c1 = g_cos[t * 64 + 32 + lane], s1 = g_sin[t * 64 + 32 + lane];

    #pragma unroll
    for (int w = 0; w < 2; w++) {
        const float* p = (w ? k : q) + base;
        __nv_bfloat16* oh = (w ? kh : qh) + base;
        __nv_bfloat16* ol = (w ? kl : ql) + base;
        float sc2 = w ? 1.0f : qscale;
        float v0 = p[lane], v1 = p[lane + 32], v2 = p[lane + 64], v3 = p[lane + 96];
        float ss = v0*v0 + v1*v1 + v2*v2 + v3*v3;
        #pragma unroll
        for (int o = 16; o > 0; o >>= 1) ss += __shfl_xor_sync(0xffffffffu, ss, o);
        float sc = rsqrtf(ss * (1.0f / 128.0f) + RMS_EPS) * sc2;
        v0 *= sc; v1 *= sc; v2 *= sc; v3 *= sc;
        store1_hilo(oh + lane,      ol + lane,      v0 * c0 + v2 * s0);
        store1_hilo(oh + lane + 64, ol + lane + 64, v2 * c0 - v0 * s0);
        store1_hilo(oh + lane + 32, ol + lane + 32, v1 * c1 + v3 * s1);
        store1_hilo(oh + lane + 96, ol + lane + 96, v3 * c1 - v1 * s1);
    }
}

// ---------------- kernel 5: HMMA causal flash attention ---------------------
#define AP 136   // smem pitch in halves (272B) -> conflict-free ldmatrix
#define ATTM_SMEM (512 * AP * 2)   // 139264 bytes

__global__ __launch_bounds__(256, 1) void attn_mma_kernel(
    const __nv_bfloat16* __restrict__ Qh, const __nv_bfloat16* __restrict__ Ql,
    const __nv_bfloat16* __restrict__ Kh, const __nv_bfloat16* __restrict__ Kl,
    const __nv_bfloat16* __restrict__ Vh, const __nv_bfloat16* __restrict__ Vl,
    __nv_bfloat16* __restrict__ Oh, __nv_bfloat16* __restrict__ Ol) {
    extern __shared__ __nv_bfloat16 smA[];
    __nv_bfloat16* sQh = smA;
    __nv_bfloat16* sQl = smA + 128 * AP;
    __nv_bfloat16* sKh = smA + 256 * AP;
    __nv_bfloat16* sKl = smA + 320 * AP;
    __nv_bfloat16* sVh = smA + 384 * AP;
    __nv_bfloat16* sVl = smA + 448 * AP;

    int tid = threadIdx.x;
    int l = tid & 31, wid = tid >> 5;
    int qt = (int)(gridDim.x - 1 - blockIdx.x);   // heavy tiles first
    int m0 = qt * 128;
    int bh = blockIdx.y;
    int b = bh >> 4, h = bh & 15;
    size_t base = (size_t)b * TT * CC + (size_t)h * DH;

    for (int idx = tid; idx < 128 * 16; idx += 256) {
        int r = idx >> 4, c = idx & 15;
        size_t g = base + (size_t)(m0 + r) * CC + c * 8;
        *reinterpret_cast<uint4*>(&sQh[r * AP + c * 8]) =
            *reinterpret_cast<const uint4*>(&Qh[g]);
        *reinterpret_cast<uint4*>(&sQl[r * AP + c * 8]) =
            *reinterpret_cast<const uint4*>(&Ql[g]);
    }

    float o[16][4];
    #pragma unroll
    for (int i = 0; i < 16; i++)
        #pragma unroll
        for (int j = 0; j < 4; j++) o[i][j] = 0.f;
    float mrow[2] = {-1e30f, -1e30f};
    float lrow[2] = {0.f, 0.f};

    uint32_t sQh_u = smem_u32(sQh), sQl_u = smem_u32(sQl);
    uint32_t sKh_u = smem_u32(sKh), sKl_u = smem_u32(sKl);
    uint32_t sVh_u = smem_u32(sVh), sVl_u = smem_u32(sVl);

    int aoff = ((wid * 16 + (l & 15)) * AP + ((l >> 4) << 3)) * 2;
    int brow = (l & 7) + ((l >> 4) << 3);
    int bk   = ((l >> 3) & 1) << 3;
    int vrow = l & 15;
    int vcol = (l >> 4) << 3;

    int nkv = 2 * qt + 2;
    for (int kt = 0; kt < nkv; ++kt) {
        int n0 = kt * 64;
        __syncthreads();
        for (int idx = tid; idx < 64 * 16; idx += 256) {
            int r = idx >> 4, c = idx & 15;
            size_t g = base + (size_t)(n0 + r) * CC + c * 8;
            *reinterpret_cast<uint4*>(&sKh[r * AP + c * 8]) =
                *reinterpret_cast<const uint4*>(&Kh[g]);
            *reinterpret_cast<uint4*>(&sKl[r * AP + c * 8]) =
                *reinterpret_cast<const uint4*>(&Kl[g]);
            *reinterpret_cast<uint4*>(&sVh[r * AP + c * 8]) =
                *reinterpret_cast<const uint4*>(&Vh[g]);
            *reinterpret_cast<uint4*>(&sVl[r * AP + c * 8]) =
                *reinterpret_cast<const uint4*>(&Vl[g]);
        }
        __syncthreads();

        float s[8][4];
        #pragma unroll
        for (int i = 0; i < 8; i++)
            #pragma unroll
            for (int j = 0; j < 4; j++) s[i][j] = 0.f;

        #pragma unroll
        for (int ks = 0; ks < 8; ++ks) {
            uint32_t aH[4], aL[4], bb[4][4];
            ldsm_x4(aH, sQh_u + aoff + ks * 32);
            ldsm_x4(aL, sQl_u + aoff + ks * 32);
            #pragma unroll
            for (int p = 0; p < 4; p++)
                ldsm_x4(bb[p], sKh_u + ((p * 16 + brow) * AP + ks * 16 + bk) * 2);
            #pragma unroll
            for (int nt = 0; nt < 8; nt++)
                mma16816(s[nt], aH, &bb[nt >> 1][(nt & 1) * 2], s[nt]);
            #pragma unroll
            for (int nt = 0; nt < 8; nt++)
                mma16816(s[nt], aL, &bb[nt >> 1][(nt & 1) * 2], s[nt]);
            #pragma unroll
            for (int p = 0; p < 4; p++)
                ldsm_x4(bb[p], sKl_u + ((p * 16 + brow) * AP + ks * 16 + bk) * 2);
            #pragma unroll
            for (int nt = 0; nt < 8; nt++)
                mma16816(s[nt], aH, &bb[nt >> 1][(nt & 1) * 2], s[nt]);
        }

        int gr0 = m0 + wid * 16 + (l >> 2);
        int gr1 = gr0 + 8;
        if (kt >= 2 * qt) {
            #pragma unroll
            for (int nt = 0; nt < 8; nt++) {
                int c0 = n0 + nt * 8 + (l & 3) * 2;
                if (c0     > gr0) s[nt][0] = -1e30f;
                if (c0 + 1 > gr0) s[nt][1] = -1e30f;
                if (c0     > gr1) s[nt][2] = -1e30f;
                if (c0 + 1 > gr1) s[nt][3] = -1e30f;
            }
        }
        float tm0 = -1e30f, tm1 = -1e30f;
        #pragma unroll
        for (int nt = 0; nt < 8; nt++) {
            tm0 = fmaxf(tm0, fmaxf(s[nt][0], s[nt][1]));
            tm1 = fmaxf(tm1, fmaxf(s[nt][2], s[nt][3]));
        }
        tm0 = fmaxf(tm0, __shfl_xor_sync(0xffffffffu, tm0, 1));
        tm0 = fmaxf(tm0, __shfl_xor_sync(0xffffffffu, tm0, 2));
        tm1 = fmaxf(tm1, __shfl_xor_sync(0xffffffffu, tm1, 1));
        tm1 = fmaxf(tm1, __shfl_xor_sync(0xffffffffu, tm1, 2));
        float mn0 = fmaxf(mrow[0], tm0), mn1 = fmaxf(mrow[1], tm1);
        float al0 = fexp(mrow[0] - mn0), al1 = fexp(mrow[1] - mn1);
        float ts0 = 0.f, ts1 = 0.f;
        #pragma unroll
        for (int nt = 0; nt < 8; nt++) {
            s[nt][0] = fexp(s[nt][0] - mn0); ts0 += s[nt][0];
            s[nt][1] = fexp(s[nt][1] - mn0); ts0 += s[nt][1];
            s[nt][2] = fexp(s[nt][2] - mn1); ts1 += s[nt][2];
            s[nt][3] = fexp(s[nt][3] - mn1); ts1 += s[nt][3];
        }
        ts0 += __shfl_xor_sync(0xffffffffu, ts0, 1);
        ts0 += __shfl_xor_sync(0xffffffffu, ts0, 2);
        ts1 += __shfl_xor_sync(0xffffffffu, ts1, 1);
        ts1 += __shfl_xor_sync(0xffffffffu, ts1, 2);
        lrow[0] = lrow[0] * al0 + ts0; mrow[0] = mn0;
        lrow[1] = lrow[1] * al1 + ts1; mrow[1] = mn1;
        #pragma unroll
        for (int ot = 0; ot < 16; ot++) {
            o[ot][0] *= al0; o[ot][1] *= al0;
            o[ot][2] *= al1; o[ot][3] *= al1;
        }

        uint32_t pH[4][4], pL[4][4];
        #pragma unroll
        for (int k2 = 0; k2 < 4; k2++) {
            #pragma unroll
            for (int hx = 0; hx < 2; hx++) {
                int nt = 2 * k2 + hx;
                pH[k2][hx * 2 + 0] = packbf(s[nt][0], s[nt][1]);
                pH[k2][hx * 2 + 1] = packbf(s[nt][2], s[nt][3]);
                pL[k2][hx * 2 + 0] = packbf(s[nt][0] - bfhi(s[nt][0]),
                                            s[nt][1] - bfhi(s[nt][1]));
                pL[k2][hx * 2 + 1] = packbf(s[nt][2] - bfhi(s[nt][2]),
                                            s[nt][3] - bfhi(s[nt][3]));
            }
        }

        #pragma unroll
        for (int k2 = 0; k2 < 4; k2++) {
            uint32_t bV[8][4];
            #pragma unroll
            for (int dv = 0; dv < 8; dv++)
                ldsm_x4_t(bV[dv], sVh_u + ((k2 * 16 + vrow) * AP + dv * 16 + vcol) * 2);
            #pragma unroll
            for (int ot = 0; ot < 16; ot++)
                mma16816(o[ot], pH[k2], &bV[ot >> 1][(ot & 1) * 2], o[ot]);
            #pragma unroll
            for (int ot = 0; ot < 16; ot++)
                mma16816(o[ot], pL[k2], &bV[ot >> 1][(ot & 1) * 2], o[ot]);
            #pragma unroll
            for (int dv = 0; dv < 8; dv++)
                ldsm_x4_t(bV[dv], sVl_u + ((k2 * 16 + vrow) * AP + dv * 16 + vcol) * 2);
            #pragma unroll
            for (int ot = 0; ot < 16; ot++)
                mma16816(o[ot], pH[k2], &bV[ot >> 1][(ot & 1) * 2], o[ot]);
        }
    }

    float inv0 = 1.f / lrow[0], inv1 = 1.f / lrow[1];
    int gr0 = m0 + wid * 16 + (l >> 2);
    #pragma unroll
    for (int ot = 0; ot < 16; ot++) {
        size_t i0 = base + (size_t)gr0 * CC + ot * 8 + (l & 3) * 2;
        size_t i1 = i0 + (size_t)8 * CC;
        store2_hilo(Oh + i0, Ol + i0, o[ot][0] * inv0, o[ot][1] * inv0);
        store2_hilo(Oh + i1, Ol + i1, o[ot][2] * inv1, o[ot][3] * inv1);
    }
}

// ---------------- launch -----------------------------------------------------
extern "C" void kernel_launch(void* const* d_in, const int* in_sizes, int n_in,
                              void* d_out, int out_size) {
    const float* residual = (const float*)d_in[0];
    const float* w[4] = {(const float*)d_in[1], (const float*)d_in[2],
                         (const float*)d_in[3], (const float*)d_in[4]};
    float* out = (float*)d_out;

    cudaFuncSetAttribute(attn_mma_kernel, cudaFuncAttributeMaxDynamicSharedMemorySize,
                         ATTM_SMEM);
    cudaFuncSetAttribute(gemm_pipe_kernel<0>,
                         cudaFuncAttributeMaxDynamicSharedMemorySize, GEMM_SMEM);
    cudaFuncSetAttribute(gemm_pipe_kernel<1>,
                         cudaFuncAttributeMaxDynamicSharedMemorySize, GEMM_SMEM);

    void *pq, *pk, *pxh, *pxl, *pyh, *pyl, *pwh, *pwl;
    void *pqh, *pql, *pkh, *pkl, *pvh, *pvl;
    cudaGetSymbolAddress(&pq, g_q);
    cudaGetSymbolAddress(&pk, g_k);
    cudaGetSymbolAddress(&pxh, g_xh);
    cudaGetSymbolAddress(&pxl, g_xl);
    cudaGetSymbolAddress(&pyh, g_yh);
    cudaGetSymbolAddress(&pyl, g_yl);
    cudaGetSymbolAddress(&pwh, g_wh);
    cudaGetSymbolAddress(&pwl, g_wl);
    cudaGetSymbolAddress(&pqh, g_qh);
    cudaGetSymbolAddress(&pql, g_ql);
    cudaGetSymbolAddress(&pkh, g_kh);
    cudaGetSymbolAddress(&pkl, g_kl);
    cudaGetSymbolAddress(&pvh, g_vh);
    cudaGetSymbolAddress(&pvl, g_vl);
    float* gq = (float*)pq; float* gk = (float*)pk;
    __nv_bfloat16* xh = (__nv_bfloat16*)pxh; __nv_bfloat16* xl = (__nv_bfloat16*)pxl;
    __nv_bfloat16* yh = (__nv_bfloat16*)pyh; __nv_bfloat16* yl = (__nv_bfloat16*)pyl;
    __nv_bfloat16* wh = (__nv_bfloat16*)pwh; __nv_bfloat16* wl = (__nv_bfloat16*)pwl;
    __nv_bfloat16* qh = (__nv_bfloat16*)pqh; __nv_bfloat16* ql = (__nv_bfloat16*)pql;
    __nv_bfloat16* kh = (__nv_bfloat16*)pkh; __nv_bfloat16* kl = (__nv_bfloat16*)pkl;
    __nv_bfloat16* vh = (__nv_bfloat16*)pvh; __nv_bfloat16* vl = (__nv_bfloat16*)pvl;

    const size_t WSZ = (size_t)CC * CC;

    // 0. split weights to bf16 hi/lo
    for (int i = 0; i < 4; i++)
        split_kernel<<<(int)(WSZ / 4 / 256), 256>>>(w[i], wh + i * WSZ, wl + i * WSZ,
                                                    (int)(WSZ / 4));
    // 1. rmsnorm input -> split bf16
    rmsnorm_in_kernel<<<BT, 256>>>(residual, xh, xl);
    // 2. rope tables
    rope_table_kernel<<<(TT * 64 + 255) / 256, 256>>>();
    // 3. fused QKV projection (pipelined HMMA): q,k fp32; v split bf16
    dim3 qkvgrid(3 * CC / QN, BT / QM);
    gemm_pipe_kernel<0><<<qkvgrid, 256, GEMM_SMEM>>>(
        xh, xl, wh, wl, nullptr, gq, gk, vh, vl);
    // 4. per-head rmsnorm + rope -> split bf16 q,k
    qknorm_rope_split_kernel<<<(BT * HH) / 8, 256>>>(gq, gk, qh, ql, kh, kl);
    // 5. HMMA causal flash attention -> split bf16 y
    dim3 agrid(TT / 128, BB * HH);
    attn_mma_kernel<<<agrid, 256, ATTM_SMEM>>>(qh, ql, kh, kl, vh, vl, yh, yl);
    // 6. output projection + residual add (pipelined HMMA)
    dim3 pgrid(CC / QN, BT / QM);
    gemm_pipe_kernel<1><<<pgrid, 256, GEMM_SMEM>>>(
        yh, yl, wh, wl, residual, out, nullptr, nullptr, nullptr);
}

// round 10
// speedup vs baseline: 4.4306x; 1.4820x over previous
#include <cuda_runtime.h>
#include <cuda_fp16.h>
#include <math.h>
#include <stdint.h>

// Problem constants
#define BB   4
#define TT   2048
#define CC   2048
#define HH   16
#define DH   128
#define BT   (BB * TT)          // 8192
#define ELEMS ((size_t)BT * CC) // 16777216

#define RMS_EPS 1.1920928955078125e-07f
#define WSCALE     32.0f        // weight pre-scale (keeps wl out of fp16 subnormals)
#define WSCALE_INV 0.03125f

// ---------------- scratch (device globals; no allocation allowed) ----------
__device__ __align__(16) float g_q[ELEMS];
__device__ __align__(16) float g_k[ELEMS];
__device__ __align__(16) __half g_xh[ELEMS];
__device__ __align__(16) __half g_yh[ELEMS];
__device__ __align__(16) __half g_qh[ELEMS];
__device__ __align__(16) __half g_kh[ELEMS];
__device__ __align__(16) __half g_kl[ELEMS];
__device__ __align__(16) __half g_vh[ELEMS];
__device__ __align__(16) __half g_vl[ELEMS];
__device__ __align__(16) __half g_wh[4][(size_t)CC * CC];
__device__ __align__(16) __half g_wl[4][(size_t)CC * CC];
__device__ __align__(16) float g_cos[TT * 64];
__device__ __align__(16) float g_sin[TT * 64];

// ======================= PTX helpers (portable, no 'a' features) ============
__device__ __forceinline__ uint32_t smem_u32(const void* p) {
    uint32_t a;
    asm("{ .reg .u64 t; cvta.to.shared.u64 t, %1; cvt.u32.u64 %0, t; }"
        : "=r"(a) : "l"(p));
    return a;
}

__device__ __forceinline__ void ldsm_x4(uint32_t* r, uint32_t addr) {
    asm volatile("ldmatrix.sync.aligned.m8n8.x4.shared.b16 {%0,%1,%2,%3}, [%4];"
                 : "=r"(r[0]), "=r"(r[1]), "=r"(r[2]), "=r"(r[3]) : "r"(addr));
}
__device__ __forceinline__ void ldsm_x4_t(uint32_t* r, uint32_t addr) {
    asm volatile("ldmatrix.sync.aligned.m8n8.x4.trans.shared.b16 {%0,%1,%2,%3}, [%4];"
                 : "=r"(r[0]), "=r"(r[1]), "=r"(r[2]), "=r"(r[3]) : "r"(addr));
}

// fp16 MMA, fp32 accumulate
__device__ __forceinline__ void mma16816(float* d, const uint32_t* a,
                                         const uint32_t* b, const float* c) {
    asm volatile(
        "mma.sync.aligned.m16n8k16.row.col.f32.f16.f16.f32 "
        "{%0,%1,%2,%3}, {%4,%5,%6,%7}, {%8,%9}, {%10,%11,%12,%13};\n"
        : "=f"(d[0]), "=f"(d[1]), "=f"(d[2]), "=f"(d[3])
        : "r"(a[0]), "r"(a[1]), "r"(a[2]), "r"(a[3]),
          "r"(b[0]), "r"(b[1]),
          "f"(c[0]), "f"(c[1]), "f"(c[2]), "f"(c[3]));
}

#define CP_ASYNC16(sdst, gsrc) \
    asm volatile("cp.async.cg.shared.global [%0], [%1], 16;" \
                 :: "r"(sdst), "l"(gsrc) : "memory")
#define CP_COMMIT() asm volatile("cp.async.commit_group;" ::: "memory")
#define CP_WAIT1()  asm volatile("cp.async.wait_group 1;" ::: "memory")
#define CP_WAIT0()  asm volatile("cp.async.wait_group 0;" ::: "memory")

// pack two fp32 into f16x2 (first arg -> low half)
__device__ __forceinline__ uint32_t packh(float lo, float hi) {
    uint32_t d;
    asm("cvt.rn.f16x2.f32 %0, %1, %2;" : "=r"(d) : "f"(hi), "f"(lo));
    return d;
}
__device__ __forceinline__ float hhi(float x) {
    return __half2float(__float2half_rn(x));
}

// fast e^x for x <= 0 (no MUFU): 2^y with rint + deg-5 poly, rel err ~2.4e-6
__device__ __forceinline__ float fexp(float x) {
    float y = x * 1.4426950408889634f;
    y = fmaxf(y, -126.0f);
    float nf = rintf(y);
    float f = y - nf;
    float p = 1.3333558146e-3f;
    p = fmaf(p, f, 9.6181291076e-3f);
    p = fmaf(p, f, 5.5504108664e-2f);
    p = fmaf(p, f, 2.4022650696e-1f);
    p = fmaf(p, f, 6.9314718056e-1f);
    p = fmaf(p, f, 1.0f);
    return __int_as_float(__float_as_int(p) + (((int)nf) << 23));
}

// ------------- fp16 hi/lo split store helpers ------------------------------
__device__ __forceinline__ void store4h_hilo(__half* ph, __half* pl,
                                             float a, float b, float c, float d) {
    uint2 uh, ul;
    uh.x = packh(a, b); uh.y = packh(c, d);
    ul.x = packh(a - hhi(a), b - hhi(b));
    ul.y = packh(c - hhi(c), d - hhi(d));
    *reinterpret_cast<uint2*>(ph) = uh;
    *reinterpret_cast<uint2*>(pl) = ul;
}

__device__ __forceinline__ void store2h_hilo(__half* ph, __half* pl, float a, float b) {
    *reinterpret_cast<uint32_t*>(ph) = packh(a, b);
    *reinterpret_cast<uint32_t*>(pl) = packh(a - hhi(a), b - hhi(b));
}

__device__ __forceinline__ void store1h_hilo(__half* ph, __half* pl, float v) {
    __half h = __float2half_rn(v);
    *ph = h;
    *pl = __float2half_rn(v - __half2float(h));
}

// ---------------- kernel: split weights fp32 -> fp16 hi/lo (x WSCALE) -------
__global__ __launch_bounds__(256) void splitw_kernel(const float* __restrict__ in,
                                                     __half* __restrict__ hi,
                                                     __half* __restrict__ lo,
                                                     int n4) {
    int i = blockIdx.x * 256 + threadIdx.x;
    if (i >= n4) return;
    float4 v = reinterpret_cast<const float4*>(in)[i];
    store4h_hilo(hi + 4 * (size_t)i, lo + 4 * (size_t)i,
                 v.x * WSCALE, v.y * WSCALE, v.z * WSCALE, v.w * WSCALE);
}

// ---------------- kernel 1: rmsnorm over C, output fp16 hi ------------------
__global__ __launch_bounds__(256) void rmsnorm_in_kernel(const float* __restrict__ in,
                                                         __half* __restrict__ xh) {
    int row = blockIdx.x;
    const float4* ip = reinterpret_cast<const float4*>(in) + (size_t)row * 512;
    int t = threadIdx.x;
    float4 a = ip[t];
    float4 b = ip[t + 256];
    float ss = a.x*a.x + a.y*a.y + a.z*a.z + a.w*a.w
             + b.x*b.x + b.y*b.y + b.z*b.z + b.w*b.w;
    __shared__ float red[8];
    #pragma unroll
    for (int o = 16; o > 0; o >>= 1) ss += __shfl_xor_sync(0xffffffffu, ss, o);
    if ((t & 31) == 0) red[t >> 5] = ss;
    __syncthreads();
    if (t < 8) {
        float v = red[t];
        #pragma unroll
        for (int o = 4; o > 0; o >>= 1) v += __shfl_xor_sync(0xffu, v, o);
        if (t == 0) red[0] = v;
    }
    __syncthreads();
    float sc = rsqrtf(red[0] * (1.0f / 2048.0f) + RMS_EPS);
    size_t base = (size_t)row * CC;
    uint2 u0, u1;
    u0.x = packh(a.x * sc, a.y * sc); u0.y = packh(a.z * sc, a.w * sc);
    u1.x = packh(b.x * sc, b.y * sc); u1.y = packh(b.z * sc, b.w * sc);
    *reinterpret_cast<uint2*>(xh + base + 4 * t)         = u0;
    *reinterpret_cast<uint2*>(xh + base + 4 * (t + 256)) = u1;
}

// ---------------- kernel 2: RoPE cos/sin tables -----------------------------
__global__ void rope_table_kernel() {
    int idx = blockIdx.x * blockDim.x + threadIdx.x;
    if (idx >= TT * 64) return;
    int t = idx >> 6;
    int p = idx & 63;
    double inv = pow(10000.0, -((double)p) / 64.0);
    float ang = (float)t * (float)inv;
    g_cos[idx] = cosf(ang);
    g_sin[idx] = sinf(ang);
}

// ---------------- kernel 3: pipelined HMMA fp16 2-pass GEMM -----------------
// C[m,n] = (1/WSCALE) * sum_k Ah[m,k]*(Wh+Wl)[n,k]  (+ addend)
// Block 128x128, Kc=32, cp.async double buffer, 3 smem arrays (Ah, Wh, Wl).
#define QM 128
#define QN 128
#define QKC 32
#define LDT 40                      // smem row pitch halves (80B)
#define ARR_B (QM * LDT * 2)        // 10240 bytes per array
#define BUF_B (3 * ARR_B)           // 30720 bytes per buffer
#define GEMM_SMEM (2 * BUF_B)       // 61440 bytes

__device__ __forceinline__ void gemm_chunk_load(
    uint32_t sbuf, const __half* __restrict__ Ah,
    const __half* __restrict__ Wh, const __half* __restrict__ Wl,
    int m0, int wrow0, int k0, int tid) {
    #pragma unroll
    for (int it = 0; it < 2; it++) {
        int idx = tid + it * 256;
        int r = idx >> 2, c = idx & 3;
        uint32_t so = (uint32_t)(r * LDT + c * 8) * 2;
        size_t ga = (size_t)(m0 + r) * CC + k0 + c * 8;
        size_t gw = (size_t)(wrow0 + r) * CC + k0 + c * 8;
        CP_ASYNC16(sbuf + 0 * ARR_B + so, Ah + ga);
        CP_ASYNC16(sbuf + 1 * ARR_B + so, Wh + gw);
        CP_ASYNC16(sbuf + 2 * ARR_B + so, Wl + gw);
    }
}

__device__ __forceinline__ void gemm_chunk_compute(
    uint32_t sbuf, int arow, int acol, int brow, int bk, float acc[4][4][4]) {
    uint32_t sAh = sbuf;
    uint32_t sWh = sbuf + 1 * ARR_B, sWl = sbuf + 2 * ARR_B;
    #pragma unroll
    for (int ks = 0; ks < QKC; ks += 16) {
        uint32_t af[4][4], bh[2][4], bl[2][4];
        #pragma unroll
        for (int mt = 0; mt < 4; mt++)
            ldsm_x4(af[mt], sAh + ((arow + mt * 16) * LDT + ks + acol) * 2);
        #pragma unroll
        for (int p = 0; p < 2; p++)
            ldsm_x4(bh[p], sWh + ((brow + p * 16) * LDT + ks + bk) * 2);
        #pragma unroll
        for (int mt = 0; mt < 4; mt++)
            #pragma unroll
            for (int nt = 0; nt < 4; nt++)
                mma16816(acc[mt][nt], af[mt], &bh[nt >> 1][(nt & 1) * 2], acc[mt][nt]);
        #pragma unroll
        for (int p = 0; p < 2; p++)
            ldsm_x4(bl[p], sWl + ((brow + p * 16) * LDT + ks + bk) * 2);
        #pragma unroll
        for (int mt = 0; mt < 4; mt++)
            #pragma unroll
            for (int nt = 0; nt < 4; nt++)
                mma16816(acc[mt][nt], af[mt], &bl[nt >> 1][(nt & 1) * 2], acc[mt][nt]);
    }
}

template <int MODE>
__global__ __launch_bounds__(256, 2) void gemm_pipe_kernel(
    const __half* __restrict__ Ah,
    const __half* __restrict__ Whb, const __half* __restrict__ Wlb,
    const float* __restrict__ addend,
    float* __restrict__ outq, float* __restrict__ outk,
    __half* __restrict__ vh, __half* __restrict__ vl) {
    extern __shared__ __align__(16) char sdyn[];
    uint32_t sbase = smem_u32(sdyn);

    int tid = threadIdx.x;
    int l = tid & 31, wid = tid >> 5;
    int warp_m = wid >> 2;
    int warp_n = wid & 3;
    int m0 = blockIdx.y * QM;
    int n0 = blockIdx.x * QN;

    int which = (MODE == 0) ? (n0 >> 11) : 3;
    const __half* Wh = Whb + (size_t)which * CC * CC;
    const __half* Wl = Wlb + (size_t)which * CC * CC;
    int wrow0 = (MODE == 0) ? (n0 & 2047) : n0;

    float acc[4][4][4];
    #pragma unroll
    for (int i = 0; i < 4; i++)
        #pragma unroll
        for (int j = 0; j < 4; j++)
            #pragma unroll
            for (int q = 0; q < 4; q++) acc[i][j][q] = 0.f;

    int arow = warp_m * 64 + (l & 15);
    int acol = (l >> 4) << 3;
    int brow = warp_n * 32 + (l & 7) + ((l >> 4) << 3);
    int bk   = ((l >> 3) & 1) << 3;

    const int NC = CC / QKC;  // 64
    gemm_chunk_load(sbase, Ah, Wh, Wl, m0, wrow0, 0, tid);
    CP_COMMIT();

    for (int c = 0; c < NC; ++c) {
        uint32_t sbuf = sbase + (c & 1) * BUF_B;
        if (c + 1 < NC) {
            gemm_chunk_load(sbase + ((c + 1) & 1) * BUF_B, Ah, Wh, Wl,
                            m0, wrow0, (c + 1) * QKC, tid);
            CP_COMMIT();
            CP_WAIT1();
        } else {
            CP_WAIT0();
        }
        __syncthreads();
        gemm_chunk_compute(sbuf, arow, acol, brow, bk, acc);
        __syncthreads();
    }

    // epilogue (descale by 1/WSCALE)
    #pragma unroll
    for (int mt = 0; mt < 4; mt++) {
        #pragma unroll
        for (int nt = 0; nt < 4; nt++) {
            int row = m0 + warp_m * 64 + mt * 16 + (l >> 2);
            int col = wrow0 + warp_n * 32 + nt * 8 + (l & 3) * 2;
            size_t i0 = (size_t)row * CC + col;
            size_t i1 = (size_t)(row + 8) * CC + col;
            float2 v0 = make_float2(acc[mt][nt][0] * WSCALE_INV,
                                    acc[mt][nt][1] * WSCALE_INV);
            float2 v1 = make_float2(acc[mt][nt][2] * WSCALE_INV,
                                    acc[mt][nt][3] * WSCALE_INV);
            if (MODE == 1) {
                float2 a0 = *reinterpret_cast<const float2*>(addend + i0);
                float2 a1 = *reinterpret_cast<const float2*>(addend + i1);
                v0.x += a0.x; v0.y += a0.y;
                v1.x += a1.x; v1.y += a1.y;
                *reinterpret_cast<float2*>(outq + i0) = v0;
                *reinterpret_cast<float2*>(outq + i1) = v1;
            } else if (which == 0) {
                *reinterpret_cast<float2*>(outq + i0) = v0;
                *reinterpret_cast<float2*>(outq + i1) = v1;
            } else if (which == 1) {
                *reinterpret_cast<float2*>(outk + i0) = v0;
                *reinterpret_cast<float2*>(outk + i1) = v1;
            } else {
                store2h_hilo(vh + i0, vl + i0, v0.x, v0.y);
                store2h_hilo(vh + i1, vl + i1, v1.x, v1.y);
            }
        }
    }
}

// ---------------- kernel 4: per-head rmsnorm + RoPE -------------------------
// q: fp16 hi only (pre-scaled by 1/sqrt(DH)); k: fp16 hi/lo.
__global__ __launch_bounds__(256) void qknorm_rope_split_kernel(
    const float* __restrict__ q, const float* __restrict__ k,
    __half* __restrict__ qh,
    __half* __restrict__ kh, __half* __restrict__ kl) {
    int gwarp = (blockIdx.x * 256 + threadIdx.x) >> 5;
    int lane  = threadIdx.x & 31;
    int m = gwarp >> 4;
    int h = gwarp & 15;
    int t = m & (TT - 1);
    size_t base = (size_t)m * CC + h * DH;
    const float qscale = 0.08838834764831845f;  // 1/sqrt(128)

    float c0 = g_cos[t * 64 + lane],      s0 = g_sin[t * 64 + lane];
    float c1 = g_cos[t * 64 + 32 + lane], s1 = g_sin[t * 64 + 32 + lane];

    // q (hi only)
    {
        const float* p = q + base;
        float v0 = p[lane], v1 = p[lane + 32], v2 = p[lane + 64], v3 = p[lane + 96];
        float ss = v0*v0 + v1*v1 + v2*v2 + v3*v3;
        #pragma unroll
        for (int o = 16; o > 0; o >>= 1) ss += __shfl_xor_sync(0xffffffffu, ss, o);
        float sc = rsqrtf(ss * (1.0f / 128.0f) + RMS_EPS) * qscale;
        v0 *= sc; v1 *= sc; v2 *= sc; v3 *= sc;
        qh[base + lane]      = __float2half_rn(v0 * c0 + v2 * s0);
        qh[base + lane + 64] = __float2half_rn(v2 * c0 - v0 * s0);
        qh[base + lane + 32] = __float2half_rn(v1 * c1 + v3 * s1);
        qh[base + lane + 96] = __float2half_rn(v3 * c1 - v1 * s1);
    }
    // k (hi + lo)
    {
        const float* p = k + base;
        float v0 = p[lane], v1 = p[lane + 32], v2 = p[lane + 64], v3 = p[lane + 96];
        float ss = v0*v0 + v1*v1 + v2*v2 + v3*v3;
        #pragma unroll
        for (int o = 16; o > 0; o >>= 1) ss += __shfl_xor_sync(0xffffffffu, ss, o);
        float sc = rsqrtf(ss * (1.0f / 128.0f) + RMS_EPS);
        v0 *= sc; v1 *= sc; v2 *= sc; v3 *= sc;
        store1h_hilo(kh + base + lane,      kl + base + lane,      v0 * c0 + v2 * s0);
        store1h_hilo(kh + base + lane + 64, kl + base + lane + 64, v2 * c0 - v0 * s0);
        store1h_hilo(kh + base + lane + 32, kl + base + lane + 32, v1 * c1 + v3 * s1);
        store1h_hilo(kh + base + lane + 96, kl + base + lane + 96, v3 * c1 - v1 * s1);
    }
}

// ---------------- kernel 5: HMMA causal flash attention (fp16 2-pass) -------
// BM=128 q rows, BN=64 kv, cp.async double-buffered K/V stages.
#define AP 136   // smem pitch in halves (272B) -> conflict-free ldmatrix
// smem halves: sQ 128*AP, then 2 stages x (Kh,Kl,Vh,Vl each 64*AP)
#define ATT_SMEM ((128 * AP + 2 * 256 * AP) * 2)   // 174080 bytes

__device__ __forceinline__ void attn_load_stage(
    uint32_t st_u, const __half* __restrict__ Kh, const __half* __restrict__ Kl,
    const __half* __restrict__ Vh, const __half* __restrict__ Vl,
    int n0, size_t base, int tid) {
    const uint32_t KL_OFF = 64 * AP * 2;
    const uint32_t VH_OFF = 128 * AP * 2;
    const uint32_t VL_OFF = 192 * AP * 2;
    #pragma unroll
    for (int it = 0; it < 4; it++) {
        int idx = tid + it * 256;
        int r = idx >> 4, c = idx & 15;
        size_t g = base + (size_t)(n0 + r) * CC + c * 8;
        uint32_t so = (uint32_t)(r * AP + c * 8) * 2;
        CP_ASYNC16(st_u + so, Kh + g);
        CP_ASYNC16(st_u + KL_OFF + so, Kl + g);
        CP_ASYNC16(st_u + VH_OFF + so, Vh + g);
        CP_ASYNC16(st_u + VL_OFF + so, Vl + g);
    }
}

__global__ __launch_bounds__(256, 1) void attn_mma_kernel(
    const __half* __restrict__ Qh,
    const __half* __restrict__ Kh, const __half* __restrict__ Kl,
    const __half* __restrict__ Vh, const __half* __restrict__ Vl,
    __half* __restrict__ Oh) {
    extern __shared__ __half smA[];
    __half* sQ = smA;

    int tid = threadIdx.x;
    int l = tid & 31, wid = tid >> 5;
    int qt = (int)(gridDim.x - 1 - blockIdx.x);   // heavy tiles first
    int m0 = qt * 128;
    int bh = blockIdx.y;
    int b = bh >> 4, h = bh & 15;
    size_t base = (size_t)b * TT * CC + (size_t)h * DH;

    uint32_t sQ_u = smem_u32(sQ);
    uint32_t stage_u[2];
    stage_u[0] = sQ_u + 128 * AP * 2;
    stage_u[1] = stage_u[0] + 256 * AP * 2;

    // load Q (hi only): 128 rows x 128 halves
    for (int idx = tid; idx < 128 * 16; idx += 256) {
        int r = idx >> 4, c = idx & 15;
        size_t g = base + (size_t)(m0 + r) * CC + c * 8;
        *reinterpret_cast<uint4*>(&sQ[r * AP + c * 8]) =
            *reinterpret_cast<const uint4*>(&Qh[g]);
    }

    float o[16][4];
    #pragma unroll
    for (int i = 0; i < 16; i++)
        #pragma unroll
        for (int j = 0; j < 4; j++) o[i][j] = 0.f;
    float mrow[2] = {-1e30f, -1e30f};
    float lrow[2] = {0.f, 0.f};

    int aoff = ((wid * 16 + (l & 15)) * AP + ((l >> 4) << 3)) * 2;
    int brow = (l & 7) + ((l >> 4) << 3);
    int bk   = ((l >> 3) & 1) << 3;
    int vrow = l & 15;
    int vcol = (l >> 4) << 3;

    int nkv = 2 * qt + 2;
    attn_load_stage(stage_u[0], Kh, Kl, Vh, Vl, 0, base, tid);
    CP_COMMIT();

    for (int kt = 0; kt < nkv; ++kt) {
        int n0 = kt * 64;
        uint32_t st = stage_u[kt & 1];
        if (kt + 1 < nkv) {
            attn_load_stage(stage_u[(kt + 1) & 1], Kh, Kl, Vh, Vl,
                            (kt + 1) * 64, base, tid);
            CP_COMMIT();
            CP_WAIT1();
        } else {
            CP_WAIT0();
        }
        __syncthreads();

        uint32_t sKh_u = st;
        uint32_t sKl_u = st + 64 * AP * 2;
        uint32_t sVh_u = st + 128 * AP * 2;
        uint32_t sVl_u = st + 192 * AP * 2;

        float s[8][4];
        #pragma unroll
        for (int i = 0; i < 8; i++)
            #pragma unroll
            for (int j = 0; j < 4; j++) s[i][j] = 0.f;

        // S = Qh * (Kh + Kl)  (2-pass)
        #pragma unroll
        for (int ks = 0; ks < 8; ++ks) {
            uint32_t aH[4], bb[4][4];
            ldsm_x4(aH, sQ_u + aoff + ks * 32);
            #pragma unroll
            for (int p = 0; p < 4; p++)
                ldsm_x4(bb[p], sKh_u + ((p * 16 + brow) * AP + ks * 16 + bk) * 2);
            #pragma unroll
            for (int nt = 0; nt < 8; nt++)
                mma16816(s[nt], aH, &bb[nt >> 1][(nt & 1) * 2], s[nt]);
            #pragma unroll
            for (int p = 0; p < 4; p++)
                ldsm_x4(bb[p], sKl_u + ((p * 16 + brow) * AP + ks * 16 + bk) * 2);
            #pragma unroll
            for (int nt = 0; nt < 8; nt++)
                mma16816(s[nt], aH, &bb[nt >> 1][(nt & 1) * 2], s[nt]);
        }

        int gr0 = m0 + wid * 16 + (l >> 2);
        int gr1 = gr0 + 8;
        if (kt >= 2 * qt) {
            #pragma unroll
            for (int nt = 0; nt < 8; nt++) {
                int c0 = n0 + nt * 8 + (l & 3) * 2;
                if (c0     > gr0) s[nt][0] = -1e30f;
                if (c0 + 1 > gr0) s[nt][1] = -1e30f;
                if (c0     > gr1) s[nt][2] = -1e30f;
                if (c0 + 1 > gr1) s[nt][3] = -1e30f;
            }
        }
        float tm0 = -1e30f, tm1 = -1e30f;
        #pragma unroll
        for (int nt = 0; nt < 8; nt++) {
            tm0 = fmaxf(tm0, fmaxf(s[nt][0], s[nt][1]));
            tm1 = fmaxf(tm1, fmaxf(s[nt][2], s[nt][3]));
        }
        tm0 = fmaxf(tm0, __shfl_xor_sync(0xffffffffu, tm0, 1));
        tm0 = fmaxf(tm0, __shfl_xor_sync(0xffffffffu, tm0, 2));
        tm1 = fmaxf(tm1, __shfl_xor_sync(0xffffffffu, tm1, 1));
        tm1 = fmaxf(tm1, __shfl_xor_sync(0xffffffffu, tm1, 2));
        float mn0 = fmaxf(mrow[0], tm0), mn1 = fmaxf(mrow[1], tm1);
        float al0 = fexp(mrow[0] - mn0), al1 = fexp(mrow[1] - mn1);
        float ts0 = 0.f, ts1 = 0.f;
        #pragma unroll
        for (int nt = 0; nt < 8; nt++) {
            s[nt][0] = fexp(s[nt][0] - mn0); ts0 += s[nt][0];
            s[nt][1] = fexp(s[nt][1] - mn0); ts0 += s[nt][1];
            s[nt][2] = fexp(s[nt][2] - mn1); ts1 += s[nt][2];
            s[nt][3] = fexp(s[nt][3] - mn1); ts1 += s[nt][3];
        }
        ts0 += __shfl_xor_sync(0xffffffffu, ts0, 1);
        ts0 += __shfl_xor_sync(0xffffffffu, ts0, 2);
        ts1 += __shfl_xor_sync(0xffffffffu, ts1, 1);
        ts1 += __shfl_xor_sync(0xffffffffu, ts1, 2);
        lrow[0] = lrow[0] * al0 + ts0; mrow[0] = mn0;
        lrow[1] = lrow[1] * al1 + ts1; mrow[1] = mn1;
        #pragma unroll
        for (int ot = 0; ot < 16; ot++) {
            o[ot][0] *= al0; o[ot][1] *= al0;
            o[ot][2] *= al1; o[ot][3] *= al1;
        }

        // pack P (hi only) from accumulators
        uint32_t pH[4][4];
        #pragma unroll
        for (int k2 = 0; k2 < 4; k2++) {
            #pragma unroll
            for (int hx = 0; hx < 2; hx++) {
                int nt = 2 * k2 + hx;
                pH[k2][hx * 2 + 0] = packh(s[nt][0], s[nt][1]);
                pH[k2][hx * 2 + 1] = packh(s[nt][2], s[nt][3]);
            }
        }

        // O += P * (Vh + Vl)  (2-pass)
        #pragma unroll
        for (int k2 = 0; k2 < 4; k2++) {
            uint32_t bV[8][4];
            #pragma unroll
            for (int dv = 0; dv < 8; dv++)
                ldsm_x4_t(bV[dv], sVh_u + ((k2 * 16 + vrow) * AP + dv * 16 + vcol) * 2);
            #pragma unroll
            for (int ot = 0; ot < 16; ot++)
                mma16816(o[ot], pH[k2], &bV[ot >> 1][(ot & 1) * 2], o[ot]);
            #pragma unroll
            for (int dv = 0; dv < 8; dv++)
                ldsm_x4_t(bV[dv], sVl_u + ((k2 * 16 + vrow) * AP + dv * 16 + vcol) * 2);
            #pragma unroll
            for (int ot = 0; ot < 16; ot++)
                mma16816(o[ot], pH[k2], &bV[ot >> 1][(ot & 1) * 2], o[ot]);
        }
        __syncthreads();
    }

    // epilogue: normalize, write fp16 hi
    float inv0 = 1.f / lrow[0], inv1 = 1.f / lrow[1];
    int gr0 = m0 + wid * 16 + (l >> 2);
    #pragma unroll
    for (int ot = 0; ot < 16; ot++) {
        size_t i0 = base + (size_t)gr0 * CC + ot * 8 + (l & 3) * 2;
        size_t i1 = i0 + (size_t)8 * CC;
        *reinterpret_cast<uint32_t*>(Oh + i0) = packh(o[ot][0] * inv0, o[ot][1] * inv0);
        *reinterpret_cast<uint32_t*>(Oh + i1) = packh(o[ot][2] * inv1, o[ot][3] * inv1);
    }
}

// ---------------- launch -----------------------------------------------------
extern "C" void kernel_launch(void* const* d_in, const int* in_sizes, int n_in,
                              void* d_out, int out_size) {
    const float* residual = (const float*)d_in[0];
    const float* w[4] = {(const float*)d_in[1], (const float*)d_in[2],
                         (const float*)d_in[3], (const float*)d_in[4]};
    float* out = (float*)d_out;

    cudaFuncSetAttribute(attn_mma_kernel, cudaFuncAttributeMaxDynamicSharedMemorySize,
                         ATT_SMEM);
    cudaFuncSetAttribute(gemm_pipe_kernel<0>,
                         cudaFuncAttributeMaxDynamicSharedMemorySize, GEMM_SMEM);
    cudaFuncSetAttribute(gemm_pipe_kernel<1>,
                         cudaFuncAttributeMaxDynamicSharedMemorySize, GEMM_SMEM);

    void *pq, *pk, *pxh, *pyh, *pwh, *pwl, *pqh, *pkh, *pkl, *pvh, *pvl;
    cudaGetSymbolAddress(&pq, g_q);
    cudaGetSymbolAddress(&pk, g_k);
    cudaGetSymbolAddress(&pxh, g_xh);
    cudaGetSymbolAddress(&pyh, g_yh);
    cudaGetSymbolAddress(&pwh, g_wh);
    cudaGetSymbolAddress(&pwl, g_wl);
    cudaGetSymbolAddress(&pqh, g_qh);
    cudaGetSymbolAddress(&pkh, g_kh);
    cudaGetSymbolAddress(&pkl, g_kl);
    cudaGetSymbolAddress(&pvh, g_vh);
    cudaGetSymbolAddress(&pvl, g_vl);
    float* gq = (float*)pq; float* gk = (float*)pk;
    __half* xh = (__half*)pxh; __half* yh = (__half*)pyh;
    __half* wh = (__half*)pwh; __half* wl = (__half*)pwl;
    __half* qh = (__half*)pqh;
    __half* kh = (__half*)pkh; __half* kl = (__half*)pkl;
    __half* vh = (__half*)pvh; __half* vl = (__half*)pvl;

    const size_t WSZ = (size_t)CC * CC;

    // 0. split weights to fp16 hi/lo (pre-scaled x32)
    for (int i = 0; i < 4; i++)
        splitw_kernel<<<(int)(WSZ / 4 / 256), 256>>>(w[i], wh + i * WSZ, wl + i * WSZ,
                                                     (int)(WSZ / 4));
    // 1. rmsnorm input -> fp16 hi
    rmsnorm_in_kernel<<<BT, 256>>>(residual, xh);
    // 2. rope tables
    rope_table_kernel<<<(TT * 64 + 255) / 256, 256>>>();
    // 3. fused QKV projection: q,k fp32; v fp16 hi/lo
    dim3 qkvgrid(3 * CC / QN, BT / QM);
    gemm_pipe_kernel<0><<<qkvgrid, 256, GEMM_SMEM>>>(
        xh, wh, wl, nullptr, gq, gk, vh, vl);
    // 4. per-head rmsnorm + rope -> q fp16 hi, k fp16 hi/lo
    qknorm_rope_split_kernel<<<(BT * HH) / 8, 256>>>(gq, gk, qh, kh, kl);
    // 5. HMMA causal flash attention -> y fp16 hi
    dim3 agrid(TT / 128, BB * HH);
    attn_mma_kernel<<<agrid, 256, ATT_SMEM>>>(qh, kh, kl, vh, vl, yh);
    // 6. output projection + residual add
    dim3 pgrid(CC / QN, BT / QM);
    gemm_pipe_kernel<1><<<pgrid, 256, GEMM_SMEM>>>(
        yh, wh, wl, residual, out, nullptr, nullptr, nullptr);
}

// round 11
// speedup vs baseline: 7.0219x; 1.5848x over previous
#include <cuda_runtime.h>
#include <cuda_fp16.h>
#include <math.h>
#include <stdint.h>

// Problem constants
#define BB   4
#define TT   2048
#define CC   2048
#define HH   16
#define DH   128
#define BT   (BB * TT)          // 8192
#define ELEMS ((size_t)BT * CC) // 16777216

#define RMS_EPS 1.1920928955078125e-07f
#define WSCALE     32.0f        // weight pre-scale (keeps small weights normal in fp16)
#define WSCALE_INV 0.03125f

// ---------------- scratch (device globals; no allocation allowed) ----------
__device__ __align__(16) float g_q[ELEMS];
__device__ __align__(16) float g_k[ELEMS];
__device__ __align__(16) __half g_xh[ELEMS];
__device__ __align__(16) __half g_yh[ELEMS];
__device__ __align__(16) __half g_qh[ELEMS];
__device__ __align__(16) __half g_kh[ELEMS];
__device__ __align__(16) __half g_vh[ELEMS];
__device__ __align__(16) __half g_wh[4][(size_t)CC * CC];
__device__ __align__(16) float g_cos[TT * 64];
__device__ __align__(16) float g_sin[TT * 64];

// ======================= PTX helpers (portable, no 'a' features) ============
__device__ __forceinline__ uint32_t smem_u32(const void* p) {
    uint32_t a;
    asm("{ .reg .u64 t; cvta.to.shared.u64 t, %1; cvt.u32.u64 %0, t; }"
        : "=r"(a) : "l"(p));
    return a;
}

__device__ __forceinline__ void ldsm_x4(uint32_t* r, uint32_t addr) {
    asm volatile("ldmatrix.sync.aligned.m8n8.x4.shared.b16 {%0,%1,%2,%3}, [%4];"
                 : "=r"(r[0]), "=r"(r[1]), "=r"(r[2]), "=r"(r[3]) : "r"(addr));
}
__device__ __forceinline__ void ldsm_x4_t(uint32_t* r, uint32_t addr) {
    asm volatile("ldmatrix.sync.aligned.m8n8.x4.trans.shared.b16 {%0,%1,%2,%3}, [%4];"
                 : "=r"(r[0]), "=r"(r[1]), "=r"(r[2]), "=r"(r[3]) : "r"(addr));
}

// fp16 MMA, fp32 accumulate
__device__ __forceinline__ void mma16816(float* d, const uint32_t* a,
                                         const uint32_t* b, const float* c) {
    asm volatile(
        "mma.sync.aligned.m16n8k16.row.col.f32.f16.f16.f32 "
        "{%0,%1,%2,%3}, {%4,%5,%6,%7}, {%8,%9}, {%10,%11,%12,%13};\n"
        : "=f"(d[0]), "=f"(d[1]), "=f"(d[2]), "=f"(d[3])
        : "r"(a[0]), "r"(a[1]), "r"(a[2]), "r"(a[3]),
          "r"(b[0]), "r"(b[1]),
          "f"(c[0]), "f"(c[1]), "f"(c[2]), "f"(c[3]));
}

#define CP_ASYNC16(sdst, gsrc) \
    asm volatile("cp.async.cg.shared.global [%0], [%1], 16;" \
                 :: "r"(sdst), "l"(gsrc) : "memory")
#define CP_COMMIT() asm volatile("cp.async.commit_group;" ::: "memory")
#define CP_WAIT1()  asm volatile("cp.async.wait_group 1;" ::: "memory")
#define CP_WAIT0()  asm volatile("cp.async.wait_group 0;" ::: "memory")

// pack two fp32 into f16x2 (first arg -> low half)
__device__ __forceinline__ uint32_t packh(float lo, float hi) {
    uint32_t d;
    asm("cvt.rn.f16x2.f32 %0, %1, %2;" : "=r"(d) : "f"(hi), "f"(lo));
    return d;
}

// fast e^x for x <= 0 (no MUFU): 2^y with rint + deg-5 poly, rel err ~2.4e-6
__device__ __forceinline__ float fexp(float x) {
    float y = x * 1.4426950408889634f;
    y = fmaxf(y, -126.0f);
    float nf = rintf(y);
    float f = y - nf;
    float p = 1.3333558146e-3f;
    p = fmaf(p, f, 9.6181291076e-3f);
    p = fmaf(p, f, 5.5504108664e-2f);
    p = fmaf(p, f, 2.4022650696e-1f);
    p = fmaf(p, f, 6.9314718056e-1f);
    p = fmaf(p, f, 1.0f);
    return __int_as_float(__float_as_int(p) + (((int)nf) << 23));
}

// ---------------- kernel: cast weights fp32 -> fp16 (x WSCALE) --------------
__global__ __launch_bounds__(256) void castw_kernel(const float* __restrict__ in,
                                                    __half* __restrict__ hi,
                                                    int n4) {
    int i = blockIdx.x * 256 + threadIdx.x;
    if (i >= n4) return;
    float4 v = reinterpret_cast<const float4*>(in)[i];
    uint2 u;
    u.x = packh(v.x * WSCALE, v.y * WSCALE);
    u.y = packh(v.z * WSCALE, v.w * WSCALE);
    *reinterpret_cast<uint2*>(hi + 4 * (size_t)i) = u;
}

// ---------------- kernel 1: rmsnorm over C, output fp16 ---------------------
__global__ __launch_bounds__(256) void rmsnorm_in_kernel(const float* __restrict__ in,
                                                         __half* __restrict__ xh) {
    int row = blockIdx.x;
    const float4* ip = reinterpret_cast<const float4*>(in) + (size_t)row * 512;
    int t = threadIdx.x;
    float4 a = ip[t];
    float4 b = ip[t + 256];
    float ss = a.x*a.x + a.y*a.y + a.z*a.z + a.w*a.w
             + b.x*b.x + b.y*b.y + b.z*b.z + b.w*b.w;
    __shared__ float red[8];
    #pragma unroll
    for (int o = 16; o > 0; o >>= 1) ss += __shfl_xor_sync(0xffffffffu, ss, o);
    if ((t & 31) == 0) red[t >> 5] = ss;
    __syncthreads();
    if (t < 8) {
        float v = red[t];
        #pragma unroll
        for (int o = 4; o > 0; o >>= 1) v += __shfl_xor_sync(0xffu, v, o);
        if (t == 0) red[0] = v;
    }
    __syncthreads();
    float sc = rsqrtf(red[0] * (1.0f / 2048.0f) + RMS_EPS);
    size_t base = (size_t)row * CC;
    uint2 u0, u1;
    u0.x = packh(a.x * sc, a.y * sc); u0.y = packh(a.z * sc, a.w * sc);
    u1.x = packh(b.x * sc, b.y * sc); u1.y = packh(b.z * sc, b.w * sc);
    *reinterpret_cast<uint2*>(xh + base + 4 * t)         = u0;
    *reinterpret_cast<uint2*>(xh + base + 4 * (t + 256)) = u1;
}

// ---------------- kernel 2: RoPE cos/sin tables -----------------------------
__global__ void rope_table_kernel() {
    int idx = blockIdx.x * blockDim.x + threadIdx.x;
    if (idx >= TT * 64) return;
    int t = idx >> 6;
    int p = idx & 63;
    double inv = pow(10000.0, -((double)p) / 64.0);
    float ang = (float)t * (float)inv;
    g_cos[idx] = cosf(ang);
    g_sin[idx] = sinf(ang);
}

// ---------------- kernel 3: pipelined HMMA fp16 single-pass GEMM ------------
// C[m,n] = (1/WSCALE) * sum_k Ah[m,k]*Wh[n,k]  (+ addend)
// Block 128x128, Kc=32, cp.async double buffer, 2 smem arrays (Ah, Wh).
#define QM 128
#define QN 128
#define QKC 32
#define LDT 40                      // smem row pitch halves (80B)
#define ARR_B (QM * LDT * 2)        // 10240 bytes per array
#define BUF_B (2 * ARR_B)           // 20480 bytes per buffer
#define GEMM_SMEM (2 * BUF_B)       // 40960 bytes

__device__ __forceinline__ void gemm_chunk_load(
    uint32_t sbuf, const __half* __restrict__ Ah, const __half* __restrict__ Wh,
    int m0, int wrow0, int k0, int tid) {
    #pragma unroll
    for (int it = 0; it < 2; it++) {
        int idx = tid + it * 256;
        int r = idx >> 2, c = idx & 3;
        uint32_t so = (uint32_t)(r * LDT + c * 8) * 2;
        size_t ga = (size_t)(m0 + r) * CC + k0 + c * 8;
        size_t gw = (size_t)(wrow0 + r) * CC + k0 + c * 8;
        CP_ASYNC16(sbuf + 0 * ARR_B + so, Ah + ga);
        CP_ASYNC16(sbuf + 1 * ARR_B + so, Wh + gw);
    }
}

__device__ __forceinline__ void gemm_chunk_compute(
    uint32_t sbuf, int arow, int acol, int brow, int bk, float acc[4][4][4]) {
    uint32_t sAh = sbuf;
    uint32_t sWh = sbuf + 1 * ARR_B;
    #pragma unroll
    for (int ks = 0; ks < QKC; ks += 16) {
        uint32_t af[4][4], bh[2][4];
        #pragma unroll
        for (int mt = 0; mt < 4; mt++)
            ldsm_x4(af[mt], sAh + ((arow + mt * 16) * LDT + ks + acol) * 2);
        #pragma unroll
        for (int p = 0; p < 2; p++)
            ldsm_x4(bh[p], sWh + ((brow + p * 16) * LDT + ks + bk) * 2);
        #pragma unroll
        for (int mt = 0; mt < 4; mt++)
            #pragma unroll
            for (int nt = 0; nt < 4; nt++)
                mma16816(acc[mt][nt], af[mt], &bh[nt >> 1][(nt & 1) * 2], acc[mt][nt]);
    }
}

template <int MODE>
__global__ __launch_bounds__(256, 2) void gemm_pipe_kernel(
    const __half* __restrict__ Ah, const __half* __restrict__ Whb,
    const float* __restrict__ addend,
    float* __restrict__ outq, float* __restrict__ outk,
    __half* __restrict__ vh) {
    extern __shared__ __align__(16) char sdyn[];
    uint32_t sbase = smem_u32(sdyn);

    int tid = threadIdx.x;
    int l = tid & 31, wid = tid >> 5;
    int warp_m = wid >> 2;
    int warp_n = wid & 3;
    int m0 = blockIdx.y * QM;
    int n0 = blockIdx.x * QN;

    int which = (MODE == 0) ? (n0 >> 11) : 3;
    const __half* Wh = Whb + (size_t)which * CC * CC;
    int wrow0 = (MODE == 0) ? (n0 & 2047) : n0;

    float acc[4][4][4];
    #pragma unroll
    for (int i = 0; i < 4; i++)
        #pragma unroll
        for (int j = 0; j < 4; j++)
            #pragma unroll
            for (int q = 0; q < 4; q++) acc[i][j][q] = 0.f;

    int arow = warp_m * 64 + (l & 15);
    int acol = (l >> 4) << 3;
    int brow = warp_n * 32 + (l & 7) + ((l >> 4) << 3);
    int bk   = ((l >> 3) & 1) << 3;

    const int NC = CC / QKC;  // 64
    gemm_chunk_load(sbase, Ah, Wh, m0, wrow0, 0, tid);
    CP_COMMIT();

    for (int c = 0; c < NC; ++c) {
        uint32_t sbuf = sbase + (c & 1) * BUF_B;
        if (c + 1 < NC) {
            gemm_chunk_load(sbase + ((c + 1) & 1) * BUF_B, Ah, Wh,
                            m0, wrow0, (c + 1) * QKC, tid);
            CP_COMMIT();
            CP_WAIT1();
        } else {
            CP_WAIT0();
        }
        __syncthreads();
        gemm_chunk_compute(sbuf, arow, acol, brow, bk, acc);
        __syncthreads();
    }

    // epilogue (descale by 1/WSCALE)
    #pragma unroll
    for (int mt = 0; mt < 4; mt++) {
        #pragma unroll
        for (int nt = 0; nt < 4; nt++) {
            int row = m0 + warp_m * 64 + mt * 16 + (l >> 2);
            int col = wrow0 + warp_n * 32 + nt * 8 + (l & 3) * 2;
            size_t i0 = (size_t)row * CC + col;
            size_t i1 = (size_t)(row + 8) * CC + col;
            float2 v0 = make_float2(acc[mt][nt][0] * WSCALE_INV,
                                    acc[mt][nt][1] * WSCALE_INV);
            float2 v1 = make_float2(acc[mt][nt][2] * WSCALE_INV,
                                    acc[mt][nt][3] * WSCALE_INV);
            if (MODE == 1) {
                float2 a0 = *reinterpret_cast<const float2*>(addend + i0);
                float2 a1 = *reinterpret_cast<const float2*>(addend + i1);
                v0.x += a0.x; v0.y += a0.y;
                v1.x += a1.x; v1.y += a1.y;
                *reinterpret_cast<float2*>(outq + i0) = v0;
                *reinterpret_cast<float2*>(outq + i1) = v1;
            } else if (which == 0) {
                *reinterpret_cast<float2*>(outq + i0) = v0;
                *reinterpret_cast<float2*>(outq + i1) = v1;
            } else if (which == 1) {
                *reinterpret_cast<float2*>(outk + i0) = v0;
                *reinterpret_cast<float2*>(outk + i1) = v1;
            } else {
                *reinterpret_cast<uint32_t*>(vh + i0) = packh(v0.x, v0.y);
                *reinterpret_cast<uint32_t*>(vh + i1) = packh(v1.x, v1.y);
            }
        }
    }
}

// ---------------- kernel 4: per-head rmsnorm + RoPE -> fp16 -----------------
// q pre-scaled by 1/sqrt(DH)
__global__ __launch_bounds__(256) void qknorm_rope_kernel(
    const float* __restrict__ q, const float* __restrict__ k,
    __half* __restrict__ qh, __half* __restrict__ kh) {
    int gwarp = (blockIdx.x * 256 + threadIdx.x) >> 5;
    int lane  = threadIdx.x & 31;
    int m = gwarp >> 4;
    int h = gwarp & 15;
    int t = m & (TT - 1);
    size_t base = (size_t)m * CC + h * DH;
    const float qscale = 0.08838834764831845f;  // 1/sqrt(128)

    float c0 = g_cos[t * 64 + lane],      s0 = g_sin[t * 64 + lane];
    float c1 = g_cos[t * 64 + 32 + lane], s1 = g_sin[t * 64 + 32 + lane];

    #pragma unroll
    for (int w = 0; w < 2; w++) {
        const float* p = (w ? k : q) + base;
        __half* oh = (w ? kh : qh) + base;
        float sc2 = w ? 1.0f : qscale;
        float v0 = p[lane], v1 = p[lane + 32], v2 = p[lane + 64], v3 = p[lane + 96];
        float ss = v0*v0 + v1*v1 + v2*v2 + v3*v3;
        #pragma unroll
        for (int o = 16; o > 0; o >>= 1) ss += __shfl_xor_sync(0xffffffffu, ss, o);
        float sc = rsqrtf(ss * (1.0f / 128.0f) + RMS_EPS) * sc2;
        v0 *= sc; v1 *= sc; v2 *= sc; v3 *= sc;
        oh[lane]      = __float2half_rn(v0 * c0 + v2 * s0);
        oh[lane + 64] = __float2half_rn(v2 * c0 - v0 * s0);
        oh[lane + 32] = __float2half_rn(v1 * c1 + v3 * s1);
        oh[lane + 96] = __float2half_rn(v3 * c1 - v1 * s1);
    }
}

// ---------------- kernel 5: HMMA causal flash attention (fp16 1-pass) -------
// BM=128 q rows, BN=64 kv, cp.async double-buffered K/V stages.
#define AP 136   // smem pitch in halves (272B) -> conflict-free ldmatrix
// smem halves: sQ 128*AP, then 2 stages x (K,V each 64*AP)
#define ATT_SMEM ((128 * AP + 2 * 128 * AP) * 2)   // 104448 bytes

__device__ __forceinline__ void attn_load_stage(
    uint32_t st_u, const __half* __restrict__ Kh, const __half* __restrict__ Vh,
    int n0, size_t base, int tid) {
    const uint32_t V_OFF = 64 * AP * 2;
    #pragma unroll
    for (int it = 0; it < 4; it++) {
        int idx = tid + it * 256;
        int r = idx >> 4, c = idx & 15;
        size_t g = base + (size_t)(n0 + r) * CC + c * 8;
        uint32_t so = (uint32_t)(r * AP + c * 8) * 2;
        CP_ASYNC16(st_u + so, Kh + g);
        CP_ASYNC16(st_u + V_OFF + so, Vh + g);
    }
}

__global__ __launch_bounds__(256, 1) void attn_mma_kernel(
    const __half* __restrict__ Qh, const __half* __restrict__ Kh,
    const __half* __restrict__ Vh, __half* __restrict__ Oh) {
    extern __shared__ __half smA[];
    __half* sQ = smA;

    int tid = threadIdx.x;
    int l = tid & 31, wid = tid >> 5;
    int qt = (int)(gridDim.x - 1 - blockIdx.x);   // heavy tiles first
    int m0 = qt * 128;
    int bh = blockIdx.y;
    int b = bh >> 4, h = bh & 15;
    size_t base = (size_t)b * TT * CC + (size_t)h * DH;

    uint32_t sQ_u = smem_u32(sQ);
    uint32_t stage_u[2];
    stage_u[0] = sQ_u + 128 * AP * 2;
    stage_u[1] = stage_u[0] + 128 * AP * 2;

    // load Q: 128 rows x 128 halves
    for (int idx = tid; idx < 128 * 16; idx += 256) {
        int r = idx >> 4, c = idx & 15;
        size_t g = base + (size_t)(m0 + r) * CC + c * 8;
        *reinterpret_cast<uint4*>(&sQ[r * AP + c * 8]) =
            *reinterpret_cast<const uint4*>(&Qh[g]);
    }

    float o[16][4];
    #pragma unroll
    for (int i = 0; i < 16; i++)
        #pragma unroll
        for (int j = 0; j < 4; j++) o[i][j] = 0.f;
    float mrow[2] = {-1e30f, -1e30f};
    float lrow[2] = {0.f, 0.f};

    int aoff = ((wid * 16 + (l & 15)) * AP + ((l >> 4) << 3)) * 2;
    int brow = (l & 7) + ((l >> 4) << 3);
    int bk   = ((l >> 3) & 1) << 3;
    int vrow = l & 15;
    int vcol = (l >> 4) << 3;

    int nkv = 2 * qt + 2;
    attn_load_stage(stage_u[0], Kh, Vh, 0, base, tid);
    CP_COMMIT();

    for (int kt = 0; kt < nkv; ++kt) {
        int n0 = kt * 64;
        uint32_t st = stage_u[kt & 1];
        if (kt + 1 < nkv) {
            attn_load_stage(stage_u[(kt + 1) & 1], Kh, Vh, (kt + 1) * 64, base, tid);
            CP_COMMIT();
            CP_WAIT1();
        } else {
            CP_WAIT0();
        }
        __syncthreads();

        uint32_t sK_u = st;
        uint32_t sV_u = st + 64 * AP * 2;

        float s[8][4];
        #pragma unroll
        for (int i = 0; i < 8; i++)
            #pragma unroll
            for (int j = 0; j < 4; j++) s[i][j] = 0.f;

        // S = Q * K^T (single pass)
        #pragma unroll
        for (int ks = 0; ks < 8; ++ks) {
            uint32_t aH[4], bb[4][4];
            ldsm_x4(aH, sQ_u + aoff + ks * 32);
            #pragma unroll
            for (int p = 0; p < 4; p++)
                ldsm_x4(bb[p], sK_u + ((p * 16 + brow) * AP + ks * 16 + bk) * 2);
            #pragma unroll
            for (int nt = 0; nt < 8; nt++)
                mma16816(s[nt], aH, &bb[nt >> 1][(nt & 1) * 2], s[nt]);
        }

        int gr0 = m0 + wid * 16 + (l >> 2);
        int gr1 = gr0 + 8;
        if (kt >= 2 * qt) {
            #pragma unroll
            for (int nt = 0; nt < 8; nt++) {
                int c0 = n0 + nt * 8 + (l & 3) * 2;
                if (c0     > gr0) s[nt][0] = -1e30f;
                if (c0 + 1 > gr0) s[nt][1] = -1e30f;
                if (c0     > gr1) s[nt][2] = -1e30f;
                if (c0 + 1 > gr1) s[nt][3] = -1e30f;
            }
        }
        float tm0 = -1e30f, tm1 = -1e30f;
        #pragma unroll
        for (int nt = 0; nt < 8; nt++) {
            tm0 = fmaxf(tm0, fmaxf(s[nt][0], s[nt][1]));
            tm1 = fmaxf(tm1, fmaxf(s[nt][2], s[nt][3]));
        }
        tm0 = fmaxf(tm0, __shfl_xor_sync(0xffffffffu, tm0, 1));
        tm0 = fmaxf(tm0, __shfl_xor_sync(0xffffffffu, tm0, 2));
        tm1 = fmaxf(tm1, __shfl_xor_sync(0xffffffffu, tm1, 1));
        tm1 = fmaxf(tm1, __shfl_xor_sync(0xffffffffu, tm1, 2));
        float mn0 = fmaxf(mrow[0], tm0), mn1 = fmaxf(mrow[1], tm1);
        float al0 = fexp(mrow[0] - mn0), al1 = fexp(mrow[1] - mn1);
        float ts0 = 0.f, ts1 = 0.f;
        #pragma unroll
        for (int nt = 0; nt < 8; nt++) {
            s[nt][0] = fexp(s[nt][0] - mn0); ts0 += s[nt][0];
            s[nt][1] = fexp(s[nt][1] - mn0); ts0 += s[nt][1];
            s[nt][2] = fexp(s[nt][2] - mn1); ts1 += s[nt][2];
            s[nt][3] = fexp(s[nt][3] - mn1); ts1 += s[nt][3];
        }
        ts0 += __shfl_xor_sync(0xffffffffu, ts0, 1);
        ts0 += __shfl_xor_sync(0xffffffffu, ts0, 2);
        ts1 += __shfl_xor_sync(0xffffffffu, ts1, 1);
        ts1 += __shfl_xor_sync(0xffffffffu, ts1, 2);
        lrow[0] = lrow[0] * al0 + ts0; mrow[0] = mn0;
        lrow[1] = lrow[1] * al1 + ts1; mrow[1] = mn1;
        #pragma unroll
        for (int ot = 0; ot < 16; ot++) {
            o[ot][0] *= al0; o[ot][1] *= al0;
            o[ot][2] *= al1; o[ot][3] *= al1;
        }

        // pack P from accumulators
        uint32_t pH[4][4];
        #pragma unroll
        for (int k2 = 0; k2 < 4; k2++) {
            #pragma unroll
            for (int hx = 0; hx < 2; hx++) {
                int nt = 2 * k2 + hx;
                pH[k2][hx * 2 + 0] = packh(s[nt][0], s[nt][1]);
                pH[k2][hx * 2 + 1] = packh(s[nt][2], s[nt][3]);
            }
        }

        // O += P * V (single pass)
        #pragma unroll
        for (int k2 = 0; k2 < 4; k2++) {
            uint32_t bV[8][4];
            #pragma unroll
            for (int dv = 0; dv < 8; dv++)
                ldsm_x4_t(bV[dv], sV_u + ((k2 * 16 + vrow) * AP + dv * 16 + vcol) * 2);
            #pragma unroll
            for (int ot = 0; ot < 16; ot++)
                mma16816(o[ot], pH[k2], &bV[ot >> 1][(ot & 1) * 2], o[ot]);
        }
        __syncthreads();
    }

    // epilogue: normalize, write fp16
    float inv0 = 1.f / lrow[0], inv1 = 1.f / lrow[1];
    int gr0 = m0 + wid * 16 + (l >> 2);
    #pragma unroll
    for (int ot = 0; ot < 16; ot++) {
        size_t i0 = base + (size_t)gr0 * CC + ot * 8 + (l & 3) * 2;
        size_t i1 = i0 + (size_t)8 * CC;
        *reinterpret_cast<uint32_t*>(Oh + i0) = packh(o[ot][0] * inv0, o[ot][1] * inv0);
        *reinterpret_cast<uint32_t*>(Oh + i1) = packh(o[ot][2] * inv1, o[ot][3] * inv1);
    }
}

// ---------------- launch -----------------------------------------------------
extern "C" void kernel_launch(void* const* d_in, const int* in_sizes, int n_in,
                              void* d_out, int out_size) {
    const float* residual = (const float*)d_in[0];
    const float* w[4] = {(const float*)d_in[1], (const float*)d_in[2],
                         (const float*)d_in[3], (const float*)d_in[4]};
    float* out = (float*)d_out;

    cudaFuncSetAttribute(attn_mma_kernel, cudaFuncAttributeMaxDynamicSharedMemorySize,
                         ATT_SMEM);
    cudaFuncSetAttribute(gemm_pipe_kernel<0>,
                         cudaFuncAttributeMaxDynamicSharedMemorySize, GEMM_SMEM);
    cudaFuncSetAttribute(gemm_pipe_kernel<1>,
                         cudaFuncAttributeMaxDynamicSharedMemorySize, GEMM_SMEM);

    void *pq, *pk, *pxh, *pyh, *pwh, *pqh, *pkh, *pvh;
    cudaGetSymbolAddress(&pq, g_q);
    cudaGetSymbolAddress(&pk, g_k);
    cudaGetSymbolAddress(&pxh, g_xh);
    cudaGetSymbolAddress(&pyh, g_yh);
    cudaGetSymbolAddress(&pwh, g_wh);
    cudaGetSymbolAddress(&pqh, g_qh);
    cudaGetSymbolAddress(&pkh, g_kh);
    cudaGetSymbolAddress(&pvh, g_vh);
    float* gq = (float*)pq; float* gk = (float*)pk;
    __half* xh = (__half*)pxh; __half* yh = (__half*)pyh;
    __half* wh = (__half*)pwh;
    __half* qh = (__half*)pqh; __half* kh = (__half*)pkh; __half* vh = (__half*)pvh;

    const size_t WSZ = (size_t)CC * CC;

    // 0. cast weights to fp16 (pre-scaled x32)
    for (int i = 0; i < 4; i++)
        castw_kernel<<<(int)(WSZ / 4 / 256), 256>>>(w[i], wh + i * WSZ,
                                                    (int)(WSZ / 4));
    // 1. rmsnorm input -> fp16
    rmsnorm_in_kernel<<<BT, 256>>>(residual, xh);
    // 2. rope tables
    rope_table_kernel<<<(TT * 64 + 255) / 256, 256>>>();
    // 3. fused QKV projection: q,k fp32; v fp16
    dim3 qkvgrid(3 * CC / QN, BT / QM);
    gemm_pipe_kernel<0><<<qkvgrid, 256, GEMM_SMEM>>>(xh, wh, nullptr, gq, gk, vh);
    // 4. per-head rmsnorm + rope -> fp16 q,k
    qknorm_rope_kernel<<<(BT * HH) / 8, 256>>>(gq, gk, qh, kh);
    // 5. HMMA causal flash attention -> fp16 y
    dim3 agrid(TT / 128, BB * HH);
    attn_mma_kernel<<<agrid, 256, ATT_SMEM>>>(qh, kh, vh, yh);
    // 6. output projection + residual add
    dim3 pgrid(CC / QN, BT / QM);
    gemm_pipe_kernel<1><<<pgrid, 256, GEMM_SMEM>>>(yh, wh, residual, out, nullptr, nullptr);
}

// round 12
// speedup vs baseline: 7.9190x; 1.1278x over previous
#include <cuda_runtime.h>
#include <cuda_fp16.h>
#include <math.h>
#include <stdint.h>

// Problem constants
#define BB   4
#define TT   2048
#define CC   2048
#define HH   16
#define DH   128
#define BT   (BB * TT)          // 8192
#define ELEMS ((size_t)BT * CC) // 16777216

#define RMS_EPS 1.1920928955078125e-07f
#define WSCALE     32.0f        // weight pre-scale (keeps small weights normal in fp16)
#define WSCALE_INV 0.03125f

// ---------------- scratch (device globals; no allocation allowed) ----------
__device__ __align__(16) float g_q[ELEMS];
__device__ __align__(16) float g_k[ELEMS];
__device__ __align__(16) __half g_xh[ELEMS];
__device__ __align__(16) __half g_yh[ELEMS];
__device__ __align__(16) __half g_qh[ELEMS];
__device__ __align__(16) __half g_kh[ELEMS];
__device__ __align__(16) __half g_vh[ELEMS];
__device__ __align__(16) __half g_wh[4][(size_t)CC * CC];
__device__ __align__(16) float g_cos[TT * 64];
__device__ __align__(16) float g_sin[TT * 64];

// ======================= PTX helpers (portable, no 'a' features) ============
__device__ __forceinline__ uint32_t smem_u32(const void* p) {
    uint32_t a;
    asm("{ .reg .u64 t; cvta.to.shared.u64 t, %1; cvt.u32.u64 %0, t; }"
        : "=r"(a) : "l"(p));
    return a;
}

__device__ __forceinline__ void ldsm_x4(uint32_t* r, uint32_t addr) {
    asm volatile("ldmatrix.sync.aligned.m8n8.x4.shared.b16 {%0,%1,%2,%3}, [%4];"
                 : "=r"(r[0]), "=r"(r[1]), "=r"(r[2]), "=r"(r[3]) : "r"(addr));
}
__device__ __forceinline__ void ldsm_x4_t(uint32_t* r, uint32_t addr) {
    asm volatile("ldmatrix.sync.aligned.m8n8.x4.trans.shared.b16 {%0,%1,%2,%3}, [%4];"
                 : "=r"(r[0]), "=r"(r[1]), "=r"(r[2]), "=r"(r[3]) : "r"(addr));
}

// fp16 MMA, fp32 accumulate
__device__ __forceinline__ void mma16816(float* d, const uint32_t* a,
                                         const uint32_t* b, const float* c) {
    asm volatile(
        "mma.sync.aligned.m16n8k16.row.col.f32.f16.f16.f32 "
        "{%0,%1,%2,%3}, {%4,%5,%6,%7}, {%8,%9}, {%10,%11,%12,%13};\n"
        : "=f"(d[0]), "=f"(d[1]), "=f"(d[2]), "=f"(d[3])
        : "r"(a[0]), "r"(a[1]), "r"(a[2]), "r"(a[3]),
          "r"(b[0]), "r"(b[1]),
          "f"(c[0]), "f"(c[1]), "f"(c[2]), "f"(c[3]));
}

#define CP_ASYNC16(sdst, gsrc) \
    asm volatile("cp.async.cg.shared.global [%0], [%1], 16;" \
                 :: "r"(sdst), "l"(gsrc) : "memory")
#define CP_COMMIT() asm volatile("cp.async.commit_group;" ::: "memory")
#define CP_WAIT2()  asm volatile("cp.async.wait_group 2;" ::: "memory")
#define CP_WAIT1()  asm volatile("cp.async.wait_group 1;" ::: "memory")
#define CP_WAIT0()  asm volatile("cp.async.wait_group 0;" ::: "memory")

// pack two fp32 into f16x2 (first arg -> low half)
__device__ __forceinline__ uint32_t packh(float lo, float hi) {
    uint32_t d;
    asm("cvt.rn.f16x2.f32 %0, %1, %2;" : "=r"(d) : "f"(hi), "f"(lo));
    return d;
}

// fast e^x for x <= 0 (no MUFU): 2^y with rint + deg-5 poly, rel err ~2.4e-6
__device__ __forceinline__ float fexp(float x) {
    float y = x * 1.4426950408889634f;
    y = fmaxf(y, -126.0f);
    float nf = rintf(y);
    float f = y - nf;
    float p = 1.3333558146e-3f;
    p = fmaf(p, f, 9.6181291076e-3f);
    p = fmaf(p, f, 5.5504108664e-2f);
    p = fmaf(p, f, 2.4022650696e-1f);
    p = fmaf(p, f, 6.9314718056e-1f);
    p = fmaf(p, f, 1.0f);
    return __int_as_float(__float_as_int(p) + (((int)nf) << 23));
}

// ---------------- kernel: cast all 4 weights fp32 -> fp16 (x WSCALE) --------
__global__ __launch_bounds__(256) void castw4_kernel(const float* __restrict__ w0,
                                                     const float* __restrict__ w1,
                                                     const float* __restrict__ w2,
                                                     const float* __restrict__ w3,
                                                     __half* __restrict__ hi) {
    int gb = blockIdx.x >> 12;              // 4096 blocks per weight
    const float* in = (gb == 0) ? w0 : (gb == 1) ? w1 : (gb == 2) ? w2 : w3;
    size_t i = (size_t)(blockIdx.x & 4095) * 256 + threadIdx.x;
    float4 v = reinterpret_cast<const float4*>(in)[i];
    uint2 u;
    u.x = packh(v.x * WSCALE, v.y * WSCALE);
    u.y = packh(v.z * WSCALE, v.w * WSCALE);
    *reinterpret_cast<uint2*>(hi + (size_t)gb * CC * CC + 4 * i) = u;
}

// ---------------- kernel 1: rmsnorm over C, output fp16 ---------------------
__global__ __launch_bounds__(256) void rmsnorm_in_kernel(const float* __restrict__ in,
                                                         __half* __restrict__ xh) {
    int row = blockIdx.x;
    const float4* ip = reinterpret_cast<const float4*>(in) + (size_t)row * 512;
    int t = threadIdx.x;
    float4 a = ip[t];
    float4 b = ip[t + 256];
    float ss = a.x*a.x + a.y*a.y + a.z*a.z + a.w*a.w
             + b.x*b.x + b.y*b.y + b.z*b.z + b.w*b.w;
    __shared__ float red[8];
    #pragma unroll
    for (int o = 16; o > 0; o >>= 1) ss += __shfl_xor_sync(0xffffffffu, ss, o);
    if ((t & 31) == 0) red[t >> 5] = ss;
    __syncthreads();
    if (t < 8) {
        float v = red[t];
        #pragma unroll
        for (int o = 4; o > 0; o >>= 1) v += __shfl_xor_sync(0xffu, v, o);
        if (t == 0) red[0] = v;
    }
    __syncthreads();
    float sc = rsqrtf(red[0] * (1.0f / 2048.0f) + RMS_EPS);
    size_t base = (size_t)row * CC;
    uint2 u0, u1;
    u0.x = packh(a.x * sc, a.y * sc); u0.y = packh(a.z * sc, a.w * sc);
    u1.x = packh(b.x * sc, b.y * sc); u1.y = packh(b.z * sc, b.w * sc);
    *reinterpret_cast<uint2*>(xh + base + 4 * t)         = u0;
    *reinterpret_cast<uint2*>(xh + base + 4 * (t + 256)) = u1;
}

// ---------------- kernel 2: RoPE cos/sin tables -----------------------------
__global__ void rope_table_kernel() {
    int idx = blockIdx.x * blockDim.x + threadIdx.x;
    if (idx >= TT * 64) return;
    int t = idx >> 6;
    int p = idx & 63;
    double inv = pow(10000.0, -((double)p) / 64.0);
    float ang = (float)t * (float)inv;
    g_cos[idx] = cosf(ang);
    g_sin[idx] = sinf(ang);
}

// ---------------- kernel 3: 3-stage pipelined HMMA fp16 GEMM ----------------
// C[m,n] = (1/WSCALE) * sum_k Ah[m,k]*Wh[n,k]  (+ addend)
// Block 128x128, Kc=64, cp.async 3-stage ring, ONE sync per chunk.
#define QM 128
#define QN 128
#define QKC 64
#define LDT 72                      // smem row pitch halves (144B) -> conflict-free
#define ARR_B (QM * LDT * 2)        // 18432 bytes per array
#define BUF_B (2 * ARR_B)           // 36864 bytes per stage (A + W)
#define GEMM_SMEM (3 * BUF_B)       // 110592 bytes

__device__ __forceinline__ void gemm_chunk_load(
    uint32_t sbuf, const __half* __restrict__ Ah, const __half* __restrict__ Wh,
    int m0, int wrow0, int k0, int tid) {
    #pragma unroll
    for (int it = 0; it < 4; it++) {
        int idx = tid + it * 256;           // 0..1023
        int r = idx >> 3, c = idx & 7;
        uint32_t so = (uint32_t)(r * LDT + c * 8) * 2;
        size_t ga = (size_t)(m0 + r) * CC + k0 + c * 8;
        size_t gw = (size_t)(wrow0 + r) * CC + k0 + c * 8;
        CP_ASYNC16(sbuf + 0 * ARR_B + so, Ah + ga);
        CP_ASYNC16(sbuf + 1 * ARR_B + so, Wh + gw);
    }
}

__device__ __forceinline__ void gemm_chunk_compute(
    uint32_t sbuf, int arow, int acol, int brow, int bk, float acc[4][4][4]) {
    uint32_t sAh = sbuf;
    uint32_t sWh = sbuf + 1 * ARR_B;
    #pragma unroll
    for (int ks = 0; ks < QKC; ks += 16) {
        uint32_t af[4][4], bh[2][4];
        #pragma unroll
        for (int mt = 0; mt < 4; mt++)
            ldsm_x4(af[mt], sAh + ((arow + mt * 16) * LDT + ks + acol) * 2);
        #pragma unroll
        for (int p = 0; p < 2; p++)
            ldsm_x4(bh[p], sWh + ((brow + p * 16) * LDT + ks + bk) * 2);
        #pragma unroll
        for (int mt = 0; mt < 4; mt++)
            #pragma unroll
            for (int nt = 0; nt < 4; nt++)
                mma16816(acc[mt][nt], af[mt], &bh[nt >> 1][(nt & 1) * 2], acc[mt][nt]);
    }
}

template <int MODE>
__global__ __launch_bounds__(256, 2) void gemm_pipe_kernel(
    const __half* __restrict__ Ah, const __half* __restrict__ Whb,
    const float* __restrict__ addend,
    float* __restrict__ outq, float* __restrict__ outk,
    __half* __restrict__ vh) {
    extern __shared__ __align__(16) char sdyn[];
    uint32_t sbase = smem_u32(sdyn);

    int tid = threadIdx.x;
    int l = tid & 31, wid = tid >> 5;
    int warp_m = wid >> 2;
    int warp_n = wid & 3;
    int m0 = blockIdx.y * QM;
    int n0 = blockIdx.x * QN;

    int which = (MODE == 0) ? (n0 >> 11) : 3;
    const __half* Wh = Whb + (size_t)which * CC * CC;
    int wrow0 = (MODE == 0) ? (n0 & 2047) : n0;

    float acc[4][4][4];
    #pragma unroll
    for (int i = 0; i < 4; i++)
        #pragma unroll
        for (int j = 0; j < 4; j++)
            #pragma unroll
            for (int q = 0; q < 4; q++) acc[i][j][q] = 0.f;

    int arow = warp_m * 64 + (l & 15);
    int acol = (l >> 4) << 3;
    int brow = warp_n * 32 + (l & 7) + ((l >> 4) << 3);
    int bk   = ((l >> 3) & 1) << 3;

    const int NC = CC / QKC;  // 32
    gemm_chunk_load(sbase + 0 * BUF_B, Ah, Wh, m0, wrow0, 0, tid);
    CP_COMMIT();
    gemm_chunk_load(sbase + 1 * BUF_B, Ah, Wh, m0, wrow0, QKC, tid);
    CP_COMMIT();

    int st = 0;            // stage of chunk c
    for (int c = 0; c < NC; ++c) {
        if (c + 1 < NC) CP_WAIT1(); else CP_WAIT0();
        __syncthreads();   // stage c visible; all threads done computing c-1
        if (c + 2 < NC) {
            int st2 = st + 2; if (st2 >= 3) st2 -= 3;
            gemm_chunk_load(sbase + st2 * BUF_B, Ah, Wh, m0, wrow0,
                            (c + 2) * QKC, tid);
            CP_COMMIT();
        }
        gemm_chunk_compute(sbase + st * BUF_B, arow, acol, brow, bk, acc);
        if (++st == 3) st = 0;
    }

    // epilogue (descale by 1/WSCALE)
    #pragma unroll
    for (int mt = 0; mt < 4; mt++) {
        #pragma unroll
        for (int nt = 0; nt < 4; nt++) {
            int row = m0 + warp_m * 64 + mt * 16 + (l >> 2);
            int col = wrow0 + warp_n * 32 + nt * 8 + (l & 3) * 2;
            size_t i0 = (size_t)row * CC + col;
            size_t i1 = (size_t)(row + 8) * CC + col;
            float2 v0 = make_float2(acc[mt][nt][0] * WSCALE_INV,
                                    acc[mt][nt][1] * WSCALE_INV);
            float2 v1 = make_float2(acc[mt][nt][2] * WSCALE_INV,
                                    acc[mt][nt][3] * WSCALE_INV);
            if (MODE == 1) {
                float2 a0 = *reinterpret_cast<const float2*>(addend + i0);
                float2 a1 = *reinterpret_cast<const float2*>(addend + i1);
                v0.x += a0.x; v0.y += a0.y;
                v1.x += a1.x; v1.y += a1.y;
                *reinterpret_cast<float2*>(outq + i0) = v0;
                *reinterpret_cast<float2*>(outq + i1) = v1;
            } else if (which == 0) {
                *reinterpret_cast<float2*>(outq + i0) = v0;
                *reinterpret_cast<float2*>(outq + i1) = v1;
            } else if (which == 1) {
                *reinterpret_cast<float2*>(outk + i0) = v0;
                *reinterpret_cast<float2*>(outk + i1) = v1;
            } else {
                *reinterpret_cast<uint32_t*>(vh + i0) = packh(v0.x, v0.y);
                *reinterpret_cast<uint32_t*>(vh + i1) = packh(v1.x, v1.y);
            }
        }
    }
}

// ---------------- kernel 4: per-head rmsnorm + RoPE -> fp16 -----------------
// q pre-scaled by 1/sqrt(DH)
__global__ __launch_bounds__(256) void qknorm_rope_kernel(
    const float* __restrict__ q, const float* __restrict__ k,
    __half* __restrict__ qh, __half* __restrict__ kh) {
    int gwarp = (blockIdx.x * 256 + threadIdx.x) >> 5;
    int lane  = threadIdx.x & 31;
    int m = gwarp >> 4;
    int h = gwarp & 15;
    int t = m & (TT - 1);
    size_t base = (size_t)m * CC + h * DH;
    const float qscale = 0.08838834764831845f;  // 1/sqrt(128)

    float c0 = g_cos[t * 64 + lane],      s0 = g_sin[t * 64 + lane];
    float c1 = g_cos[t * 64 + 32 + lane], s1 = g_sin[t * 64 + 32 + lane];

    #pragma unroll
    for (int w = 0; w < 2; w++) {
        const float* p = (w ? k : q) + base;
        __half* oh = (w ? kh : qh) + base;
        float sc2 = w ? 1.0f : qscale;
        float v0 = p[lane], v1 = p[lane + 32], v2 = p[lane + 64], v3 = p[lane + 96];
        float ss = v0*v0 + v1*v1 + v2*v2 + v3*v3;
        #pragma unroll
        for (int o = 16; o > 0; o >>= 1) ss += __shfl_xor_sync(0xffffffffu, ss, o);
        float sc = rsqrtf(ss * (1.0f / 128.0f) + RMS_EPS) * sc2;
        v0 *= sc; v1 *= sc; v2 *= sc; v3 *= sc;
        oh[lane]      = __float2half_rn(v0 * c0 + v2 * s0);
        oh[lane + 64] = __float2half_rn(v2 * c0 - v0 * s0);
        oh[lane + 32] = __float2half_rn(v1 * c1 + v3 * s1);
        oh[lane + 96] = __float2half_rn(v3 * c1 - v1 * s1);
    }
}

// ---------------- kernel 5: HMMA causal flash attention (BM=128, BN=128) ----
#define AP 136   // smem pitch in halves (272B) -> conflict-free ldmatrix
// smem halves: sQ 128*AP, then 2 stages x (K 128*AP + V 128*AP)
#define ATT_SMEM ((128 + 2 * 256) * AP * 2)   // 174080 bytes

__device__ __forceinline__ void attn_load_stage(
    uint32_t st_u, const __half* __restrict__ Kh, const __half* __restrict__ Vh,
    int n0, size_t base, int tid) {
    const uint32_t V_OFF = 128 * AP * 2;
    #pragma unroll
    for (int it = 0; it < 8; it++) {
        int idx = tid + it * 256;           // 0..2047
        int r = idx >> 4, c = idx & 15;
        size_t g = base + (size_t)(n0 + r) * CC + c * 8;
        uint32_t so = (uint32_t)(r * AP + c * 8) * 2;
        CP_ASYNC16(st_u + so, Kh + g);
        CP_ASYNC16(st_u + V_OFF + so, Vh + g);
    }
}

__global__ __launch_bounds__(256, 1) void attn_mma_kernel(
    const __half* __restrict__ Qh, const __half* __restrict__ Kh,
    const __half* __restrict__ Vh, __half* __restrict__ Oh) {
    extern __shared__ __half smA[];
    __half* sQ = smA;

    int tid = threadIdx.x;
    int l = tid & 31, wid = tid >> 5;
    int qt = (int)(gridDim.x - 1 - blockIdx.x);   // heavy tiles first
    int m0 = qt * 128;
    int bh = blockIdx.y;
    int b = bh >> 4, h = bh & 15;
    size_t base = (size_t)b * TT * CC + (size_t)h * DH;

    uint32_t sQ_u = smem_u32(sQ);
    uint32_t stage_u[2];
    stage_u[0] = sQ_u + 128 * AP * 2;
    stage_u[1] = stage_u[0] + 256 * AP * 2;

    // load Q: 128 rows x 128 halves
    for (int idx = tid; idx < 128 * 16; idx += 256) {
        int r = idx >> 4, c = idx & 15;
        size_t g = base + (size_t)(m0 + r) * CC + c * 8;
        *reinterpret_cast<uint4*>(&sQ[r * AP + c * 8]) =
            *reinterpret_cast<const uint4*>(&Qh[g]);
    }

    float o[16][4];
    #pragma unroll
    for (int i = 0; i < 16; i++)
        #pragma unroll
        for (int j = 0; j < 4; j++) o[i][j] = 0.f;
    float mrow[2] = {-1e30f, -1e30f};
    float lrow[2] = {0.f, 0.f};

    int aoff = ((wid * 16 + (l & 15)) * AP + ((l >> 4) << 3)) * 2;
    int brow = (l & 7) + ((l >> 4) << 3);
    int bk   = ((l >> 3) & 1) << 3;
    int vrow = l & 15;
    int vcol = (l >> 4) << 3;

    int nkv = qt + 1;
    attn_load_stage(stage_u[0], Kh, Vh, 0, base, tid);
    CP_COMMIT();

    for (int kt = 0; kt < nkv; ++kt) {
        int n0 = kt * 128;
        uint32_t st = stage_u[kt & 1];
        if (kt + 1 < nkv) {
            attn_load_stage(stage_u[(kt + 1) & 1], Kh, Vh, (kt + 1) * 128, base, tid);
            CP_COMMIT();
            CP_WAIT1();
        } else {
            CP_WAIT0();
        }
        __syncthreads();

        uint32_t sK_u = st;
        uint32_t sV_u = st + 128 * AP * 2;

        float s[16][4];
        #pragma unroll
        for (int i = 0; i < 16; i++)
            #pragma unroll
            for (int j = 0; j < 4; j++) s[i][j] = 0.f;

        // S = Q * K^T (single pass), K processed in two 64-row halves
        #pragma unroll
        for (int ks = 0; ks < 8; ++ks) {
            uint32_t aH[4], bb[4][4];
            ldsm_x4(aH, sQ_u + aoff + ks * 32);
            #pragma unroll
            for (int p = 0; p < 4; p++)
                ldsm_x4(bb[p], sK_u + ((p * 16 + brow) * AP + ks * 16 + bk) * 2);
            #pragma unroll
            for (int nt = 0; nt < 8; nt++)
                mma16816(s[nt], aH, &bb[nt >> 1][(nt & 1) * 2], s[nt]);
            #pragma unroll
            for (int p = 0; p < 4; p++)
                ldsm_x4(bb[p], sK_u + (((p + 4) * 16 + brow) * AP + ks * 16 + bk) * 2);
            #pragma unroll
            for (int nt = 0; nt < 8; nt++)
                mma16816(s[nt + 8], aH, &bb[nt >> 1][(nt & 1) * 2], s[nt + 8]);
        }

        int gr0 = m0 + wid * 16 + (l >> 2);
        int gr1 = gr0 + 8;
        if (kt == qt) {   // diagonal tile -> causal mask
            #pragma unroll
            for (int nt = 0; nt < 16; nt++) {
                int c0 = n0 + nt * 8 + (l & 3) * 2;
                if (c0     > gr0) s[nt][0] = -1e30f;
                if (c0 + 1 > gr0) s[nt][1] = -1e30f;
                if (c0     > gr1) s[nt][2] = -1e30f;
                if (c0 + 1 > gr1) s[nt][3] = -1e30f;
            }
        }
        float tm0 = -1e30f, tm1 = -1e30f;
        #pragma unroll
        for (int nt = 0; nt < 16; nt++) {
            tm0 = fmaxf(tm0, fmaxf(s[nt][0], s[nt][1]));
            tm1 = fmaxf(tm1, fmaxf(s[nt][2], s[nt][3]));
        }
        tm0 = fmaxf(tm0, __shfl_xor_sync(0xffffffffu, tm0, 1));
        tm0 = fmaxf(tm0, __shfl_xor_sync(0xffffffffu, tm0, 2));
        tm1 = fmaxf(tm1, __shfl_xor_sync(0xffffffffu, tm1, 1));
        tm1 = fmaxf(tm1, __shfl_xor_sync(0xffffffffu, tm1, 2));
        float mn0 = fmaxf(mrow[0], tm0), mn1 = fmaxf(mrow[1], tm1);
        float al0 = fexp(mrow[0] - mn0), al1 = fexp(mrow[1] - mn1);
        float ts0 = 0.f, ts1 = 0.f;
        #pragma unroll
        for (int nt = 0; nt < 16; nt++) {
            s[nt][0] = fexp(s[nt][0] - mn0); ts0 += s[nt][0];
            s[nt][1] = fexp(s[nt][1] - mn0); ts0 += s[nt][1];
            s[nt][2] = fexp(s[nt][2] - mn1); ts1 += s[nt][2];
            s[nt][3] = fexp(s[nt][3] - mn1); ts1 += s[nt][3];
        }
        ts0 += __shfl_xor_sync(0xffffffffu, ts0, 1);
        ts0 += __shfl_xor_sync(0xffffffffu, ts0, 2);
        ts1 += __shfl_xor_sync(0xffffffffu, ts1, 1);
        ts1 += __shfl_xor_sync(0xffffffffu, ts1, 2);
        lrow[0] = lrow[0] * al0 + ts0; mrow[0] = mn0;
        lrow[1] = lrow[1] * al1 + ts1; mrow[1] = mn1;
        #pragma unroll
        for (int ot = 0; ot < 16; ot++) {
            o[ot][0] *= al0; o[ot][1] *= al0;
            o[ot][2] *= al1; o[ot][3] *= al1;
        }

        // pack P from accumulators: pH[k2] covers kv rows k2*16..k2*16+15
        uint32_t pH[8][4];
        #pragma unroll
        for (int k2 = 0; k2 < 8; k2++) {
            #pragma unroll
            for (int hx = 0; hx < 2; hx++) {
                int nt = 2 * k2 + hx;
                pH[k2][hx * 2 + 0] = packh(s[nt][0], s[nt][1]);
                pH[k2][hx * 2 + 1] = packh(s[nt][2], s[nt][3]);
            }
        }

        // O += P * V (single pass over 128 kv rows)
        #pragma unroll
        for (int k2 = 0; k2 < 8; k2++) {
            uint32_t bV[8][4];
            #pragma unroll
            for (int dv = 0; dv < 8; dv++)
                ldsm_x4_t(bV[dv], sV_u + ((k2 * 16 + vrow) * AP + dv * 16 + vcol) * 2);
            #pragma unroll
            for (int ot = 0; ot < 16; ot++)
                mma16816(o[ot], pH[k2], &bV[ot >> 1][(ot & 1) * 2], o[ot]);
        }
        __syncthreads();
    }

    // epilogue: normalize, write fp16
    float inv0 = 1.f / lrow[0], inv1 = 1.f / lrow[1];
    int gr0 = m0 + wid * 16 + (l >> 2);
    #pragma unroll
    for (int ot = 0; ot < 16; ot++) {
        size_t i0 = base + (size_t)gr0 * CC + ot * 8 + (l & 3) * 2;
        size_t i1 = i0 + (size_t)8 * CC;
        *reinterpret_cast<uint32_t*>(Oh + i0) = packh(o[ot][0] * inv0, o[ot][1] * inv0);
        *reinterpret_cast<uint32_t*>(Oh + i1) = packh(o[ot][2] * inv1, o[ot][3] * inv1);
    }
}

// ---------------- launch -----------------------------------------------------
extern "C" void kernel_launch(void* const* d_in, const int* in_sizes, int n_in,
                              void* d_out, int out_size) {
    const float* residual = (const float*)d_in[0];
    const float* w[4] = {(const float*)d_in[1], (const float*)d_in[2],
                         (const float*)d_in[3], (const float*)d_in[4]};
    float* out = (float*)d_out;

    cudaFuncSetAttribute(attn_mma_kernel, cudaFuncAttributeMaxDynamicSharedMemorySize,
                         ATT_SMEM);
    cudaFuncSetAttribute(gemm_pipe_kernel<0>,
                         cudaFuncAttributeMaxDynamicSharedMemorySize, GEMM_SMEM);
    cudaFuncSetAttribute(gemm_pipe_kernel<1>,
                         cudaFuncAttributeMaxDynamicSharedMemorySize, GEMM_SMEM);

    void *pq, *pk, *pxh, *pyh, *pwh, *pqh, *pkh, *pvh;
    cudaGetSymbolAddress(&pq, g_q);
    cudaGetSymbolAddress(&pk, g_k);
    cudaGetSymbolAddress(&pxh, g_xh);
    cudaGetSymbolAddress(&pyh, g_yh);
    cudaGetSymbolAddress(&pwh, g_wh);
    cudaGetSymbolAddress(&pqh, g_qh);
    cudaGetSymbolAddress(&pkh, g_kh);
    cudaGetSymbolAddress(&pvh, g_vh);
    float* gq = (float*)pq; float* gk = (float*)pk;
    __half* xh = (__half*)pxh; __half* yh = (__half*)pyh;
    __half* wh = (__half*)pwh;
    __half* qh = (__half*)pqh; __half* kh = (__half*)pkh; __half* vh = (__half*)pvh;

    // 0. cast all weights to fp16 (pre-scaled x32) in one launch
    castw4_kernel<<<4 * 4096, 256>>>(w[0], w[1], w[2], w[3], wh);
    // 1. rmsnorm input -> fp16
    rmsnorm_in_kernel<<<BT, 256>>>(residual, xh);
    // 2. rope tables
    rope_table_kernel<<<(TT * 64 + 255) / 256, 256>>>();
    // 3. fused QKV projection: q,k fp32; v fp16
    dim3 qkvgrid(3 * CC / QN, BT / QM);
    gemm_pipe_kernel<0><<<qkvgrid, 256, GEMM_SMEM>>>(xh, wh, nullptr, gq, gk, vh);
    // 4. per-head rmsnorm + rope -> fp16 q,k
    qknorm_rope_kernel<<<(BT * HH) / 8, 256>>>(gq, gk, qh, kh);
    // 5. HMMA causal flash attention -> fp16 y
    dim3 agrid(TT / 128, BB * HH);
    attn_mma_kernel<<<agrid, 256, ATT_SMEM>>>(qh, kh, vh, yh);
    // 6. output projection + residual add
    dim3 pgrid(CC / QN, BT / QM);
    gemm_pipe_kernel<1><<<pgrid, 256, GEMM_SMEM>>>(yh, wh, residual, out, nullptr, nullptr);
}